// round 2
// baseline (speedup 1.0000x reference)
#include <cuda_runtime.h>
#include <math.h>

#define BB 8
#define CH 256
#define CL 128
#define RR 64
#define HW 4096
#define MM 2048
#define SPLITK 16

// ---------------- scratch (static device globals; no runtime alloc) ----------------
__device__ float g_TH[BB*CL*HW];
__device__ float g_PH[BB*CL*HW];
__device__ float g_GX[BB*CL*HW];
__device__ float g_Y [BB*CL*HW];
__device__ float g_ZC[BB*CH*HW];
__device__ float g_G2[BB*RR*HW];
__device__ float g_T2[BB*RR*HW];
__device__ float g_P2[BB*RR*HW];
__device__ float g_Y2[BB*RR*HW];
__device__ float g_ZP[BB*CH*HW];
__device__ float g_ATT[BB*CL*CL];
__device__ float g_ATTP[BB*SPLITK*CL*CL];
__device__ float g_ATT2[(size_t)BB*MM*MM];
__device__ float g_pm[BB*CH];
__device__ float g_px[BB*CH];
__device__ float g_ca[BB*CH];
__device__ float g_sam[BB*HW];
__device__ float g_sax[BB*HW];
__device__ float g_sas[BB*HW];
__device__ float g_s1[CH], g_b1[CH], g_s2[CH], g_b2[CH];

// ---------------- fused BN scale/bias precompute ----------------
__global__ void prep_kernel(const float* __restrict__ cWb, const float* __restrict__ cg,
                            const float* __restrict__ cb, const float* __restrict__ cm,
                            const float* __restrict__ cv,
                            const float* __restrict__ pWb, const float* __restrict__ pg,
                            const float* __restrict__ pb, const float* __restrict__ pm,
                            const float* __restrict__ pv) {
    int c = threadIdx.x;
    if (c < CH) {
        float s1 = cg[c] * rsqrtf(cv[c] + 1e-5f);
        g_s1[c] = s1;
        g_b1[c] = cWb[c] * s1 + cb[c] - cm[c] * s1;
        float s2 = pg[c] * rsqrtf(pv[c] + 1e-5f);
        g_s2[c] = s2;
        g_b2[c] = pWb[c] * s2 + pb[c] - pm[c] * s2;
    }
}

// ---------------- generic tiled GEMM ----------------
// C[M,N] = f( alpha * op(A)[M,K] @ op(B)[K,N] )
// MODE 0: C = alpha*AB + (bias ? bias[m] : 0)
// MODE 1: C = AB*scale[m] + bias[m] + R[m,n]         (BN + residual)
// MODE 2: split-K partial: C_slice(z) = alpha*AB over K-chunk  (deterministic; reduce later)
// TA: A stored [K,M] row-major (lda = M-stride). TB: B stored [N,K] row-major.
// All M,N multiples of 64, K-chunks multiples of 16 (verified by problem shapes).
template<int MODE, bool TA, bool TB>
__global__ __launch_bounds__(256) void gemm64(
    const float* __restrict__ A, const float* __restrict__ Bm,
    float* __restrict__ C, const float* __restrict__ R,
    const float* __restrict__ bias, const float* __restrict__ scale,
    int M, int N, int K, int lda, int ldb, int ldc,
    long sA, long sB, long sC, float alpha, int splitK)
{
    int z = blockIdx.z;
    int batch = z / splitK;
    int kslice = z - batch * splitK;
    int Kchunk = K / splitK;
    int k0base = kslice * Kchunk;

    A  += (long)batch * sA;
    Bm += (long)batch * sB;
    if (MODE == 2) C += (long)z * sC;
    else           C += (long)batch * sC;
    if (MODE == 1) R += (long)batch * sC;

    int m0 = blockIdx.y * 64;
    int n0 = blockIdx.x * 64;
    int tid = threadIdx.x;
    int ty = tid >> 4, tx = tid & 15;

    __shared__ __align__(16) float As[16][68];
    __shared__ __align__(16) float Bs[16][68];

    float acc[4][4];
    #pragma unroll
    for (int i = 0; i < 4; i++)
        #pragma unroll
        for (int j = 0; j < 4; j++) acc[i][j] = 0.f;

    for (int kt = 0; kt < Kchunk; kt += 16) {
        int k0 = k0base + kt;
        // ---- load A tile -> As[k][m] ----
        if (!TA) {
            int m = tid >> 2;
            int kb = (tid & 3) * 4;
            float4 v = *reinterpret_cast<const float4*>(&A[(long)(m0 + m) * lda + k0 + kb]);
            As[kb+0][m] = v.x; As[kb+1][m] = v.y; As[kb+2][m] = v.z; As[kb+3][m] = v.w;
        } else {
            int k = tid >> 4;
            int mb = (tid & 15) * 4;
            float4 v = *reinterpret_cast<const float4*>(&A[(long)(k0 + k) * lda + m0 + mb]);
            As[k][mb+0] = v.x; As[k][mb+1] = v.y; As[k][mb+2] = v.z; As[k][mb+3] = v.w;
        }
        // ---- load B tile -> Bs[k][n] ----
        if (!TB) {
            int k = tid >> 4;
            int nb = (tid & 15) * 4;
            float4 v = *reinterpret_cast<const float4*>(&Bm[(long)(k0 + k) * ldb + n0 + nb]);
            Bs[k][nb+0] = v.x; Bs[k][nb+1] = v.y; Bs[k][nb+2] = v.z; Bs[k][nb+3] = v.w;
        } else {
            int n = tid >> 2;
            int kb = (tid & 3) * 4;
            float4 v = *reinterpret_cast<const float4*>(&Bm[(long)(n0 + n) * ldb + k0 + kb]);
            Bs[kb+0][n] = v.x; Bs[kb+1][n] = v.y; Bs[kb+2][n] = v.z; Bs[kb+3][n] = v.w;
        }
        __syncthreads();
        #pragma unroll
        for (int k = 0; k < 16; k++) {
            float4 a = *reinterpret_cast<const float4*>(&As[k][ty * 4]);
            float4 b = *reinterpret_cast<const float4*>(&Bs[k][tx * 4]);
            acc[0][0] += a.x*b.x; acc[0][1] += a.x*b.y; acc[0][2] += a.x*b.z; acc[0][3] += a.x*b.w;
            acc[1][0] += a.y*b.x; acc[1][1] += a.y*b.y; acc[1][2] += a.y*b.z; acc[1][3] += a.y*b.w;
            acc[2][0] += a.z*b.x; acc[2][1] += a.z*b.y; acc[2][2] += a.z*b.z; acc[2][3] += a.z*b.w;
            acc[3][0] += a.w*b.x; acc[3][1] += a.w*b.y; acc[3][2] += a.w*b.z; acc[3][3] += a.w*b.w;
        }
        __syncthreads();
    }

    #pragma unroll
    for (int i = 0; i < 4; i++) {
        int gm = m0 + ty * 4 + i;
        #pragma unroll
        for (int j = 0; j < 4; j++) {
            int gn = n0 + tx * 4 + j;
            long idx = (long)gm * ldc + gn;
            if (MODE == 0) {
                C[idx] = alpha * acc[i][j] + (bias ? bias[gm] : 0.f);
            } else if (MODE == 1) {
                C[idx] = acc[i][j] * scale[gm] + bias[gm] + R[idx];
            } else {
                C[idx] = alpha * acc[i][j];
            }
        }
    }
}

// ---------------- deterministic split-K reduce for ATT ----------------
__global__ void att_reduce_kernel() {
    int i = blockIdx.x * 256 + threadIdx.x;     // i < BB*CL*CL
    int b = i / (CL * CL);
    int r = i - b * (CL * CL);
    float s = 0.f;
    #pragma unroll
    for (int ks = 0; ks < SPLITK; ks++)
        s += g_ATTP[((long)b * SPLITK + ks) * (CL * CL) + r];
    g_ATT[i] = s;
}

// ---------------- CBAM: channel pooling (mean+max over HW) ----------------
__global__ void chanpool_kernel() {
    int c = blockIdx.x, b = blockIdx.y;
    int t = threadIdx.x;
    const float* p = g_ZP + ((long)b * CH + c) * HW;
    float s = 0.f, mx = -1e30f;
    for (int i = t; i < HW; i += 256) {
        float v = p[i];
        s += v;
        mx = fmaxf(mx, v);
    }
    __shared__ float ss[256];
    __shared__ float sm[256];
    ss[t] = s; sm[t] = mx;
    __syncthreads();
    for (int o = 128; o > 0; o >>= 1) {
        if (t < o) { ss[t] += ss[t + o]; sm[t] = fmaxf(sm[t], sm[t + o]); }
        __syncthreads();
    }
    if (t == 0) {
        g_pm[b * CH + c] = ss[0] * (1.f / HW);
        g_px[b * CH + c] = sm[0];
    }
}

// ---------------- CBAM: channel-attention MLP ----------------
__global__ void camlp_kernel(const float* __restrict__ fc1, const float* __restrict__ fc2) {
    int b = blockIdx.x;
    int t = threadIdx.x;
    __shared__ float hm[16], hx[16];
    if (t < 16) {
        float s = 0.f;
        for (int c = 0; c < CH; c++) s += fc1[t * CH + c] * g_pm[b * CH + c];
        hm[t] = fmaxf(s, 0.f);
    } else if (t < 32) {
        int h = t - 16;
        float s = 0.f;
        for (int c = 0; c < CH; c++) s += fc1[h * CH + c] * g_px[b * CH + c];
        hx[h] = fmaxf(s, 0.f);
    }
    __syncthreads();
    float sm = 0.f, sx = 0.f;
    #pragma unroll
    for (int h = 0; h < 16; h++) {
        float w = fc2[t * 16 + h];
        sm += w * hm[h];
        sx += w * hx[h];
    }
    g_ca[b * CH + t] = 1.f / (1.f + expf(-(sm + sx)));
}

// ---------------- CBAM: spatial pooling over channels of z_pnl*ca ----------------
__global__ void spool_kernel() {
    __shared__ float cas[CH];
    int idx = blockIdx.x * 256 + threadIdx.x;
    int b = idx / HW;
    int p = idx - b * HW;
    for (int c = threadIdx.x; c < CH; c += 256) cas[c] = g_ca[b * CH + c];
    __syncthreads();
    float s = 0.f, mx = -1e30f;
    for (int c = 0; c < CH; c++) {
        float v = g_ZP[((long)b * CH + c) * HW + p] * cas[c];
        s += v;
        mx = fmaxf(mx, v);
    }
    g_sam[idx] = s * (1.f / CH);
    g_sax[idx] = mx;
}

// ---------------- CBAM: 7x7 spatial conv + sigmoid ----------------
__global__ void sconv_kernel(const float* __restrict__ w) {
    int idx = blockIdx.x * 256 + threadIdx.x;
    int b = idx / HW;
    int p = idx - b * HW;
    int h = p >> 6, wq = p & 63;
    float s = 0.f;
    #pragma unroll
    for (int kh = 0; kh < 7; kh++) {
        int ih = h + kh - 3;
        if (ih < 0 || ih >= 64) continue;
        #pragma unroll
        for (int kw = 0; kw < 7; kw++) {
            int iw = wq + kw - 3;
            if (iw < 0 || iw >= 64) continue;
            int q = (ih << 6) | iw;
            s += w[kh * 7 + kw] * g_sam[b * HW + q] + w[49 + kh * 7 + kw] * g_sax[b * HW + q];
        }
    }
    g_sas[idx] = 1.f / (1.f + expf(-s));
}

// ---------------- final weighted fusion ----------------
__global__ void final_kernel(const float* __restrict__ x, const float* __restrict__ fwp,
                             float* __restrict__ out) {
    long i = (long)blockIdx.x * 256 + threadIdx.x;
    long p = i % HW;
    long bc = i / HW;
    long b = bc / CH;
    float fw = *fwp;
    out[i] = fw * g_ZP[i] * g_ca[bc] * g_sas[b * HW + p] + (1.f - fw) * x[i];
}

// ---------------- launch ----------------
extern "C" void kernel_launch(void* const* d_in, const int* in_sizes, int n_in,
                              void* d_out, int out_size) {
    const float* x   = (const float*)d_in[0];
    const float* x0  = (const float*)d_in[1];
    const float* cgw = (const float*)d_in[2];
    const float* cgb = (const float*)d_in[3];
    const float* ctw = (const float*)d_in[4];
    const float* ctb = (const float*)d_in[5];
    const float* cpw = (const float*)d_in[6];
    const float* cpb = (const float*)d_in[7];
    const float* cWw = (const float*)d_in[8];
    const float* cWb = (const float*)d_in[9];
    const float* cbg = (const float*)d_in[10];
    const float* cbb = (const float*)d_in[11];
    const float* cbm = (const float*)d_in[12];
    const float* cbv = (const float*)d_in[13];
    const float* pgw = (const float*)d_in[14];
    const float* pgb = (const float*)d_in[15];
    const float* ptw = (const float*)d_in[16];
    const float* ptb = (const float*)d_in[17];
    const float* ppw = (const float*)d_in[18];
    const float* ppb = (const float*)d_in[19];
    const float* pWw = (const float*)d_in[20];
    const float* pWb = (const float*)d_in[21];
    const float* pbg = (const float*)d_in[22];
    const float* pbb = (const float*)d_in[23];
    const float* pbm = (const float*)d_in[24];
    const float* pbv = (const float*)d_in[25];
    const float* fc1 = (const float*)d_in[26];
    const float* fc2 = (const float*)d_in[27];
    const float* saw = (const float*)d_in[28];
    const float* fwp = (const float*)d_in[29];
    float* out = (float*)d_out;

    float *TH, *PH, *GX, *Y, *ZC, *G2, *T2, *P2, *Y2, *ZP, *ATTP, *ATT, *ATT2, *S1, *B1, *S2, *B2;
    cudaGetSymbolAddress((void**)&TH,  g_TH);
    cudaGetSymbolAddress((void**)&PH,  g_PH);
    cudaGetSymbolAddress((void**)&GX,  g_GX);
    cudaGetSymbolAddress((void**)&Y,   g_Y);
    cudaGetSymbolAddress((void**)&ZC,  g_ZC);
    cudaGetSymbolAddress((void**)&G2,  g_G2);
    cudaGetSymbolAddress((void**)&T2,  g_T2);
    cudaGetSymbolAddress((void**)&P2,  g_P2);
    cudaGetSymbolAddress((void**)&Y2,  g_Y2);
    cudaGetSymbolAddress((void**)&ZP,  g_ZP);
    cudaGetSymbolAddress((void**)&ATTP, g_ATTP);
    cudaGetSymbolAddress((void**)&ATT, g_ATT);
    cudaGetSymbolAddress((void**)&ATT2, g_ATT2);
    cudaGetSymbolAddress((void**)&S1,  g_s1);
    cudaGetSymbolAddress((void**)&B1,  g_b1);
    cudaGetSymbolAddress((void**)&S2,  g_s2);
    cudaGetSymbolAddress((void**)&B2,  g_b2);

    prep_kernel<<<1, 256>>>(cWb, cbg, cbb, cbm, cbv, pWb, pbg, pbb, pbm, pbv);

    // ---- CNL 1x1 convs ----
    gemm64<0,false,false><<<dim3(HW/64, CL/64, BB), 256>>>(
        ctw, x, TH, nullptr, ctb, nullptr, CL, HW, CH, CH, HW, HW,
        0L, (long)CH*HW, (long)CL*HW, 1.f, 1);
    gemm64<0,false,false><<<dim3(HW/64, CL/64, BB), 256>>>(
        cpw, x0, PH, nullptr, cpb, nullptr, CL, HW, CL, CL, HW, HW,
        0L, (long)CL*HW, (long)CL*HW, 1.f, 1);
    gemm64<0,false,false><<<dim3(HW/64, CL/64, BB), 256>>>(
        cgw, x0, GX, nullptr, cgb, nullptr, CL, HW, CL, CL, HW, HW,
        0L, (long)CL*HW, (long)CL*HW, 1.f, 1);
    // ---- CNL affinity: ATT = TH @ PH^T / Cl  (split-K, deterministic) ----
    gemm64<2,false,true><<<dim3(CL/64, CL/64, BB*SPLITK), 256>>>(
        TH, PH, ATTP, nullptr, nullptr, nullptr, CL, CL, HW, HW, HW, CL,
        (long)CL*HW, (long)CL*HW, (long)CL*CL, 1.f/CL, SPLITK);
    att_reduce_kernel<<<BB*CL*CL/256, 256>>>();
    // ---- Y = ATT @ GX ----
    gemm64<0,false,false><<<dim3(HW/64, CL/64, BB), 256>>>(
        ATT, GX, Y, nullptr, nullptr, nullptr, CL, HW, CL, CL, HW, HW,
        (long)CL*CL, (long)CL*HW, (long)CL*HW, 1.f, 1);
    // ---- Z_CNL = BN(W@Y) + x ----
    gemm64<1,false,false><<<dim3(HW/64, CH/64, BB), 256>>>(
        cWw, Y, ZC, x, B1, S1, CH, HW, CL, CL, HW, HW,
        0L, (long)CL*HW, (long)CH*HW, 1.f, 1);

    // ---- PNL 1x1 convs ----
    gemm64<0,false,false><<<dim3(HW/64, RR/64, BB), 256>>>(
        pgw, x0, G2, nullptr, pgb, nullptr, RR, HW, CL, CL, HW, HW,
        0L, (long)CL*HW, (long)RR*HW, 1.f, 1);
    gemm64<0,false,false><<<dim3(HW/64, RR/64, BB), 256>>>(
        ptw, ZC, T2, nullptr, ptb, nullptr, RR, HW, CH, CH, HW, HW,
        0L, (long)CH*HW, (long)RR*HW, 1.f, 1);
    gemm64<0,false,false><<<dim3(HW/64, RR/64, BB), 256>>>(
        ppw, x0, P2, nullptr, ppb, nullptr, RR, HW, CL, CL, HW, HW,
        0L, (long)CL*HW, (long)RR*HW, 1.f, 1);
    // ---- ATT2 = T2view^T @ P2view / M   (views: [CL=128, MM=2048]) ----
    gemm64<0,true,false><<<dim3(MM/64, MM/64, BB), 256>>>(
        T2, P2, ATT2, nullptr, nullptr, nullptr, MM, MM, CL, MM, MM, MM,
        (long)RR*HW, (long)RR*HW, (long)MM*MM, 1.f/MM, 1);
    // ---- Y2view = G2view @ ATT2^T ----
    gemm64<0,false,true><<<dim3(MM/64, CL/64, BB), 256>>>(
        G2, ATT2, Y2, nullptr, nullptr, nullptr, CL, MM, MM, MM, MM, MM,
        (long)RR*HW, (long)MM*MM, (long)RR*HW, 1.f, 1);
    // ---- Z_PNL = BN(W@Y2) + Z_CNL ----
    gemm64<1,false,false><<<dim3(HW/64, CH/64, BB), 256>>>(
        pWw, Y2, ZP, ZC, B2, S2, CH, HW, RR, RR, HW, HW,
        0L, (long)RR*HW, (long)CH*HW, 1.f, 1);

    // ---- CBAM + fusion ----
    chanpool_kernel<<<dim3(CH, BB), 256>>>();
    camlp_kernel<<<BB, 256>>>(fc1, fc2);
    spool_kernel<<<BB*HW/256, 256>>>();
    sconv_kernel<<<BB*HW/256, 256>>>(saw);
    final_kernel<<<BB*CH*HW/256, 256>>>(x, fwp, out);
}

// round 3
// speedup vs baseline: 1.0561x; 1.0561x over previous
#include <cuda_runtime.h>
#include <cstdint>
#include <math.h>

#define BB 8
#define CH 256
#define CL 128
#define RR 64
#define HW 4096
#define MM 2048
#define SPLITK 32

// ---------------- scratch (static device globals; no runtime alloc) ----------------
__device__ float g_TH[BB*CL*HW];
__device__ float g_PH[BB*CL*HW];
__device__ float g_GX[BB*CL*HW];
__device__ float g_Y [BB*CL*HW];
__device__ float g_ZC[BB*CH*HW];
__device__ float g_G2[BB*RR*HW];
__device__ float g_T2[BB*RR*HW];
__device__ float g_P2[BB*RR*HW];
__device__ float g_Y2[BB*RR*HW];
__device__ float g_ZP[BB*CH*HW];
__device__ float g_ATT[BB*CL*CL];
__device__ float g_ATTP[BB*SPLITK*CL*CL];
__device__ float g_ATT2[(size_t)BB*MM*MM];
__device__ float g_pm[BB*CH];
__device__ float g_px[BB*CH];
__device__ float g_ca[BB*CH];
__device__ float g_sam[BB*HW];
__device__ float g_sax[BB*HW];
__device__ float g_sas[BB*HW];
__device__ float g_s1[CH], g_b1[CH], g_s2[CH], g_b2[CH];

// ---------------- fused BN scale/bias precompute ----------------
__global__ void prep_kernel(const float* __restrict__ cWb, const float* __restrict__ cg,
                            const float* __restrict__ cb, const float* __restrict__ cm,
                            const float* __restrict__ cv,
                            const float* __restrict__ pWb, const float* __restrict__ pg,
                            const float* __restrict__ pb, const float* __restrict__ pm,
                            const float* __restrict__ pv) {
    int c = threadIdx.x;
    if (c < CH) {
        float s1 = cg[c] * rsqrtf(cv[c] + 1e-5f);
        g_s1[c] = s1;
        g_b1[c] = cWb[c] * s1 + cb[c] - cm[c] * s1;
        float s2 = pg[c] * rsqrtf(pv[c] + 1e-5f);
        g_s2[c] = s2;
        g_b2[c] = pWb[c] * s2 + pb[c] - pm[c] * s2;
    }
}

// ---------------- TF32 tensor-core GEMM ----------------
__device__ __forceinline__ uint32_t f2tf(float f) {
    uint32_t r;
    asm("cvt.rna.tf32.f32 %0, %1;" : "=r"(r) : "f"(f));
    return r;
}

#define MMA_TF32(d, a0,a1,a2,a3, b0,b1) \
    asm volatile("mma.sync.aligned.m16n8k8.row.col.f32.tf32.tf32.f32 " \
        "{%0,%1,%2,%3},{%4,%5,%6,%7},{%8,%9},{%0,%1,%2,%3};" \
        : "+f"(d[0]),"+f"(d[1]),"+f"(d[2]),"+f"(d[3]) \
        : "r"(a0),"r"(a1),"r"(a2),"r"(a3),"r"(b0),"r"(b1))

// C[M,N] = f( alpha * op(A)[M,K] @ op(B)[K,N] )
// MODE 0: C = alpha*AB + (bias ? bias[m] : 0)
// MODE 1: C = AB*scale[m] + bias[m] + R[m,n]
// MODE 2: split-K partial (deterministic; reduced later)
// Block tile 128x128, 8 warps of 64x32, k-step 16, double-buffered smem,
// permuted+swizzled smem so fragments load as conflict-free LDS.128.
// Requires: N % 128 == 0, Kchunk % 16 == 0. M arbitrary (rows >= M zero-padded).
template<int MODE, bool TA, bool TB>
__global__ __launch_bounds__(256, 1) void gemm_tc(
    const float* __restrict__ A, const float* __restrict__ Bm,
    float* __restrict__ C, const float* __restrict__ R,
    const float* __restrict__ bias, const float* __restrict__ scale,
    int M, int N, int K, int lda, int ldb, int ldc,
    long sA, long sB, long sC, float alpha, int splitK)
{
    int z = blockIdx.z;
    int batch = z / splitK;
    int kslice = z - batch * splitK;
    int Kchunk = K / splitK;
    int k0base = kslice * Kchunk;

    A  += (long)batch * sA;
    Bm += (long)batch * sB;
    if (MODE == 2) C += (long)z * sC;
    else           C += (long)batch * sC;
    if (MODE == 1) R += (long)batch * sC;

    const int m0 = blockIdx.y * 128;
    const int n0 = blockIdx.x * 128;
    const int tid = threadIdx.x;
    const int warp = tid >> 5, lane = tid & 31;
    const int wm = warp >> 2, wn = warp & 3;       // 2 x 4 warp grid
    const int g = lane >> 2, c = lane & 3;
    const int m0w = wm * 64, n0w = wn * 32;

    __shared__ uint32_t As[2][128 * 16];
    __shared__ uint32_t Bs[2][128 * 16];

    float acc[4][4][4];
    #pragma unroll
    for (int i = 0; i < 4; i++)
        #pragma unroll
        for (int j = 0; j < 4; j++)
            #pragma unroll
            for (int e = 0; e < 4; e++) acc[i][j][e] = 0.f;

    const int nk = Kchunk / 16;
    float4 pa[2], pb[2];

    // ---- global load of k-tile t into regs ----
    auto load_tile = [&](int t) {
        int k0 = k0base + t * 16;
        #pragma unroll
        for (int it = 0; it < 2; it++) {
            int f = tid + it * 256;
            if (!TA) {
                int m = f >> 2, j = f & 3;
                bool ok = (m0 + m) < M;
                pa[it] = ok ? *reinterpret_cast<const float4*>(&A[(long)(m0 + m) * lda + k0 + 4 * j])
                            : make_float4(0.f, 0.f, 0.f, 0.f);
            } else {
                int k = f >> 5, mb = (f & 31) << 2;
                bool ok = (m0 + mb) < M;
                pa[it] = ok ? *reinterpret_cast<const float4*>(&A[(long)(k0 + k) * lda + m0 + mb])
                            : make_float4(0.f, 0.f, 0.f, 0.f);
            }
            if (!TB) {
                int k = f >> 5, nb = (f & 31) << 2;
                pb[it] = *reinterpret_cast<const float4*>(&Bm[(long)(k0 + k) * ldb + n0 + nb]);
            } else {
                int n = f >> 2, j = f & 3;
                pb[it] = *reinterpret_cast<const float4*>(&Bm[(long)(n0 + n) * ldb + k0 + 4 * j]);
            }
        }
    };

    // ---- store regs into smem buffer (tf32 convert + permute + swizzle) ----
    auto store_tile = [&](int buf) {
        #pragma unroll
        for (int it = 0; it < 2; it++) {
            int f = tid + it * 256;
            float va[4] = {pa[it].x, pa[it].y, pa[it].z, pa[it].w};
            float vb[4] = {pb[it].x, pb[it].y, pb[it].z, pb[it].w};
            if (!TA) {
                int m = f >> 2, j = f & 3;
                #pragma unroll
                for (int e = 0; e < 4; e++)
                    As[buf][m * 16 + ((e ^ (m & 3)) << 2) + j] = f2tf(va[e]);
            } else {
                int k = f >> 5, mb = (f & 31) << 2;
                #pragma unroll
                for (int e = 0; e < 4; e++) {
                    int m = mb + e;
                    As[buf][m * 16 + (((k & 3) ^ (m & 3)) << 2) + (k >> 2)] = f2tf(va[e]);
                }
            }
            if (!TB) {
                int k = f >> 5, nb = (f & 31) << 2;
                #pragma unroll
                for (int e = 0; e < 4; e++) {
                    int n = nb + e;
                    Bs[buf][n * 16 + (((k & 3) ^ (n & 3)) << 2) + (k >> 2)] = f2tf(vb[e]);
                }
            } else {
                int n = f >> 2, j = f & 3;
                #pragma unroll
                for (int e = 0; e < 4; e++)
                    Bs[buf][n * 16 + ((e ^ (n & 3)) << 2) + j] = f2tf(vb[e]);
            }
        }
    };

    load_tile(0);
    store_tile(0);
    __syncthreads();

    for (int t = 0; t < nk; t++) {
        if (t + 1 < nk) load_tile(t + 1);

        int buf = t & 1;
        uint4 afr[4][2], bfr[4];
        #pragma unroll
        for (int i = 0; i < 4; i++) {
            int r = m0w + i * 16 + g;
            int col = (c ^ (r & 3)) << 2;
            afr[i][0] = *reinterpret_cast<const uint4*>(&As[buf][r * 16 + col]);
            afr[i][1] = *reinterpret_cast<const uint4*>(&As[buf][(r + 8) * 16 + col]);
        }
        #pragma unroll
        for (int j = 0; j < 4; j++) {
            int n = n0w + j * 8 + g;
            bfr[j] = *reinterpret_cast<const uint4*>(&Bs[buf][n * 16 + ((c ^ (n & 3)) << 2)]);
        }
        #pragma unroll
        for (int i = 0; i < 4; i++)
            #pragma unroll
            for (int j = 0; j < 4; j++) {
                MMA_TF32(acc[i][j], afr[i][0].x, afr[i][1].x, afr[i][0].y, afr[i][1].y,
                         bfr[j].x, bfr[j].y);
                MMA_TF32(acc[i][j], afr[i][0].z, afr[i][1].z, afr[i][0].w, afr[i][1].w,
                         bfr[j].z, bfr[j].w);
            }

        if (t + 1 < nk) {
            store_tile((t + 1) & 1);
            __syncthreads();
        }
    }

    // ---- epilogue ----
    #pragma unroll
    for (int i = 0; i < 4; i++) {
        int gm0 = m0 + m0w + i * 16 + g;
        #pragma unroll
        for (int half = 0; half < 2; half++) {
            int gm = gm0 + half * 8;
            if (gm >= M) continue;
            float bv = 0.f, sv = 1.f;
            if (MODE == 0) bv = bias ? bias[gm] : 0.f;
            if (MODE == 1) { bv = bias[gm]; sv = scale[gm]; }
            #pragma unroll
            for (int j = 0; j < 4; j++) {
                int gn = n0 + n0w + j * 8 + 2 * c;
                long idx = (long)gm * ldc + gn;
                float v0 = acc[i][j][half * 2 + 0];
                float v1 = acc[i][j][half * 2 + 1];
                float2 o;
                if (MODE == 0)      { o.x = alpha * v0 + bv;            o.y = alpha * v1 + bv; }
                else if (MODE == 1) { o.x = v0 * sv + bv + R[idx];      o.y = v1 * sv + bv + R[idx + 1]; }
                else                { o.x = alpha * v0;                 o.y = alpha * v1; }
                *reinterpret_cast<float2*>(&C[idx]) = o;
            }
        }
    }
}

// ---------------- deterministic split-K reduce for ATT ----------------
__global__ void att_reduce_kernel() {
    int i = blockIdx.x * 256 + threadIdx.x;     // i < BB*CL*CL
    int b = i / (CL * CL);
    int r = i - b * (CL * CL);
    float s = 0.f;
    #pragma unroll
    for (int ks = 0; ks < SPLITK; ks++)
        s += g_ATTP[((long)b * SPLITK + ks) * (CL * CL) + r];
    g_ATT[i] = s;
}

// ---------------- CBAM: channel pooling (mean+max over HW) ----------------
__global__ void chanpool_kernel() {
    int c = blockIdx.x, b = blockIdx.y;
    int t = threadIdx.x;
    const float* p = g_ZP + ((long)b * CH + c) * HW;
    float s = 0.f, mx = -1e30f;
    for (int i = t; i < HW; i += 256) {
        float v = p[i];
        s += v;
        mx = fmaxf(mx, v);
    }
    __shared__ float ss[256];
    __shared__ float sm[256];
    ss[t] = s; sm[t] = mx;
    __syncthreads();
    for (int o = 128; o > 0; o >>= 1) {
        if (t < o) { ss[t] += ss[t + o]; sm[t] = fmaxf(sm[t], sm[t + o]); }
        __syncthreads();
    }
    if (t == 0) {
        g_pm[b * CH + c] = ss[0] * (1.f / HW);
        g_px[b * CH + c] = sm[0];
    }
}

// ---------------- CBAM: channel-attention MLP ----------------
__global__ void camlp_kernel(const float* __restrict__ fc1, const float* __restrict__ fc2) {
    int b = blockIdx.x;
    int t = threadIdx.x;
    __shared__ float hm[16], hx[16];
    if (t < 16) {
        float s = 0.f;
        for (int c = 0; c < CH; c++) s += fc1[t * CH + c] * g_pm[b * CH + c];
        hm[t] = fmaxf(s, 0.f);
    } else if (t < 32) {
        int h = t - 16;
        float s = 0.f;
        for (int c = 0; c < CH; c++) s += fc1[h * CH + c] * g_px[b * CH + c];
        hx[h] = fmaxf(s, 0.f);
    }
    __syncthreads();
    float sm = 0.f, sx = 0.f;
    #pragma unroll
    for (int h = 0; h < 16; h++) {
        float w = fc2[t * 16 + h];
        sm += w * hm[h];
        sx += w * hx[h];
    }
    g_ca[b * CH + t] = 1.f / (1.f + expf(-(sm + sx)));
}

// ---------------- CBAM: spatial pooling over channels of z_pnl*ca ----------------
__global__ void spool_kernel() {
    __shared__ float cas[CH];
    int idx = blockIdx.x * 256 + threadIdx.x;
    int b = idx / HW;
    int p = idx - b * HW;
    for (int c = threadIdx.x; c < CH; c += 256) cas[c] = g_ca[b * CH + c];
    __syncthreads();
    float s = 0.f, mx = -1e30f;
    for (int c = 0; c < CH; c++) {
        float v = g_ZP[((long)b * CH + c) * HW + p] * cas[c];
        s += v;
        mx = fmaxf(mx, v);
    }
    g_sam[idx] = s * (1.f / CH);
    g_sax[idx] = mx;
}

// ---------------- CBAM: 7x7 spatial conv + sigmoid ----------------
__global__ void sconv_kernel(const float* __restrict__ w) {
    int idx = blockIdx.x * 256 + threadIdx.x;
    int b = idx / HW;
    int p = idx - b * HW;
    int h = p >> 6, wq = p & 63;
    float s = 0.f;
    #pragma unroll
    for (int kh = 0; kh < 7; kh++) {
        int ih = h + kh - 3;
        if (ih < 0 || ih >= 64) continue;
        #pragma unroll
        for (int kw = 0; kw < 7; kw++) {
            int iw = wq + kw - 3;
            if (iw < 0 || iw >= 64) continue;
            int q = (ih << 6) | iw;
            s += w[kh * 7 + kw] * g_sam[b * HW + q] + w[49 + kh * 7 + kw] * g_sax[b * HW + q];
        }
    }
    g_sas[idx] = 1.f / (1.f + expf(-s));
}

// ---------------- final weighted fusion ----------------
__global__ void final_kernel(const float* __restrict__ x, const float* __restrict__ fwp,
                             float* __restrict__ out) {
    long i = (long)blockIdx.x * 256 + threadIdx.x;
    long p = i % HW;
    long bc = i / HW;
    long b = bc / CH;
    float fw = *fwp;
    out[i] = fw * g_ZP[i] * g_ca[bc] * g_sas[b * HW + p] + (1.f - fw) * x[i];
}

// ---------------- launch ----------------
extern "C" void kernel_launch(void* const* d_in, const int* in_sizes, int n_in,
                              void* d_out, int out_size) {
    const float* x   = (const float*)d_in[0];
    const float* x0  = (const float*)d_in[1];
    const float* cgw = (const float*)d_in[2];
    const float* cgb = (const float*)d_in[3];
    const float* ctw = (const float*)d_in[4];
    const float* ctb = (const float*)d_in[5];
    const float* cpw = (const float*)d_in[6];
    const float* cpb = (const float*)d_in[7];
    const float* cWw = (const float*)d_in[8];
    const float* cWb = (const float*)d_in[9];
    const float* cbg = (const float*)d_in[10];
    const float* cbb = (const float*)d_in[11];
    const float* cbm = (const float*)d_in[12];
    const float* cbv = (const float*)d_in[13];
    const float* pgw = (const float*)d_in[14];
    const float* pgb = (const float*)d_in[15];
    const float* ptw = (const float*)d_in[16];
    const float* ptb = (const float*)d_in[17];
    const float* ppw = (const float*)d_in[18];
    const float* ppb = (const float*)d_in[19];
    const float* pWw = (const float*)d_in[20];
    const float* pWb = (const float*)d_in[21];
    const float* pbg = (const float*)d_in[22];
    const float* pbb = (const float*)d_in[23];
    const float* pbm = (const float*)d_in[24];
    const float* pbv = (const float*)d_in[25];
    const float* fc1 = (const float*)d_in[26];
    const float* fc2 = (const float*)d_in[27];
    const float* saw = (const float*)d_in[28];
    const float* fwp = (const float*)d_in[29];
    float* out = (float*)d_out;

    float *TH, *PH, *GX, *Y, *ZC, *G2, *T2, *P2, *Y2, *ZP, *ATTP, *ATT, *ATT2, *S1, *B1, *S2, *B2;
    cudaGetSymbolAddress((void**)&TH,  g_TH);
    cudaGetSymbolAddress((void**)&PH,  g_PH);
    cudaGetSymbolAddress((void**)&GX,  g_GX);
    cudaGetSymbolAddress((void**)&Y,   g_Y);
    cudaGetSymbolAddress((void**)&ZC,  g_ZC);
    cudaGetSymbolAddress((void**)&G2,  g_G2);
    cudaGetSymbolAddress((void**)&T2,  g_T2);
    cudaGetSymbolAddress((void**)&P2,  g_P2);
    cudaGetSymbolAddress((void**)&Y2,  g_Y2);
    cudaGetSymbolAddress((void**)&ZP,  g_ZP);
    cudaGetSymbolAddress((void**)&ATTP, g_ATTP);
    cudaGetSymbolAddress((void**)&ATT, g_ATT);
    cudaGetSymbolAddress((void**)&ATT2, g_ATT2);
    cudaGetSymbolAddress((void**)&S1,  g_s1);
    cudaGetSymbolAddress((void**)&B1,  g_b1);
    cudaGetSymbolAddress((void**)&S2,  g_s2);
    cudaGetSymbolAddress((void**)&B2,  g_b2);

    prep_kernel<<<1, 256>>>(cWb, cbg, cbb, cbm, cbv, pWb, pbg, pbb, pbm, pbv);

    // ---- CNL 1x1 convs ----
    gemm_tc<0,false,false><<<dim3(HW/128, 1, BB), 256>>>(
        ctw, x, TH, nullptr, ctb, nullptr, CL, HW, CH, CH, HW, HW,
        0L, (long)CH*HW, (long)CL*HW, 1.f, 1);
    gemm_tc<0,false,false><<<dim3(HW/128, 1, BB), 256>>>(
        cpw, x0, PH, nullptr, cpb, nullptr, CL, HW, CL, CL, HW, HW,
        0L, (long)CL*HW, (long)CL*HW, 1.f, 1);
    gemm_tc<0,false,false><<<dim3(HW/128, 1, BB), 256>>>(
        cgw, x0, GX, nullptr, cgb, nullptr, CL, HW, CL, CL, HW, HW,
        0L, (long)CL*HW, (long)CL*HW, 1.f, 1);
    // ---- CNL affinity: ATT = TH @ PH^T / Cl  (split-K, deterministic) ----
    gemm_tc<2,false,true><<<dim3(1, 1, BB*SPLITK), 256>>>(
        TH, PH, ATTP, nullptr, nullptr, nullptr, CL, CL, HW, HW, HW, CL,
        (long)CL*HW, (long)CL*HW, (long)CL*CL, 1.f/CL, SPLITK);
    att_reduce_kernel<<<BB*CL*CL/256, 256>>>();
    // ---- Y = ATT @ GX ----
    gemm_tc<0,false,false><<<dim3(HW/128, 1, BB), 256>>>(
        ATT, GX, Y, nullptr, nullptr, nullptr, CL, HW, CL, CL, HW, HW,
        (long)CL*CL, (long)CL*HW, (long)CL*HW, 1.f, 1);
    // ---- Z_CNL = BN(W@Y) + x ----
    gemm_tc<1,false,false><<<dim3(HW/128, CH/128, BB), 256>>>(
        cWw, Y, ZC, x, B1, S1, CH, HW, CL, CL, HW, HW,
        0L, (long)CL*HW, (long)CH*HW, 1.f, 1);

    // ---- PNL 1x1 convs (M=64, zero-padded to 128-row tile) ----
    gemm_tc<0,false,false><<<dim3(HW/128, 1, BB), 256>>>(
        pgw, x0, G2, nullptr, pgb, nullptr, RR, HW, CL, CL, HW, HW,
        0L, (long)CL*HW, (long)RR*HW, 1.f, 1);
    gemm_tc<0,false,false><<<dim3(HW/128, 1, BB), 256>>>(
        ptw, ZC, T2, nullptr, ptb, nullptr, RR, HW, CH, CH, HW, HW,
        0L, (long)CH*HW, (long)RR*HW, 1.f, 1);
    gemm_tc<0,false,false><<<dim3(HW/128, 1, BB), 256>>>(
        ppw, x0, P2, nullptr, ppb, nullptr, RR, HW, CL, CL, HW, HW,
        0L, (long)CL*HW, (long)RR*HW, 1.f, 1);
    // ---- ATT2 = T2view^T @ P2view / M   (views: [CL=128, MM=2048]) ----
    gemm_tc<0,true,false><<<dim3(MM/128, MM/128, BB), 256>>>(
        T2, P2, ATT2, nullptr, nullptr, nullptr, MM, MM, CL, MM, MM, MM,
        (long)RR*HW, (long)RR*HW, (long)MM*MM, 1.f/MM, 1);
    // ---- Y2view = G2view @ ATT2^T ----
    gemm_tc<0,false,true><<<dim3(MM/128, 1, BB), 256>>>(
        G2, ATT2, Y2, nullptr, nullptr, nullptr, CL, MM, MM, MM, MM, MM,
        (long)RR*HW, (long)MM*MM, (long)RR*HW, 1.f, 1);
    // ---- Z_PNL = BN(W@Y2) + Z_CNL ----
    gemm_tc<1,false,false><<<dim3(HW/128, CH/128, BB), 256>>>(
        pWw, Y2, ZP, ZC, B2, S2, CH, HW, RR, RR, HW, HW,
        0L, (long)RR*HW, (long)CH*HW, 1.f, 1);

    // ---- CBAM + fusion ----
    chanpool_kernel<<<dim3(CH, BB), 256>>>();
    camlp_kernel<<<BB, 256>>>(fc1, fc2);
    spool_kernel<<<BB*HW/256, 256>>>();
    sconv_kernel<<<BB*HW/256, 256>>>(saw);
    final_kernel<<<BB*CH*HW/256, 256>>>(x, fwp, out);
}

// round 4
// speedup vs baseline: 2.2189x; 2.1011x over previous
#include <cuda_runtime.h>
#include <cstdint>
#include <math.h>

#define BB 8
#define CH 256
#define CL 128
#define RR 64
#define HW 4096
#define MM 2048
#define SPLITK 32

// ---------------- scratch (static device globals; no runtime alloc) ----------------
__device__ float g_TH[BB*CL*HW];
__device__ float g_PH[BB*CL*HW];
__device__ float g_GX[BB*CL*HW];
__device__ float g_Y [BB*CL*HW];
__device__ float g_ZC[BB*CH*HW];
__device__ float g_G2[BB*RR*HW];
__device__ float g_T2[BB*RR*HW];
__device__ float g_P2[BB*RR*HW];
__device__ float g_Y2[BB*RR*HW];
__device__ float g_ZP[BB*CH*HW];
__device__ float g_ATT[BB*CL*CL];
__device__ float g_ATTP[BB*SPLITK*CL*CL];
__device__ float g_ATT2[(size_t)BB*MM*MM];
__device__ float g_pm[BB*CH];
__device__ float g_px[BB*CH];
__device__ float g_ca[BB*CH];
__device__ float g_sam[BB*HW];
__device__ float g_sax[BB*HW];
__device__ float g_sas[BB*HW];
__device__ float g_s1[CH], g_b1[CH], g_s2[CH], g_b2[CH];

// ---------------- fused BN scale/bias precompute ----------------
__global__ void prep_kernel(const float* __restrict__ cWb, const float* __restrict__ cg,
                            const float* __restrict__ cb, const float* __restrict__ cm,
                            const float* __restrict__ cv,
                            const float* __restrict__ pWb, const float* __restrict__ pg,
                            const float* __restrict__ pb, const float* __restrict__ pm,
                            const float* __restrict__ pv) {
    int c = threadIdx.x;
    if (c < CH) {
        float s1 = cg[c] * rsqrtf(cv[c] + 1e-5f);
        g_s1[c] = s1;
        g_b1[c] = cWb[c] * s1 + cb[c] - cm[c] * s1;
        float s2 = pg[c] * rsqrtf(pv[c] + 1e-5f);
        g_s2[c] = s2;
        g_b2[c] = pWb[c] * s2 + pb[c] - pm[c] * s2;
    }
}

// ---------------- TF32 tensor-core GEMM (cp.async 3-stage, no cvt) ----------------
#define MMA_TF32(d, a0,a1,a2,a3, b0,b1) \
    asm volatile("mma.sync.aligned.m16n8k8.row.col.f32.tf32.tf32.f32 " \
        "{%0,%1,%2,%3},{%4,%5,%6,%7},{%8,%9},{%0,%1,%2,%3};" \
        : "+f"(d[0]),"+f"(d[1]),"+f"(d[2]),"+f"(d[3]) \
        : "r"(a0),"r"(a1),"r"(a2),"r"(a3),"r"(b0),"r"(b1))

#define CP16(s, g)  asm volatile("cp.async.cg.shared.global [%0],[%1],16;\n" :: "r"(s), "l"(g))
#define CP16Z(s, g) asm volatile("cp.async.cg.shared.global [%0],[%1],16,0;\n" :: "r"(s), "l"(g))
#define CPCOMMIT()  asm volatile("cp.async.commit_group;\n")
#define CPWAIT1()   asm volatile("cp.async.wait_group 1;\n")

// C[M,N] = f( alpha * op(A)[M,K] @ op(B)[K,N] )
// MODE 0: C = alpha*AB + (bias ? bias[m] : 0)
// MODE 1: C = AB*scale[m] + bias[m] + R[m,n]
// MODE 2: split-K partial (deterministic; reduced later)
// TA: A stored [K,M] (lda = m-stride). TB: B stored [N,K] (ldb = k-stride).
// Smem layouts mirror the global major order, so cp.async chunks are contiguous:
//   "MK": 128 rows x 16 k, quad-XOR swizzle  -> conflict-free LDS.32 fragment loads
//   "KM": 16 k-rows x 128 cols, natural      -> broadcast LDS.32 fragment loads
// Requires: N % 128 == 0, Kchunk % 16 == 0. M rows >= M zero-filled via cp.async src_size=0.
template<int MODE, bool TA, bool TB>
__global__ __launch_bounds__(256, 2) void gemm_tc(
    const float* __restrict__ A, const float* __restrict__ Bm,
    float* __restrict__ C, const float* __restrict__ R,
    const float* __restrict__ bias, const float* __restrict__ scale,
    int M, int N, int K, int lda, int ldb, int ldc,
    long sA, long sB, long sC, float alpha, int splitK)
{
    int z = blockIdx.z;
    int batch = z / splitK;
    int kslice = z - batch * splitK;
    int Kchunk = K / splitK;
    int k0base = kslice * Kchunk;

    A  += (long)batch * sA;
    Bm += (long)batch * sB;
    if (MODE == 2) C += (long)z * sC;
    else           C += (long)batch * sC;
    if (MODE == 1) R += (long)batch * sC;

    const int m0 = blockIdx.y * 128;
    const int n0 = blockIdx.x * 128;
    const int tid = threadIdx.x;
    const int warp = tid >> 5, lane = tid & 31;
    const int wm = warp >> 2, wn = warp & 3;       // 2 x 4 warp grid
    const int g = lane >> 2, c = lane & 3;
    const int m0w = wm * 64, n0w = wn * 32;

    __shared__ uint32_t SA[3][2048];
    __shared__ uint32_t SB[3][2048];

    float acc[4][4][4];
    #pragma unroll
    for (int i = 0; i < 4; i++)
        #pragma unroll
        for (int j = 0; j < 4; j++)
            #pragma unroll
            for (int e = 0; e < 4; e++) acc[i][j][e] = 0.f;

    const int nk = Kchunk / 16;

    auto issue = [&](int t) {
        int buf = t % 3;
        int k0 = k0base + t * 16;
        uint32_t sbA = (uint32_t)__cvta_generic_to_shared(&SA[buf][0]);
        uint32_t sbB = (uint32_t)__cvta_generic_to_shared(&SB[buf][0]);
        #pragma unroll
        for (int it = 0; it < 2; it++) {
            int f = tid + it * 256;
            // ---- A chunk ----
            if (!TA) {
                int row = f >> 2, j = f & 3;
                const float* gp = A + (long)(m0 + row) * lda + k0 + 4 * j;
                uint32_t sa = sbA + (uint32_t)(row * 16 + ((j ^ ((row >> 1) & 3)) << 2)) * 4u;
                if (m0 + row < M) { CP16(sa, gp); } else { CP16Z(sa, A); }
            } else {
                int k = f >> 5, col = (f & 31) << 2;
                const float* gp = A + (long)(k0 + k) * lda + m0 + col;
                uint32_t sa = sbA + (uint32_t)(k * 128 + col) * 4u;
                if (m0 + col < M) { CP16(sa, gp); } else { CP16Z(sa, A); }
            }
            // ---- B chunk ----
            if (!TB) {
                int k = f >> 5, col = (f & 31) << 2;
                const float* gp = Bm + (long)(k0 + k) * ldb + n0 + col;
                CP16(sbB + (uint32_t)(k * 128 + col) * 4u, gp);
            } else {
                int row = f >> 2, j = f & 3;
                const float* gp = Bm + (long)(n0 + row) * ldb + k0 + 4 * j;
                CP16(sbB + (uint32_t)(row * 16 + ((j ^ ((row >> 1) & 3)) << 2)) * 4u, gp);
            }
        }
    };

    if (0 < nk) issue(0);
    CPCOMMIT();
    if (1 < nk) issue(1);
    CPCOMMIT();

    for (int t = 0; t < nk; t++) {
        CPWAIT1();
        __syncthreads();
        if (t + 2 < nk) issue(t + 2);
        CPCOMMIT();

        int buf = t % 3;
        const uint32_t* sa = SA[buf];
        const uint32_t* sb = SB[buf];

        // B fragments: per n-group j, ks {c, c+4, c+8, c+12}
        uint32_t bf[4][4];
        #pragma unroll
        for (int j = 0; j < 4; j++) {
            int n = n0w + j * 8 + g;
            #pragma unroll
            for (int q = 0; q < 4; q++)
                bf[j][q] = TB ? sb[n * 16 + ((q ^ ((n >> 1) & 3)) << 2) + c]
                              : sb[(c + 4 * q) * 128 + n];
        }
        #pragma unroll
        for (int i = 0; i < 4; i++) {
            int r0 = m0w + i * 16 + g;
            uint32_t af[2][4];
            #pragma unroll
            for (int h = 0; h < 2; h++) {
                int r = r0 + 8 * h;
                #pragma unroll
                for (int q = 0; q < 4; q++)
                    af[h][q] = TA ? sa[(c + 4 * q) * 128 + r]
                                  : sa[r * 16 + ((q ^ ((r >> 1) & 3)) << 2) + c];
            }
            #pragma unroll
            for (int j = 0; j < 4; j++) {
                MMA_TF32(acc[i][j], af[0][0], af[1][0], af[0][1], af[1][1], bf[j][0], bf[j][1]);
                MMA_TF32(acc[i][j], af[0][2], af[1][2], af[0][3], af[1][3], bf[j][2], bf[j][3]);
            }
        }
    }

    // ---- epilogue ----
    #pragma unroll
    for (int i = 0; i < 4; i++) {
        int gm0 = m0 + m0w + i * 16 + g;
        #pragma unroll
        for (int half = 0; half < 2; half++) {
            int gm = gm0 + half * 8;
            if (gm >= M) continue;
            float bv = 0.f, sv = 1.f;
            if (MODE == 0) bv = bias ? bias[gm] : 0.f;
            if (MODE == 1) { bv = bias[gm]; sv = scale[gm]; }
            #pragma unroll
            for (int j = 0; j < 4; j++) {
                int gn = n0 + n0w + j * 8 + 2 * c;
                long idx = (long)gm * ldc + gn;
                float v0 = acc[i][j][half * 2 + 0];
                float v1 = acc[i][j][half * 2 + 1];
                float2 o;
                if (MODE == 0)      { o.x = alpha * v0 + bv;            o.y = alpha * v1 + bv; }
                else if (MODE == 1) { o.x = v0 * sv + bv + R[idx];      o.y = v1 * sv + bv + R[idx + 1]; }
                else                { o.x = alpha * v0;                 o.y = alpha * v1; }
                *reinterpret_cast<float2*>(&C[idx]) = o;
            }
        }
    }
}

// ---------------- deterministic split-K reduce for ATT ----------------
__global__ void att_reduce_kernel() {
    int i = blockIdx.x * 256 + threadIdx.x;     // i < BB*CL*CL
    int b = i / (CL * CL);
    int r = i - b * (CL * CL);
    float s = 0.f;
    #pragma unroll
    for (int ks = 0; ks < SPLITK; ks++)
        s += g_ATTP[((long)b * SPLITK + ks) * (CL * CL) + r];
    g_ATT[i] = s;
}

// ---------------- CBAM: channel pooling (mean+max over HW) ----------------
__global__ void chanpool_kernel() {
    int c = blockIdx.x, b = blockIdx.y;
    int t = threadIdx.x;
    const float* p = g_ZP + ((long)b * CH + c) * HW;
    float s = 0.f, mx = -1e30f;
    for (int i = t; i < HW; i += 256) {
        float v = p[i];
        s += v;
        mx = fmaxf(mx, v);
    }
    __shared__ float ss[256];
    __shared__ float sm[256];
    ss[t] = s; sm[t] = mx;
    __syncthreads();
    for (int o = 128; o > 0; o >>= 1) {
        if (t < o) { ss[t] += ss[t + o]; sm[t] = fmaxf(sm[t], sm[t + o]); }
        __syncthreads();
    }
    if (t == 0) {
        g_pm[b * CH + c] = ss[0] * (1.f / HW);
        g_px[b * CH + c] = sm[0];
    }
}

// ---------------- CBAM: channel-attention MLP ----------------
__global__ void camlp_kernel(const float* __restrict__ fc1, const float* __restrict__ fc2) {
    int b = blockIdx.x;
    int t = threadIdx.x;
    __shared__ float hm[16], hx[16];
    if (t < 16) {
        float s = 0.f;
        for (int c = 0; c < CH; c++) s += fc1[t * CH + c] * g_pm[b * CH + c];
        hm[t] = fmaxf(s, 0.f);
    } else if (t < 32) {
        int h = t - 16;
        float s = 0.f;
        for (int c = 0; c < CH; c++) s += fc1[h * CH + c] * g_px[b * CH + c];
        hx[h] = fmaxf(s, 0.f);
    }
    __syncthreads();
    float sm = 0.f, sx = 0.f;
    #pragma unroll
    for (int h = 0; h < 16; h++) {
        float w = fc2[t * 16 + h];
        sm += w * hm[h];
        sx += w * hx[h];
    }
    g_ca[b * CH + t] = 1.f / (1.f + expf(-(sm + sx)));
}

// ---------------- CBAM: spatial pooling over channels of z_pnl*ca ----------------
__global__ void spool_kernel() {
    __shared__ float cas[CH];
    int idx = blockIdx.x * 256 + threadIdx.x;
    int b = idx / HW;
    int p = idx - b * HW;
    for (int c = threadIdx.x; c < CH; c += 256) cas[c] = g_ca[b * CH + c];
    __syncthreads();
    float s = 0.f, mx = -1e30f;
    for (int c = 0; c < CH; c++) {
        float v = g_ZP[((long)b * CH + c) * HW + p] * cas[c];
        s += v;
        mx = fmaxf(mx, v);
    }
    g_sam[idx] = s * (1.f / CH);
    g_sax[idx] = mx;
}

// ---------------- CBAM: 7x7 spatial conv + sigmoid ----------------
__global__ void sconv_kernel(const float* __restrict__ w) {
    int idx = blockIdx.x * 256 + threadIdx.x;
    int b = idx / HW;
    int p = idx - b * HW;
    int h = p >> 6, wq = p & 63;
    float s = 0.f;
    #pragma unroll
    for (int kh = 0; kh < 7; kh++) {
        int ih = h + kh - 3;
        if (ih < 0 || ih >= 64) continue;
        #pragma unroll
        for (int kw = 0; kw < 7; kw++) {
            int iw = wq + kw - 3;
            if (iw < 0 || iw >= 64) continue;
            int q = (ih << 6) | iw;
            s += w[kh * 7 + kw] * g_sam[b * HW + q] + w[49 + kh * 7 + kw] * g_sax[b * HW + q];
        }
    }
    g_sas[idx] = 1.f / (1.f + expf(-s));
}

// ---------------- final weighted fusion ----------------
__global__ void final_kernel(const float* __restrict__ x, const float* __restrict__ fwp,
                             float* __restrict__ out) {
    long i = (long)blockIdx.x * 256 + threadIdx.x;
    long p = i % HW;
    long bc = i / HW;
    long b = bc / CH;
    float fw = *fwp;
    out[i] = fw * g_ZP[i] * g_ca[bc] * g_sas[b * HW + p] + (1.f - fw) * x[i];
}

// ---------------- launch ----------------
extern "C" void kernel_launch(void* const* d_in, const int* in_sizes, int n_in,
                              void* d_out, int out_size) {
    const float* x   = (const float*)d_in[0];
    const float* x0  = (const float*)d_in[1];
    const float* cgw = (const float*)d_in[2];
    const float* cgb = (const float*)d_in[3];
    const float* ctw = (const float*)d_in[4];
    const float* ctb = (const float*)d_in[5];
    const float* cpw = (const float*)d_in[6];
    const float* cpb = (const float*)d_in[7];
    const float* cWw = (const float*)d_in[8];
    const float* cWb = (const float*)d_in[9];
    const float* cbg = (const float*)d_in[10];
    const float* cbb = (const float*)d_in[11];
    const float* cbm = (const float*)d_in[12];
    const float* cbv = (const float*)d_in[13];
    const float* pgw = (const float*)d_in[14];
    const float* pgb = (const float*)d_in[15];
    const float* ptw = (const float*)d_in[16];
    const float* ptb = (const float*)d_in[17];
    const float* ppw = (const float*)d_in[18];
    const float* ppb = (const float*)d_in[19];
    const float* pWw = (const float*)d_in[20];
    const float* pWb = (const float*)d_in[21];
    const float* pbg = (const float*)d_in[22];
    const float* pbb = (const float*)d_in[23];
    const float* pbm = (const float*)d_in[24];
    const float* pbv = (const float*)d_in[25];
    const float* fc1 = (const float*)d_in[26];
    const float* fc2 = (const float*)d_in[27];
    const float* saw = (const float*)d_in[28];
    const float* fwp = (const float*)d_in[29];
    float* out = (float*)d_out;

    float *TH, *PH, *GX, *Y, *ZC, *G2, *T2, *P2, *Y2, *ZP, *ATTP, *ATT, *ATT2, *S1, *B1, *S2, *B2;
    cudaGetSymbolAddress((void**)&TH,  g_TH);
    cudaGetSymbolAddress((void**)&PH,  g_PH);
    cudaGetSymbolAddress((void**)&GX,  g_GX);
    cudaGetSymbolAddress((void**)&Y,   g_Y);
    cudaGetSymbolAddress((void**)&ZC,  g_ZC);
    cudaGetSymbolAddress((void**)&G2,  g_G2);
    cudaGetSymbolAddress((void**)&T2,  g_T2);
    cudaGetSymbolAddress((void**)&P2,  g_P2);
    cudaGetSymbolAddress((void**)&Y2,  g_Y2);
    cudaGetSymbolAddress((void**)&ZP,  g_ZP);
    cudaGetSymbolAddress((void**)&ATTP, g_ATTP);
    cudaGetSymbolAddress((void**)&ATT, g_ATT);
    cudaGetSymbolAddress((void**)&ATT2, g_ATT2);
    cudaGetSymbolAddress((void**)&S1,  g_s1);
    cudaGetSymbolAddress((void**)&B1,  g_b1);
    cudaGetSymbolAddress((void**)&S2,  g_s2);
    cudaGetSymbolAddress((void**)&B2,  g_b2);

    prep_kernel<<<1, 256>>>(cWb, cbg, cbb, cbm, cbv, pWb, pbg, pbb, pbm, pbv);

    // ---- CNL 1x1 convs ----
    gemm_tc<0,false,false><<<dim3(HW/128, 1, BB), 256>>>(
        ctw, x, TH, nullptr, ctb, nullptr, CL, HW, CH, CH, HW, HW,
        0L, (long)CH*HW, (long)CL*HW, 1.f, 1);
    gemm_tc<0,false,false><<<dim3(HW/128, 1, BB), 256>>>(
        cpw, x0, PH, nullptr, cpb, nullptr, CL, HW, CL, CL, HW, HW,
        0L, (long)CL*HW, (long)CL*HW, 1.f, 1);
    gemm_tc<0,false,false><<<dim3(HW/128, 1, BB), 256>>>(
        cgw, x0, GX, nullptr, cgb, nullptr, CL, HW, CL, CL, HW, HW,
        0L, (long)CL*HW, (long)CL*HW, 1.f, 1);
    // ---- CNL affinity: ATT = TH @ PH^T / Cl  (split-K, deterministic) ----
    gemm_tc<2,false,true><<<dim3(1, 1, BB*SPLITK), 256>>>(
        TH, PH, ATTP, nullptr, nullptr, nullptr, CL, CL, HW, HW, HW, CL,
        (long)CL*HW, (long)CL*HW, (long)CL*CL, 1.f/CL, SPLITK);
    att_reduce_kernel<<<BB*CL*CL/256, 256>>>();
    // ---- Y = ATT @ GX ----
    gemm_tc<0,false,false><<<dim3(HW/128, 1, BB), 256>>>(
        ATT, GX, Y, nullptr, nullptr, nullptr, CL, HW, CL, CL, HW, HW,
        (long)CL*CL, (long)CL*HW, (long)CL*HW, 1.f, 1);
    // ---- Z_CNL = BN(W@Y) + x ----
    gemm_tc<1,false,false><<<dim3(HW/128, CH/128, BB), 256>>>(
        cWw, Y, ZC, x, B1, S1, CH, HW, CL, CL, HW, HW,
        0L, (long)CL*HW, (long)CH*HW, 1.f, 1);

    // ---- PNL 1x1 convs (M=64, zero-filled to 128-row tile) ----
    gemm_tc<0,false,false><<<dim3(HW/128, 1, BB), 256>>>(
        pgw, x0, G2, nullptr, pgb, nullptr, RR, HW, CL, CL, HW, HW,
        0L, (long)CL*HW, (long)RR*HW, 1.f, 1);
    gemm_tc<0,false,false><<<dim3(HW/128, 1, BB), 256>>>(
        ptw, ZC, T2, nullptr, ptb, nullptr, RR, HW, CH, CH, HW, HW,
        0L, (long)CH*HW, (long)RR*HW, 1.f, 1);
    gemm_tc<0,false,false><<<dim3(HW/128, 1, BB), 256>>>(
        ppw, x0, P2, nullptr, ppb, nullptr, RR, HW, CL, CL, HW, HW,
        0L, (long)CL*HW, (long)RR*HW, 1.f, 1);
    // ---- ATT2 = T2view^T @ P2view / M   (views: [CL=128, MM=2048]) ----
    gemm_tc<0,true,false><<<dim3(MM/128, MM/128, BB), 256>>>(
        T2, P2, ATT2, nullptr, nullptr, nullptr, MM, MM, CL, MM, MM, MM,
        (long)RR*HW, (long)RR*HW, (long)MM*MM, 1.f/MM, 1);
    // ---- Y2view = G2view @ ATT2^T ----
    gemm_tc<0,false,true><<<dim3(MM/128, 1, BB), 256>>>(
        G2, ATT2, Y2, nullptr, nullptr, nullptr, CL, MM, MM, MM, MM, MM,
        (long)RR*HW, (long)MM*MM, (long)RR*HW, 1.f, 1);
    // ---- Z_PNL = BN(W@Y2) + Z_CNL ----
    gemm_tc<1,false,false><<<dim3(HW/128, CH/128, BB), 256>>>(
        pWw, Y2, ZP, ZC, B2, S2, CH, HW, RR, RR, HW, HW,
        0L, (long)RR*HW, (long)CH*HW, 1.f, 1);

    // ---- CBAM + fusion ----
    chanpool_kernel<<<dim3(CH, BB), 256>>>();
    camlp_kernel<<<BB, 256>>>(fc1, fc2);
    spool_kernel<<<BB*HW/256, 256>>>();
    sconv_kernel<<<BB*HW/256, 256>>>(saw);
    final_kernel<<<BB*CH*HW/256, 256>>>(x, fwp, out);
}

// round 5
// speedup vs baseline: 4.0122x; 1.8082x over previous
#include <cuda_runtime.h>
#include <cstdint>
#include <math.h>

#define BB 8
#define CH 256
#define CL 128
#define RR 64
#define HW 4096
#define MM 2048
#define SPLITK 32     // ATT affinity (K=4096)
#define SPLITK2 16    // S2 (K=2048)

// ---------------- scratch (static device globals; no runtime alloc) ----------------
__device__ float g_TH[BB*CL*HW];
__device__ float g_PH[BB*CL*HW];
__device__ float g_GX[BB*CL*HW];
__device__ float g_Y [BB*CL*HW];
__device__ float g_ZC[BB*CH*HW];
__device__ float g_GP[BB*2*RR*HW];     // stacked G2 (rows 0-63) | P2 (rows 64-127) per batch
__device__ float g_T2[BB*RR*HW];
__device__ float g_Y2[BB*RR*HW];
__device__ float g_ZP[BB*CH*HW];
__device__ float g_ATT[BB*CL*CL];
__device__ float g_ATTP[BB*SPLITK*CL*CL];
__device__ float g_S2P[BB*SPLITK2*CL*CL];
__device__ float g_S2[BB*CL*CL];
__device__ float g_gpw[CL*CL];         // stacked pgw|ppw
__device__ float g_gpb[CL];
__device__ float g_pm[BB*CH];
__device__ float g_px[BB*CH];
__device__ float g_ca[BB*CH];
__device__ float g_sam[BB*HW];
__device__ float g_sax[BB*HW];
__device__ float g_sas[BB*HW];
__device__ float g_s1[CH], g_b1[CH], g_s2[CH], g_b2[CH];

// ---------------- fused BN scale/bias precompute ----------------
__global__ void prep_kernel(const float* __restrict__ cWb, const float* __restrict__ cg,
                            const float* __restrict__ cb, const float* __restrict__ cm,
                            const float* __restrict__ cv,
                            const float* __restrict__ pWb, const float* __restrict__ pg,
                            const float* __restrict__ pb, const float* __restrict__ pm,
                            const float* __restrict__ pv) {
    int c = threadIdx.x;
    if (c < CH) {
        float s1 = cg[c] * rsqrtf(cv[c] + 1e-5f);
        g_s1[c] = s1;
        g_b1[c] = cWb[c] * s1 + cb[c] - cm[c] * s1;
        float s2 = pg[c] * rsqrtf(pv[c] + 1e-5f);
        g_s2[c] = s2;
        g_b2[c] = pWb[c] * s2 + pb[c] - pm[c] * s2;
    }
}

// ---------------- stack pg/pp weights+biases ----------------
__global__ void stackgp_kernel(const float* __restrict__ pgw, const float* __restrict__ pgb,
                               const float* __restrict__ ppw, const float* __restrict__ ppb) {
    int i = blockIdx.x * 256 + threadIdx.x;   // 0 .. 16383
    g_gpw[i] = (i < RR * CL) ? pgw[i] : ppw[i - RR * CL];
    if (i < RR) g_gpb[i] = pgb[i];
    else if (i < CL) g_gpb[i] = ppb[i - RR];
}

// ---------------- TF32 tensor-core GEMM (cp.async 3-stage, no cvt) ----------------
#define MMA_TF32(d, a0,a1,a2,a3, b0,b1) \
    asm volatile("mma.sync.aligned.m16n8k8.row.col.f32.tf32.tf32.f32 " \
        "{%0,%1,%2,%3},{%4,%5,%6,%7},{%8,%9},{%0,%1,%2,%3};" \
        : "+f"(d[0]),"+f"(d[1]),"+f"(d[2]),"+f"(d[3]) \
        : "r"(a0),"r"(a1),"r"(a2),"r"(a3),"r"(b0),"r"(b1))

#define CP16(s, g)  asm volatile("cp.async.cg.shared.global [%0],[%1],16;\n" :: "r"(s), "l"(g))
#define CP16Z(s, g) asm volatile("cp.async.cg.shared.global [%0],[%1],16,0;\n" :: "r"(s), "l"(g))
#define CPCOMMIT()  asm volatile("cp.async.commit_group;\n")
#define CPWAIT1()   asm volatile("cp.async.wait_group 1;\n")

// C[M,N] = f( alpha * op(A)[M,K] @ op(B)[K,N] )
// MODE 0: C = alpha*AB + (bias ? bias[m] : 0)
// MODE 1: C = AB*scale[m] + bias[m] + R[m,n]
// MODE 2: split-K partial (deterministic; reduced later)
// Smem layouts mirror global major order (cp.async chunks contiguous):
//   "MK": 128 rows x 16 k, quad-XOR swizzle            -> conflict-free
//   "KM": 16 k-rows x 128 cols, col ^ ((k&3)<<3) XOR   -> conflict-free
template<int MODE, bool TA, bool TB>
__global__ __launch_bounds__(256, 2) void gemm_tc(
    const float* __restrict__ A, const float* __restrict__ Bm,
    float* __restrict__ C, const float* __restrict__ R,
    const float* __restrict__ bias, const float* __restrict__ scale,
    int M, int N, int K, int lda, int ldb, int ldc,
    long sA, long sB, long sC, float alpha, int splitK)
{
    int z = blockIdx.z;
    int batch = z / splitK;
    int kslice = z - batch * splitK;
    int Kchunk = K / splitK;
    int k0base = kslice * Kchunk;

    A  += (long)batch * sA;
    Bm += (long)batch * sB;
    if (MODE == 2) C += (long)z * sC;
    else           C += (long)batch * sC;
    if (MODE == 1) R += (long)batch * sC;

    const int m0 = blockIdx.y * 128;
    const int n0 = blockIdx.x * 128;
    const int tid = threadIdx.x;
    const int warp = tid >> 5, lane = tid & 31;
    const int wm = warp >> 2, wn = warp & 3;       // 2 x 4 warp grid
    const int g = lane >> 2, c = lane & 3;
    const int m0w = wm * 64, n0w = wn * 32;

    __shared__ uint32_t SA[3][2048];
    __shared__ uint32_t SB[3][2048];

    float acc[4][4][4];
    #pragma unroll
    for (int i = 0; i < 4; i++)
        #pragma unroll
        for (int j = 0; j < 4; j++)
            #pragma unroll
            for (int e = 0; e < 4; e++) acc[i][j][e] = 0.f;

    const int nk = Kchunk / 16;

    auto issue = [&](int t) {
        int buf = t % 3;
        int k0 = k0base + t * 16;
        uint32_t sbA = (uint32_t)__cvta_generic_to_shared(&SA[buf][0]);
        uint32_t sbB = (uint32_t)__cvta_generic_to_shared(&SB[buf][0]);
        #pragma unroll
        for (int it = 0; it < 2; it++) {
            int f = tid + it * 256;
            // ---- A chunk ----
            if (!TA) {
                int row = f >> 2, j = f & 3;
                const float* gp = A + (long)(m0 + row) * lda + k0 + 4 * j;
                uint32_t sa = sbA + (uint32_t)(row * 16 + ((j ^ ((row >> 1) & 3)) << 2)) * 4u;
                if (m0 + row < M) { CP16(sa, gp); } else { CP16Z(sa, A); }
            } else {
                int k = f >> 5, col = (f & 31) << 2;
                const float* gp = A + (long)(k0 + k) * lda + m0 + col;
                uint32_t sa = sbA + (uint32_t)(k * 128 + (col ^ ((k & 3) << 3))) * 4u;
                if (m0 + col < M) { CP16(sa, gp); } else { CP16Z(sa, A); }
            }
            // ---- B chunk ----
            if (!TB) {
                int k = f >> 5, col = (f & 31) << 2;
                const float* gp = Bm + (long)(k0 + k) * ldb + n0 + col;
                CP16(sbB + (uint32_t)(k * 128 + (col ^ ((k & 3) << 3))) * 4u, gp);
            } else {
                int row = f >> 2, j = f & 3;
                const float* gp = Bm + (long)(n0 + row) * ldb + k0 + 4 * j;
                CP16(sbB + (uint32_t)(row * 16 + ((j ^ ((row >> 1) & 3)) << 2)) * 4u, gp);
            }
        }
    };

    if (0 < nk) issue(0);
    CPCOMMIT();
    if (1 < nk) issue(1);
    CPCOMMIT();

    for (int t = 0; t < nk; t++) {
        CPWAIT1();
        __syncthreads();
        if (t + 2 < nk) issue(t + 2);
        CPCOMMIT();

        int buf = t % 3;
        const uint32_t* sa = SA[buf];
        const uint32_t* sb = SB[buf];

        // B fragments: per n-group j, ks {c, c+4, c+8, c+12}
        uint32_t bf[4][4];
        #pragma unroll
        for (int j = 0; j < 4; j++) {
            int n = n0w + j * 8 + g;
            int nb4 = n & ~3, n3 = n & 3;
            #pragma unroll
            for (int q = 0; q < 4; q++) {
                int k = c + 4 * q;
                bf[j][q] = TB ? sb[n * 16 + ((q ^ ((n >> 1) & 3)) << 2) + c]
                              : sb[k * 128 + (nb4 ^ ((k & 3) << 3)) + n3];
            }
        }
        #pragma unroll
        for (int i = 0; i < 4; i++) {
            int r0 = m0w + i * 16 + g;
            uint32_t af[2][4];
            #pragma unroll
            for (int h = 0; h < 2; h++) {
                int r = r0 + 8 * h;
                int rb4 = r & ~3, r3 = r & 3;
                #pragma unroll
                for (int q = 0; q < 4; q++) {
                    int k = c + 4 * q;
                    af[h][q] = TA ? sa[k * 128 + (rb4 ^ ((k & 3) << 3)) + r3]
                                  : sa[r * 16 + ((q ^ ((r >> 1) & 3)) << 2) + c];
                }
            }
            #pragma unroll
            for (int j = 0; j < 4; j++) {
                MMA_TF32(acc[i][j], af[0][0], af[1][0], af[0][1], af[1][1], bf[j][0], bf[j][1]);
                MMA_TF32(acc[i][j], af[0][2], af[1][2], af[0][3], af[1][3], bf[j][2], bf[j][3]);
            }
        }
    }

    // ---- epilogue ----
    #pragma unroll
    for (int i = 0; i < 4; i++) {
        int gm0 = m0 + m0w + i * 16 + g;
        #pragma unroll
        for (int half = 0; half < 2; half++) {
            int gm = gm0 + half * 8;
            if (gm >= M) continue;
            float bv = 0.f, sv = 1.f;
            if (MODE == 0) bv = bias ? bias[gm] : 0.f;
            if (MODE == 1) { bv = bias[gm]; sv = scale[gm]; }
            #pragma unroll
            for (int j = 0; j < 4; j++) {
                int gn = n0 + n0w + j * 8 + 2 * c;
                long idx = (long)gm * ldc + gn;
                float v0 = acc[i][j][half * 2 + 0];
                float v1 = acc[i][j][half * 2 + 1];
                float2 o;
                if (MODE == 0)      { o.x = alpha * v0 + bv;            o.y = alpha * v1 + bv; }
                else if (MODE == 1) { o.x = v0 * sv + bv + R[idx];      o.y = v1 * sv + bv + R[idx + 1]; }
                else                { o.x = alpha * v0;                 o.y = alpha * v1; }
                *reinterpret_cast<float2*>(&C[idx]) = o;
            }
        }
    }
}

// ---------------- deterministic split-K reduce ----------------
__global__ void reduce_splitk(const float* __restrict__ src, float* __restrict__ dst,
                              int per, int nslice) {
    int i = blockIdx.x * 256 + threadIdx.x;
    int b = i / per;
    int r = i - b * per;
    float s = 0.f;
    for (int k = 0; k < nslice; k++)
        s += src[((long)b * nslice + k) * per + r];
    dst[i] = s;
}

// ---------------- CBAM: channel pooling (mean+max over HW) ----------------
__global__ void chanpool_kernel() {
    int c = blockIdx.x, b = blockIdx.y;
    int t = threadIdx.x;
    const float* p = g_ZP + ((long)b * CH + c) * HW;
    float s = 0.f, mx = -1e30f;
    for (int i = t; i < HW; i += 256) {
        float v = p[i];
        s += v;
        mx = fmaxf(mx, v);
    }
    __shared__ float ss[256];
    __shared__ float sm[256];
    ss[t] = s; sm[t] = mx;
    __syncthreads();
    for (int o = 128; o > 0; o >>= 1) {
        if (t < o) { ss[t] += ss[t + o]; sm[t] = fmaxf(sm[t], sm[t + o]); }
        __syncthreads();
    }
    if (t == 0) {
        g_pm[b * CH + c] = ss[0] * (1.f / HW);
        g_px[b * CH + c] = sm[0];
    }
}

// ---------------- CBAM: channel-attention MLP ----------------
__global__ void camlp_kernel(const float* __restrict__ fc1, const float* __restrict__ fc2) {
    int b = blockIdx.x;
    int t = threadIdx.x;
    __shared__ float hm[16], hx[16];
    if (t < 16) {
        float s = 0.f;
        for (int c = 0; c < CH; c++) s += fc1[t * CH + c] * g_pm[b * CH + c];
        hm[t] = fmaxf(s, 0.f);
    } else if (t < 32) {
        int h = t - 16;
        float s = 0.f;
        for (int c = 0; c < CH; c++) s += fc1[h * CH + c] * g_px[b * CH + c];
        hx[h] = fmaxf(s, 0.f);
    }
    __syncthreads();
    float sm = 0.f, sx = 0.f;
    #pragma unroll
    for (int h = 0; h < 16; h++) {
        float w = fc2[t * 16 + h];
        sm += w * hm[h];
        sx += w * hx[h];
    }
    g_ca[b * CH + t] = 1.f / (1.f + expf(-(sm + sx)));
}

// ---------------- CBAM: spatial pooling over channels of z_pnl*ca ----------------
__global__ void spool_kernel() {
    __shared__ float cas[CH];
    int idx = blockIdx.x * 256 + threadIdx.x;
    int b = idx / HW;
    int p = idx - b * HW;
    for (int c = threadIdx.x; c < CH; c += 256) cas[c] = g_ca[b * CH + c];
    __syncthreads();
    float s = 0.f, mx = -1e30f;
    for (int c = 0; c < CH; c++) {
        float v = g_ZP[((long)b * CH + c) * HW + p] * cas[c];
        s += v;
        mx = fmaxf(mx, v);
    }
    g_sam[idx] = s * (1.f / CH);
    g_sax[idx] = mx;
}

// ---------------- CBAM: 7x7 spatial conv + sigmoid ----------------
__global__ void sconv_kernel(const float* __restrict__ w) {
    int idx = blockIdx.x * 256 + threadIdx.x;
    int b = idx / HW;
    int p = idx - b * HW;
    int h = p >> 6, wq = p & 63;
    float s = 0.f;
    #pragma unroll
    for (int kh = 0; kh < 7; kh++) {
        int ih = h + kh - 3;
        if (ih < 0 || ih >= 64) continue;
        #pragma unroll
        for (int kw = 0; kw < 7; kw++) {
            int iw = wq + kw - 3;
            if (iw < 0 || iw >= 64) continue;
            int q = (ih << 6) | iw;
            s += w[kh * 7 + kw] * g_sam[b * HW + q] + w[49 + kh * 7 + kw] * g_sax[b * HW + q];
        }
    }
    g_sas[idx] = 1.f / (1.f + expf(-s));
}

// ---------------- final weighted fusion ----------------
__global__ void final_kernel(const float* __restrict__ x, const float* __restrict__ fwp,
                             float* __restrict__ out) {
    long i = (long)blockIdx.x * 256 + threadIdx.x;
    long p = i % HW;
    long bc = i / HW;
    long b = bc / CH;
    float fw = *fwp;
    out[i] = fw * g_ZP[i] * g_ca[bc] * g_sas[b * HW + p] + (1.f - fw) * x[i];
}

// ---------------- launch ----------------
extern "C" void kernel_launch(void* const* d_in, const int* in_sizes, int n_in,
                              void* d_out, int out_size) {
    const float* x   = (const float*)d_in[0];
    const float* x0  = (const float*)d_in[1];
    const float* cgw = (const float*)d_in[2];
    const float* cgb = (const float*)d_in[3];
    const float* ctw = (const float*)d_in[4];
    const float* ctb = (const float*)d_in[5];
    const float* cpw = (const float*)d_in[6];
    const float* cpb = (const float*)d_in[7];
    const float* cWw = (const float*)d_in[8];
    const float* cWb = (const float*)d_in[9];
    const float* cbg = (const float*)d_in[10];
    const float* cbb = (const float*)d_in[11];
    const float* cbm = (const float*)d_in[12];
    const float* cbv = (const float*)d_in[13];
    const float* pgw = (const float*)d_in[14];
    const float* pgb = (const float*)d_in[15];
    const float* ptw = (const float*)d_in[16];
    const float* ptb = (const float*)d_in[17];
    const float* ppw = (const float*)d_in[18];
    const float* ppb = (const float*)d_in[19];
    const float* pWw = (const float*)d_in[20];
    const float* pWb = (const float*)d_in[21];
    const float* pbg = (const float*)d_in[22];
    const float* pbb = (const float*)d_in[23];
    const float* pbm = (const float*)d_in[24];
    const float* pbv = (const float*)d_in[25];
    const float* fc1 = (const float*)d_in[26];
    const float* fc2 = (const float*)d_in[27];
    const float* saw = (const float*)d_in[28];
    const float* fwp = (const float*)d_in[29];
    float* out = (float*)d_out;

    float *TH, *PH, *GX, *Y, *ZC, *GP, *T2, *Y2, *ZP, *ATTP, *ATT, *S2P, *S2;
    float *GPW, *GPB, *S1, *B1, *S2b, *B2;
    cudaGetSymbolAddress((void**)&TH,  g_TH);
    cudaGetSymbolAddress((void**)&PH,  g_PH);
    cudaGetSymbolAddress((void**)&GX,  g_GX);
    cudaGetSymbolAddress((void**)&Y,   g_Y);
    cudaGetSymbolAddress((void**)&ZC,  g_ZC);
    cudaGetSymbolAddress((void**)&GP,  g_GP);
    cudaGetSymbolAddress((void**)&T2,  g_T2);
    cudaGetSymbolAddress((void**)&Y2,  g_Y2);
    cudaGetSymbolAddress((void**)&ZP,  g_ZP);
    cudaGetSymbolAddress((void**)&ATTP, g_ATTP);
    cudaGetSymbolAddress((void**)&ATT, g_ATT);
    cudaGetSymbolAddress((void**)&S2P, g_S2P);
    cudaGetSymbolAddress((void**)&S2,  g_S2);
    cudaGetSymbolAddress((void**)&GPW, g_gpw);
    cudaGetSymbolAddress((void**)&GPB, g_gpb);
    cudaGetSymbolAddress((void**)&S1,  g_s1);
    cudaGetSymbolAddress((void**)&B1,  g_b1);
    cudaGetSymbolAddress((void**)&S2b, g_s2);
    cudaGetSymbolAddress((void**)&B2,  g_b2);

    prep_kernel<<<1, 256>>>(cWb, cbg, cbb, cbm, cbv, pWb, pbg, pbb, pbm, pbv);
    stackgp_kernel<<<CL*CL/256, 256>>>(pgw, pgb, ppw, ppb);

    // ---- CNL 1x1 convs ----
    gemm_tc<0,false,false><<<dim3(HW/128, 1, BB), 256>>>(
        ctw, x, TH, nullptr, ctb, nullptr, CL, HW, CH, CH, HW, HW,
        0L, (long)CH*HW, (long)CL*HW, 1.f, 1);
    gemm_tc<0,false,false><<<dim3(HW/128, 1, BB), 256>>>(
        cpw, x0, PH, nullptr, cpb, nullptr, CL, HW, CL, CL, HW, HW,
        0L, (long)CL*HW, (long)CL*HW, 1.f, 1);
    gemm_tc<0,false,false><<<dim3(HW/128, 1, BB), 256>>>(
        cgw, x0, GX, nullptr, cgb, nullptr, CL, HW, CL, CL, HW, HW,
        0L, (long)CL*HW, (long)CL*HW, 1.f, 1);
    // ---- CNL affinity: ATT = TH @ PH^T / Cl  (split-K, deterministic) ----
    gemm_tc<2,false,true><<<dim3(1, 1, BB*SPLITK), 256>>>(
        TH, PH, ATTP, nullptr, nullptr, nullptr, CL, CL, HW, HW, HW, CL,
        (long)CL*HW, (long)CL*HW, (long)CL*CL, 1.f/CL, SPLITK);
    reduce_splitk<<<BB*CL*CL/256, 256>>>(ATTP, ATT, CL*CL, SPLITK);
    // ---- Y = ATT @ GX ----
    gemm_tc<0,false,false><<<dim3(HW/128, 1, BB), 256>>>(
        ATT, GX, Y, nullptr, nullptr, nullptr, CL, HW, CL, CL, HW, HW,
        (long)CL*CL, (long)CL*HW, (long)CL*HW, 1.f, 1);
    // ---- Z_CNL = BN(W@Y) + x ----
    gemm_tc<1,false,false><<<dim3(HW/128, CH/128, BB), 256>>>(
        cWw, Y, ZC, x, B1, S1, CH, HW, CL, CL, HW, HW,
        0L, (long)CL*HW, (long)CH*HW, 1.f, 1);

    // ---- PNL convs: stacked G2|P2 (M=128 exact), T2 (M=64 zero-padded) ----
    gemm_tc<0,false,false><<<dim3(HW/128, 1, BB), 256>>>(
        GPW, x0, GP, nullptr, GPB, nullptr, CL, HW, CL, CL, HW, HW,
        0L, (long)CL*HW, (long)2*RR*HW, 1.f, 1);
    gemm_tc<0,false,false><<<dim3(HW/128, 1, BB), 256>>>(
        ptw, ZC, T2, nullptr, ptb, nullptr, RR, HW, CH, CH, HW, HW,
        0L, (long)CH*HW, (long)RR*HW, 1.f, 1);
    // ---- PNL reassociated: S2 = (G2v @ P2v^T)/M  then  Y2v = S2 @ T2v ----
    // G2v = GP rows 0-63 viewed [128, 2048]; P2v = GP rows 64-127 viewed [128, 2048]
    gemm_tc<2,false,true><<<dim3(1, 1, BB*SPLITK2), 256>>>(
        GP, GP + (long)RR*HW, S2P, nullptr, nullptr, nullptr, CL, CL, MM, MM, MM, CL,
        (long)2*RR*HW, (long)2*RR*HW, (long)CL*CL, 1.f/MM, SPLITK2);
    reduce_splitk<<<BB*CL*CL/256, 256>>>(S2P, S2, CL*CL, SPLITK2);
    gemm_tc<0,false,false><<<dim3(MM/128, 1, BB), 256>>>(
        S2, T2, Y2, nullptr, nullptr, nullptr, CL, MM, CL, CL, MM, MM,
        (long)CL*CL, (long)RR*HW, (long)RR*HW, 1.f, 1);
    // ---- Z_PNL = BN(W@Y2) + Z_CNL ----
    gemm_tc<1,false,false><<<dim3(HW/128, CH/128, BB), 256>>>(
        pWw, Y2, ZP, ZC, B2, S2b, CH, HW, RR, RR, HW, HW,
        0L, (long)RR*HW, (long)CH*HW, 1.f, 1);

    // ---- CBAM + fusion ----
    chanpool_kernel<<<dim3(CH, BB), 256>>>();
    camlp_kernel<<<BB, 256>>>(fc1, fc2);
    spool_kernel<<<BB*HW/256, 256>>>();
    sconv_kernel<<<BB*HW/256, 256>>>(saw);
    final_kernel<<<BB*CH*HW/256, 256>>>(x, fwp, out);
}

// round 6
// speedup vs baseline: 4.5593x; 1.1364x over previous
#include <cuda_runtime.h>
#include <cuda_bf16.h>
#include <cstdint>
#include <math.h>

#define BB 8
#define CH 256
#define CL 128
#define RR 64
#define HW 4096
#define MM 2048
#define SPLITK 32     // ATT affinity (K=4096)
#define SPLITK2 16    // S2 (K=2048)

// ---------------- scratch (static device globals; no runtime alloc) ----------------
__device__ __align__(16) __nv_bfloat16 g_xb  [BB*CH*HW];
__device__ __align__(16) __nv_bfloat16 g_x0b [BB*CL*HW];
__device__ __align__(16) __nv_bfloat16 g_THb [BB*CL*HW];
__device__ __align__(16) __nv_bfloat16 g_PHGXb[BB*2*CL*HW];   // PH rows 0-127 | GX rows 128-255
__device__ __align__(16) __nv_bfloat16 g_Yb  [BB*CL*HW];
__device__ __align__(16) __nv_bfloat16 g_ZCb [BB*CH*HW];
__device__ __align__(16) __nv_bfloat16 g_GPb [BB*2*RR*HW];    // G2 rows 0-63 | P2 rows 64-127
__device__ __align__(16) __nv_bfloat16 g_T2b [BB*RR*HW];
__device__ __align__(16) __nv_bfloat16 g_Y2b [BB*RR*HW];
__device__ __align__(16) __nv_bfloat16 g_ATTb[BB*CL*CL];
__device__ __align__(16) __nv_bfloat16 g_S2b [BB*CL*CL];
__device__ __align__(16) __nv_bfloat16 g_ctwb[CL*CH];
__device__ __align__(16) __nv_bfloat16 g_cWwb[CH*CL];
__device__ __align__(16) __nv_bfloat16 g_ptwb[RR*CH];
__device__ __align__(16) __nv_bfloat16 g_pWwb[CH*RR];
__device__ __align__(16) __nv_bfloat16 g_gpwb[CL*CL];         // pgw|ppw stacked
__device__ __align__(16) __nv_bfloat16 g_pgxwb[2*CL*CL];      // cpw|cgw stacked
__device__ float g_ZC[BB*CH*HW];
__device__ float g_ZP[BB*CH*HW];
__device__ float g_ATTP[BB*SPLITK*CL*CL];
__device__ float g_S2P[BB*SPLITK2*CL*CL];
__device__ float g_ATT[BB*CL*CL];
__device__ float g_S2[BB*CL*CL];
__device__ float g_gpb[CL];
__device__ float g_pgxb[2*CL];
__device__ float g_pm[BB*CH];
__device__ float g_px[BB*CH];
__device__ float g_ca[BB*CH];
__device__ float g_sam[BB*HW];
__device__ float g_sax[BB*HW];
__device__ float g_sas[BB*HW];
__device__ float g_s1[CH], g_b1[CH], g_s2v[CH], g_b2v[CH];

// ---------------- fused BN scale/bias precompute ----------------
__global__ void prep_kernel(const float* __restrict__ cWb, const float* __restrict__ cg,
                            const float* __restrict__ cb, const float* __restrict__ cm,
                            const float* __restrict__ cv,
                            const float* __restrict__ pWb, const float* __restrict__ pg,
                            const float* __restrict__ pb, const float* __restrict__ pm,
                            const float* __restrict__ pv) {
    int c = threadIdx.x;
    if (c < CH) {
        float s1 = cg[c] * rsqrtf(cv[c] + 1e-5f);
        g_s1[c] = s1;
        g_b1[c] = cWb[c] * s1 + cb[c] - cm[c] * s1;
        float s2 = pg[c] * rsqrtf(pv[c] + 1e-5f);
        g_s2v[c] = s2;
        g_b2v[c] = pWb[c] * s2 + pb[c] - pm[c] * s2;
    }
}

// ---------------- weight convert + stack (bf16) ----------------
__global__ void wprep_kernel(const float* __restrict__ ctw, const float* __restrict__ cWw,
                             const float* __restrict__ ptw, const float* __restrict__ pWw,
                             const float* __restrict__ pgw, const float* __restrict__ ppw,
                             const float* __restrict__ cpw, const float* __restrict__ cgw,
                             const float* __restrict__ pgb, const float* __restrict__ ppb,
                             const float* __restrict__ cpb, const float* __restrict__ cgb) {
    int i = blockIdx.x * 256 + threadIdx.x;   // < 32768
    g_ctwb[i] = __float2bfloat16(ctw[i]);
    g_cWwb[i] = __float2bfloat16(cWw[i]);
    g_pgxwb[i] = __float2bfloat16(i < CL*CL ? cpw[i] : cgw[i - CL*CL]);
    if (i < RR*CH) { g_ptwb[i] = __float2bfloat16(ptw[i]); g_pWwb[i] = __float2bfloat16(pWw[i]); }
    if (i < CL*CL) g_gpwb[i] = __float2bfloat16(i < RR*CL ? pgw[i] : ppw[i - RR*CL]);
    if (i < 2*CL) g_pgxb[i] = (i < CL) ? cpb[i] : cgb[i - CL];
    if (i < CL)   g_gpb[i]  = (i < RR) ? pgb[i] : ppb[i - RR];
}

// ---------------- fp32 -> bf16 bulk convert ----------------
__global__ void f2b_kernel(const float* __restrict__ in, __nv_bfloat16* __restrict__ out) {
    int i = blockIdx.x * 256 + threadIdx.x;
    float2 v = *reinterpret_cast<const float2*>(in + 2 * i);
    __nv_bfloat162 h;
    h.x = __float2bfloat16(v.x); h.y = __float2bfloat16(v.y);
    *reinterpret_cast<__nv_bfloat162*>(out + 2 * i) = h;
}

// ---------------- BF16 tensor-core GEMM (cp.async 3-stage + ldmatrix) ----------------
#define MMA_BF16(d, a0,a1,a2,a3, b0,b1) \
    asm volatile("mma.sync.aligned.m16n8k16.row.col.f32.bf16.bf16.f32 " \
        "{%0,%1,%2,%3},{%4,%5,%6,%7},{%8,%9},{%0,%1,%2,%3};" \
        : "+f"(d[0]),"+f"(d[1]),"+f"(d[2]),"+f"(d[3]) \
        : "r"(a0),"r"(a1),"r"(a2),"r"(a3),"r"(b0),"r"(b1))

#define LDSM4(r0,r1,r2,r3, ad) \
    asm volatile("ldmatrix.sync.aligned.m8n8.x4.shared.b16 {%0,%1,%2,%3},[%4];" \
        : "=r"(r0),"=r"(r1),"=r"(r2),"=r"(r3) : "r"(ad))
#define LDSM4T(r0,r1,r2,r3, ad) \
    asm volatile("ldmatrix.sync.aligned.m8n8.x4.trans.shared.b16 {%0,%1,%2,%3},[%4];" \
        : "=r"(r0),"=r"(r1),"=r"(r2),"=r"(r3) : "r"(ad))

#define CP16(s, g)  asm volatile("cp.async.cg.shared.global [%0],[%1],16;\n" :: "r"(s), "l"(g))
#define CP16Z(s, g) asm volatile("cp.async.cg.shared.global [%0],[%1],16,0;\n" :: "r"(s), "l"(g))
#define CPCOMMIT()  asm volatile("cp.async.commit_group;\n")
#define CPWAIT1()   asm volatile("cp.async.wait_group 1;\n")

// C[M,N] = f( alpha * A[M,K] @ op(B)[K,N] ), bf16 operands, fp32 accum.
// MODE 0: out = alpha*AB + (bias ? bias[m] : 0)
// MODE 1: out = AB*scale[m] + bias[m] + R[m,n]
// MODE 2: split-K partial (fp32 C only; deterministic reduce later)
// C (fp32) and/or CB (bf16) stores, either may be null.
// A row-major [M,K]. TB: B row-major [N,K]; else B row-major [K,N].
// Block tile 128x128, k-step 32, 3-stage cp.async, all fragment loads via ldmatrix.
// Smem: 64B-row layout (A, TB-B) chunk ^ ((row>>1)&3); 256B-row (KM-B) chunk ^ (k&7).
template<int MODE, bool TB>
__global__ __launch_bounds__(256, 2) void gemm_bf(
    const __nv_bfloat16* __restrict__ A, const __nv_bfloat16* __restrict__ Bm,
    float* __restrict__ C, __nv_bfloat16* __restrict__ CB,
    const float* __restrict__ R,
    const float* __restrict__ bias, const float* __restrict__ scale,
    int M, int N, int K, int lda, int ldb, int ldc,
    long sA, long sB, long sC, float alpha, int splitK)
{
    int z = blockIdx.z;
    int batch = z / splitK;
    int kslice = z - batch * splitK;
    int Kchunk = K / splitK;
    int k0base = kslice * Kchunk;

    A  += (long)batch * sA;
    Bm += (long)batch * sB;
    if (MODE == 2) C += (long)z * sC;
    else {
        if (C)  C  += (long)batch * sC;
        if (CB) CB += (long)batch * sC;
        if (MODE == 1) R += (long)batch * sC;
    }

    const int m0 = blockIdx.y * 128;
    const int n0 = blockIdx.x * 128;
    const int tid = threadIdx.x;
    const int warp = tid >> 5, lane = tid & 31;
    const int wm = warp >> 2, wn = warp & 3;       // 2 x 4 warp grid
    const int g = lane >> 2, c = lane & 3;
    const int mi = lane >> 3, lr = lane & 7;
    const int m0w = wm * 64, n0w = wn * 32;

    __shared__ uint32_t SA[3][2048];   // 8KB/stage: 128 rows x 32 bf16
    __shared__ uint32_t SB[3][2048];   // 8KB/stage

    float acc[4][4][4];
    #pragma unroll
    for (int i = 0; i < 4; i++)
        #pragma unroll
        for (int j = 0; j < 4; j++)
            #pragma unroll
            for (int e = 0; e < 4; e++) acc[i][j][e] = 0.f;

    const int nk = Kchunk / 32;

    auto issue = [&](int t) {
        int buf = t % 3;
        int k0 = k0base + t * 32;
        uint32_t sbA = (uint32_t)__cvta_generic_to_shared(&SA[buf][0]);
        uint32_t sbB = (uint32_t)__cvta_generic_to_shared(&SB[buf][0]);
        #pragma unroll
        for (int it = 0; it < 2; it++) {
            int f = tid + it * 256;
            {   // A: [M,K] rows of 32 bf16 (64B), chunk cn of 8 bf16
                int row = f >> 2, cn = f & 3;
                const __nv_bfloat16* gp = A + (long)(m0 + row) * lda + k0 + cn * 8;
                uint32_t sa = sbA + (uint32_t)(row * 4 + (cn ^ ((row >> 1) & 3))) * 16u;
                if (m0 + row < M) { CP16(sa, gp); } else { CP16Z(sa, A); }
            }
            if (!TB) {   // B: [K,N] rows of 128 bf16 (256B), chunk cn of 8 n
                int k = f >> 4, cn = f & 15;
                const __nv_bfloat16* gp = Bm + (long)(k0 + k) * ldb + n0 + cn * 8;
                CP16(sbB + (uint32_t)(k * 16 + (cn ^ (k & 7))) * 16u, gp);
            } else {     // B: [N,K] rows of 32 bf16
                int row = f >> 2, cn = f & 3;
                const __nv_bfloat16* gp = Bm + (long)(n0 + row) * ldb + k0 + cn * 8;
                CP16(sbB + (uint32_t)(row * 4 + (cn ^ ((row >> 1) & 3))) * 16u, gp);
            }
        }
    };

    if (0 < nk) issue(0);
    CPCOMMIT();
    if (1 < nk) issue(1);
    CPCOMMIT();

    for (int t = 0; t < nk; t++) {
        CPWAIT1();
        __syncthreads();
        if (t + 2 < nk) issue(t + 2);
        CPCOMMIT();

        int buf = t % 3;
        uint32_t baseA = (uint32_t)__cvta_generic_to_shared(&SA[buf][0]);
        uint32_t baseB = (uint32_t)__cvta_generic_to_shared(&SB[buf][0]);

        #pragma unroll
        for (int s = 0; s < 2; s++) {       // two k16 slices of the k32 tile
            uint32_t bfr[4][2];
            if (!TB) {
                int krow = 16 * s + (mi & 1) * 8 + lr;
                #pragma unroll
                for (int p = 0; p < 2; p++) {
                    int chunk = wn * 4 + 2 * p + (mi >> 1);
                    uint32_t ad = baseB + (uint32_t)(krow * 16 + (chunk ^ (krow & 7))) * 16u;
                    LDSM4T(bfr[2*p][0], bfr[2*p][1], bfr[2*p+1][0], bfr[2*p+1][1], ad);
                }
            } else {
                #pragma unroll
                for (int p = 0; p < 2; p++) {
                    int nrow = n0w + 16 * p + 8 * (mi >> 1) + lr;
                    int chunk = 2 * s + (mi & 1);
                    uint32_t ad = baseB + (uint32_t)(nrow * 4 + (chunk ^ ((nrow >> 1) & 3))) * 16u;
                    LDSM4(bfr[2*p][0], bfr[2*p][1], bfr[2*p+1][0], bfr[2*p+1][1], ad);
                }
            }
            #pragma unroll
            for (int i = 0; i < 4; i++) {
                int row = m0w + 16 * i + (mi & 1) * 8 + lr;
                int chunk = 2 * s + (mi >> 1);
                uint32_t ad = baseA + (uint32_t)(row * 4 + (chunk ^ ((row >> 1) & 3))) * 16u;
                uint32_t a0, a1, a2, a3;
                LDSM4(a0, a1, a2, a3, ad);
                #pragma unroll
                for (int j = 0; j < 4; j++)
                    MMA_BF16(acc[i][j], a0, a1, a2, a3, bfr[j][0], bfr[j][1]);
            }
        }
    }

    // ---- epilogue ----
    #pragma unroll
    for (int i = 0; i < 4; i++) {
        int gm0 = m0 + m0w + i * 16 + g;
        #pragma unroll
        for (int half = 0; half < 2; half++) {
            int gm = gm0 + half * 8;
            if (gm >= M) continue;
            float bv = 0.f, sv = 1.f;
            if (MODE == 0) bv = bias ? bias[gm] : 0.f;
            if (MODE == 1) { bv = bias[gm]; sv = scale[gm]; }
            #pragma unroll
            for (int j = 0; j < 4; j++) {
                int gn = n0 + n0w + j * 8 + 2 * c;
                long idx = (long)gm * ldc + gn;
                float v0 = acc[i][j][half * 2 + 0];
                float v1 = acc[i][j][half * 2 + 1];
                float2 o;
                if (MODE == 0)      { o.x = alpha * v0 + bv;            o.y = alpha * v1 + bv; }
                else if (MODE == 1) { o.x = v0 * sv + bv + R[idx];      o.y = v1 * sv + bv + R[idx + 1]; }
                else                { o.x = alpha * v0;                 o.y = alpha * v1; }
                if (MODE == 2 || C) *reinterpret_cast<float2*>(&C[idx]) = o;
                if (MODE != 2 && CB) {
                    __nv_bfloat162 h;
                    h.x = __float2bfloat16(o.x); h.y = __float2bfloat16(o.y);
                    *reinterpret_cast<__nv_bfloat162*>(&CB[idx]) = h;
                }
            }
        }
    }
}

// ---------------- deterministic split-K reduce (fp32 + bf16 out) ----------------
__global__ void reduce_splitk(const float* __restrict__ src, float* __restrict__ dst,
                              __nv_bfloat16* __restrict__ dstb, int per, int nslice) {
    int i = blockIdx.x * 256 + threadIdx.x;
    int b = i / per;
    int r = i - b * per;
    float s = 0.f;
    for (int k = 0; k < nslice; k++)
        s += src[((long)b * nslice + k) * per + r];
    dst[i] = s;
    dstb[i] = __float2bfloat16(s);
}

// ---------------- CBAM: channel pooling (mean+max over HW) ----------------
__global__ void chanpool_kernel() {
    int c = blockIdx.x, b = blockIdx.y;
    int t = threadIdx.x;
    const float* p = g_ZP + ((long)b * CH + c) * HW;
    float s = 0.f, mx = -1e30f;
    for (int i = t; i < HW; i += 256) {
        float v = p[i];
        s += v;
        mx = fmaxf(mx, v);
    }
    __shared__ float ss[256];
    __shared__ float sm[256];
    ss[t] = s; sm[t] = mx;
    __syncthreads();
    for (int o = 128; o > 0; o >>= 1) {
        if (t < o) { ss[t] += ss[t + o]; sm[t] = fmaxf(sm[t], sm[t + o]); }
        __syncthreads();
    }
    if (t == 0) {
        g_pm[b * CH + c] = ss[0] * (1.f / HW);
        g_px[b * CH + c] = sm[0];
    }
}

// ---------------- CBAM: channel-attention MLP ----------------
__global__ void camlp_kernel(const float* __restrict__ fc1, const float* __restrict__ fc2) {
    int b = blockIdx.x;
    int t = threadIdx.x;
    __shared__ float hm[16], hx[16];
    if (t < 16) {
        float s = 0.f;
        for (int c = 0; c < CH; c++) s += fc1[t * CH + c] * g_pm[b * CH + c];
        hm[t] = fmaxf(s, 0.f);
    } else if (t < 32) {
        int h = t - 16;
        float s = 0.f;
        for (int c = 0; c < CH; c++) s += fc1[h * CH + c] * g_px[b * CH + c];
        hx[h] = fmaxf(s, 0.f);
    }
    __syncthreads();
    float sm = 0.f, sx = 0.f;
    #pragma unroll
    for (int h = 0; h < 16; h++) {
        float w = fc2[t * 16 + h];
        sm += w * hm[h];
        sx += w * hx[h];
    }
    g_ca[b * CH + t] = 1.f / (1.f + expf(-(sm + sx)));
}

// ---------------- CBAM: spatial pooling over channels of z_pnl*ca ----------------
__global__ void spool_kernel() {
    __shared__ float cas[CH];
    int idx = blockIdx.x * 256 + threadIdx.x;
    int b = idx / HW;
    int p = idx - b * HW;
    for (int c = threadIdx.x; c < CH; c += 256) cas[c] = g_ca[b * CH + c];
    __syncthreads();
    float s = 0.f, mx = -1e30f;
    for (int c = 0; c < CH; c++) {
        float v = g_ZP[((long)b * CH + c) * HW + p] * cas[c];
        s += v;
        mx = fmaxf(mx, v);
    }
    g_sam[idx] = s * (1.f / CH);
    g_sax[idx] = mx;
}

// ---------------- CBAM: 7x7 spatial conv + sigmoid ----------------
__global__ void sconv_kernel(const float* __restrict__ w) {
    int idx = blockIdx.x * 256 + threadIdx.x;
    int b = idx / HW;
    int p = idx - b * HW;
    int h = p >> 6, wq = p & 63;
    float s = 0.f;
    #pragma unroll
    for (int kh = 0; kh < 7; kh++) {
        int ih = h + kh - 3;
        if (ih < 0 || ih >= 64) continue;
        #pragma unroll
        for (int kw = 0; kw < 7; kw++) {
            int iw = wq + kw - 3;
            if (iw < 0 || iw >= 64) continue;
            int q = (ih << 6) | iw;
            s += w[kh * 7 + kw] * g_sam[b * HW + q] + w[49 + kh * 7 + kw] * g_sax[b * HW + q];
        }
    }
    g_sas[idx] = 1.f / (1.f + expf(-s));
}

// ---------------- final weighted fusion ----------------
__global__ void final_kernel(const float* __restrict__ x, const float* __restrict__ fwp,
                             float* __restrict__ out) {
    long i = (long)blockIdx.x * 256 + threadIdx.x;
    long p = i % HW;
    long bc = i / HW;
    long b = bc / CH;
    float fw = *fwp;
    out[i] = fw * g_ZP[i] * g_ca[bc] * g_sas[b * HW + p] + (1.f - fw) * x[i];
}

// ---------------- launch ----------------
extern "C" void kernel_launch(void* const* d_in, const int* in_sizes, int n_in,
                              void* d_out, int out_size) {
    const float* x   = (const float*)d_in[0];
    const float* x0  = (const float*)d_in[1];
    const float* cgw = (const float*)d_in[2];
    const float* cgb = (const float*)d_in[3];
    const float* ctw = (const float*)d_in[4];
    const float* ctb = (const float*)d_in[5];
    const float* cpw = (const float*)d_in[6];
    const float* cpb = (const float*)d_in[7];
    const float* cWw = (const float*)d_in[8];
    const float* cWb = (const float*)d_in[9];
    const float* cbg = (const float*)d_in[10];
    const float* cbb = (const float*)d_in[11];
    const float* cbm = (const float*)d_in[12];
    const float* cbv = (const float*)d_in[13];
    const float* pgw = (const float*)d_in[14];
    const float* pgb = (const float*)d_in[15];
    const float* ptw = (const float*)d_in[16];
    const float* ptb = (const float*)d_in[17];
    const float* ppw = (const float*)d_in[18];
    const float* ppb = (const float*)d_in[19];
    const float* pWw = (const float*)d_in[20];
    const float* pWb = (const float*)d_in[21];
    const float* pbg = (const float*)d_in[22];
    const float* pbb = (const float*)d_in[23];
    const float* pbm = (const float*)d_in[24];
    const float* pbv = (const float*)d_in[25];
    const float* fc1 = (const float*)d_in[26];
    const float* fc2 = (const float*)d_in[27];
    const float* saw = (const float*)d_in[28];
    const float* fwp = (const float*)d_in[29];
    float* out = (float*)d_out;

    __nv_bfloat16 *XB, *X0B, *THB, *PHGXB, *YB, *ZCB, *GPB, *T2B, *Y2B, *ATTB, *S2B;
    __nv_bfloat16 *CTWB, *CWWB, *PTWB, *PWWB, *GPWB, *PGXWB;
    float *ZC, *ZP, *ATTP, *S2P, *ATT, *S2;
    float *GPBI, *PGXBI, *S1, *B1, *BS2, *BB2;
    cudaGetSymbolAddress((void**)&XB,   g_xb);
    cudaGetSymbolAddress((void**)&X0B,  g_x0b);
    cudaGetSymbolAddress((void**)&THB,  g_THb);
    cudaGetSymbolAddress((void**)&PHGXB,g_PHGXb);
    cudaGetSymbolAddress((void**)&YB,   g_Yb);
    cudaGetSymbolAddress((void**)&ZCB,  g_ZCb);
    cudaGetSymbolAddress((void**)&GPB,  g_GPb);
    cudaGetSymbolAddress((void**)&T2B,  g_T2b);
    cudaGetSymbolAddress((void**)&Y2B,  g_Y2b);
    cudaGetSymbolAddress((void**)&ATTB, g_ATTb);
    cudaGetSymbolAddress((void**)&S2B,  g_S2b);
    cudaGetSymbolAddress((void**)&CTWB, g_ctwb);
    cudaGetSymbolAddress((void**)&CWWB, g_cWwb);
    cudaGetSymbolAddress((void**)&PTWB, g_ptwb);
    cudaGetSymbolAddress((void**)&PWWB, g_pWwb);
    cudaGetSymbolAddress((void**)&GPWB, g_gpwb);
    cudaGetSymbolAddress((void**)&PGXWB,g_pgxwb);
    cudaGetSymbolAddress((void**)&ZC,   g_ZC);
    cudaGetSymbolAddress((void**)&ZP,   g_ZP);
    cudaGetSymbolAddress((void**)&ATTP, g_ATTP);
    cudaGetSymbolAddress((void**)&S2P,  g_S2P);
    cudaGetSymbolAddress((void**)&ATT,  g_ATT);
    cudaGetSymbolAddress((void**)&S2,   g_S2);
    cudaGetSymbolAddress((void**)&GPBI, g_gpb);
    cudaGetSymbolAddress((void**)&PGXBI,g_pgxb);
    cudaGetSymbolAddress((void**)&S1,   g_s1);
    cudaGetSymbolAddress((void**)&B1,   g_b1);
    cudaGetSymbolAddress((void**)&BS2,  g_s2v);
    cudaGetSymbolAddress((void**)&BB2,  g_b2v);

    prep_kernel<<<1, 256>>>(cWb, cbg, cbb, cbm, cbv, pWb, pbg, pbb, pbm, pbv);
    wprep_kernel<<<CL*CH/256, 256>>>(ctw, cWw, ptw, pWw, pgw, ppw, cpw, cgw,
                                     pgb, ppb, cpb, cgb);
    f2b_kernel<<<BB*CH*HW/512, 256>>>(x, XB);
    f2b_kernel<<<BB*CL*HW/512, 256>>>(x0, X0B);

    // ---- CNL 1x1 convs: TH (from x), PH|GX stacked (from x0) ----
    gemm_bf<0,false><<<dim3(HW/128, 1, BB), 256>>>(
        CTWB, XB, nullptr, THB, nullptr, ctb, nullptr, CL, HW, CH, CH, HW, HW,
        0L, (long)CH*HW, (long)CL*HW, 1.f, 1);
    gemm_bf<0,false><<<dim3(HW/128, 2, BB), 256>>>(
        PGXWB, X0B, nullptr, PHGXB, nullptr, PGXBI, nullptr, 2*CL, HW, CL, CL, HW, HW,
        0L, (long)CL*HW, (long)2*CL*HW, 1.f, 1);
    // ---- CNL affinity: ATT = TH @ PH^T / Cl  (split-K, deterministic) ----
    gemm_bf<2,true><<<dim3(1, 1, BB*SPLITK), 256>>>(
        THB, PHGXB, ATTP, nullptr, nullptr, nullptr, nullptr, CL, CL, HW, HW, HW, CL,
        (long)CL*HW, (long)2*CL*HW, (long)CL*CL, 1.f/CL, SPLITK);
    reduce_splitk<<<BB*CL*CL/256, 256>>>(ATTP, ATT, ATTB, CL*CL, SPLITK);
    // ---- Y = ATT @ GX ----
    gemm_bf<0,false><<<dim3(HW/128, 1, BB), 256>>>(
        ATTB, PHGXB + (long)CL*HW, nullptr, YB, nullptr, nullptr, nullptr,
        CL, HW, CL, CL, HW, HW,
        (long)CL*CL, (long)2*CL*HW, (long)CL*HW, 1.f, 1);
    // ---- Z_CNL = BN(W@Y) + x  (fp32 + bf16) ----
    gemm_bf<1,false><<<dim3(HW/128, CH/128, BB), 256>>>(
        CWWB, YB, ZC, ZCB, x, B1, S1, CH, HW, CL, CL, HW, HW,
        0L, (long)CL*HW, (long)CH*HW, 1.f, 1);

    // ---- PNL convs: stacked G2|P2 (M=128 exact), T2 (M=64 zero-padded) ----
    gemm_bf<0,false><<<dim3(HW/128, 1, BB), 256>>>(
        GPWB, X0B, nullptr, GPB, nullptr, GPBI, nullptr, CL, HW, CL, CL, HW, HW,
        0L, (long)CL*HW, (long)2*RR*HW, 1.f, 1);
    gemm_bf<0,false><<<dim3(HW/128, 1, BB), 256>>>(
        PTWB, ZCB, nullptr, T2B, nullptr, ptb, nullptr, RR, HW, CH, CH, HW, HW,
        0L, (long)CH*HW, (long)RR*HW, 1.f, 1);
    // ---- PNL reassociated: S2 = (G2v @ P2v^T)/M  then  Y2v = S2 @ T2v ----
    gemm_bf<2,true><<<dim3(1, 1, BB*SPLITK2), 256>>>(
        GPB, GPB + (long)RR*HW, S2P, nullptr, nullptr, nullptr, nullptr,
        CL, CL, MM, MM, MM, CL,
        (long)2*RR*HW, (long)2*RR*HW, (long)CL*CL, 1.f/MM, SPLITK2);
    reduce_splitk<<<BB*CL*CL/256, 256>>>(S2P, S2, S2B, CL*CL, SPLITK2);
    gemm_bf<0,false><<<dim3(MM/128, 1, BB), 256>>>(
        S2B, T2B, nullptr, Y2B, nullptr, nullptr, nullptr, CL, MM, CL, CL, MM, MM,
        (long)CL*CL, (long)RR*HW, (long)RR*HW, 1.f, 1);
    // ---- Z_PNL = BN(W@Y2) + Z_CNL  (fp32) ----
    gemm_bf<1,false><<<dim3(HW/128, CH/128, BB), 256>>>(
        PWWB, Y2B, ZP, nullptr, ZC, BB2, BS2, CH, HW, RR, RR, HW, HW,
        0L, (long)RR*HW, (long)CH*HW, 1.f, 1);

    // ---- CBAM + fusion ----
    chanpool_kernel<<<dim3(CH, BB), 256>>>();
    camlp_kernel<<<BB, 256>>>(fc1, fc2);
    spool_kernel<<<BB*HW/256, 256>>>();
    sconv_kernel<<<BB*HW/256, 256>>>(saw);
    final_kernel<<<BB*CH*HW/256, 256>>>(x, fwp, out);
}

// round 7
// speedup vs baseline: 4.6312x; 1.0158x over previous
#include <cuda_runtime.h>
#include <cuda_bf16.h>
#include <cstdint>
#include <math.h>

#define BB 8
#define CH 256
#define CL 128
#define RR 64
#define HW 4096
#define MM 2048
#define SPLITK 32     // ATT affinity (K=4096)
#define SPLITK2 16    // S2 (K=2048)
#define SLABR 448     // slab rows per batch: [Y2(64) | Y(128) | x(256)]
#define Y2OFF 0
#define YOFF  64
#define XOFF  192
#define KT2   384     // T2 fused K  ([Y;x])
#define KZP   192     // ZP fused K  ([Y2;Y])

// ---------------- scratch (static device globals; no runtime alloc) ----------------
__device__ __align__(16) __nv_bfloat16 g_slab[BB*SLABR*HW];   // Y2 | Y | x (bf16)
__device__ __align__(16) __nv_bfloat16 g_x0b [BB*CL*HW];
__device__ __align__(16) __nv_bfloat16 g_THb [BB*CL*HW];
__device__ __align__(16) __nv_bfloat16 g_PHGXb[BB*2*CL*HW];   // PH rows 0-127 | GX rows 128-255
__device__ __align__(16) __nv_bfloat16 g_GPb [BB*2*RR*HW];    // G2 rows 0-63 | P2 rows 64-127
__device__ __align__(16) __nv_bfloat16 g_T2b [BB*RR*HW];
__device__ __align__(16) __nv_bfloat16 g_ZPb [BB*CH*HW];
__device__ __align__(16) __nv_bfloat16 g_ATTb[BB*CL*CL];
__device__ __align__(16) __nv_bfloat16 g_S2b [BB*CL*CL];
__device__ __align__(16) __nv_bfloat16 g_ctwb[CL*CH];
__device__ __align__(16) __nv_bfloat16 g_gpwb[CL*CL];         // pgw|ppw stacked
__device__ __align__(16) __nv_bfloat16 g_pgxwb[2*CL*CL];      // cpw|cgw stacked
__device__ __align__(16) __nv_bfloat16 g_wt2b[RR*KT2];        // [ptw*s1*cWw | ptw]
__device__ __align__(16) __nv_bfloat16 g_zpwb[CH*KZP];        // [s2*pWw | s1*cWw]
__device__ float g_ATTP[BB*SPLITK*CL*CL];
__device__ float g_S2P[BB*SPLITK2*CL*CL];
__device__ float g_gpb[CL];
__device__ float g_pgxb[2*CL];
__device__ float g_biast[RR];
__device__ float g_bias2[CH];
__device__ float g_pm[BB*CH];
__device__ float g_px[BB*CH];
__device__ float g_ca[BB*CH];
__device__ float g_sam[BB*HW];
__device__ float g_sax[BB*HW];
__device__ float g_sas[BB*HW];
__device__ float g_s1[CH], g_b1[CH], g_s2v[CH], g_b2v[CH];

// ---------------- fused BN scale/bias precompute ----------------
__global__ void prep_kernel(const float* __restrict__ cWb, const float* __restrict__ cg,
                            const float* __restrict__ cb, const float* __restrict__ cm,
                            const float* __restrict__ cv,
                            const float* __restrict__ pWb, const float* __restrict__ pg,
                            const float* __restrict__ pb, const float* __restrict__ pm,
                            const float* __restrict__ pv) {
    int c = threadIdx.x;
    if (c < CH) {
        float s1 = cg[c] * rsqrtf(cv[c] + 1e-5f);
        g_s1[c] = s1;
        g_b1[c] = cWb[c] * s1 + cb[c] - cm[c] * s1;
        float s2 = pg[c] * rsqrtf(pv[c] + 1e-5f);
        g_s2v[c] = s2;
        g_b2v[c] = pWb[c] * s2 + pb[c] - pm[c] * s2;
        g_bias2[c] = g_b1[c] + g_b2v[c];
    }
}

// ---------------- weight convert + stack (bf16) ----------------
__global__ void wprep_kernel(const float* __restrict__ ctw,
                             const float* __restrict__ pgw, const float* __restrict__ ppw,
                             const float* __restrict__ cpw, const float* __restrict__ cgw,
                             const float* __restrict__ pgb, const float* __restrict__ ppb,
                             const float* __restrict__ cpb, const float* __restrict__ cgb) {
    int i = blockIdx.x * 256 + threadIdx.x;   // < 32768
    g_ctwb[i] = __float2bfloat16(ctw[i]);
    g_pgxwb[i] = __float2bfloat16(i < CL*CL ? cpw[i] : cgw[i - CL*CL]);
    if (i < CL*CL) g_gpwb[i] = __float2bfloat16(i < RR*CL ? pgw[i] : ppw[i - RR*CL]);
    if (i < 2*CL) g_pgxb[i] = (i < CL) ? cpb[i] : cgb[i - CL];
    if (i < CL)   g_gpb[i]  = (i < RR) ? pgb[i] : ppb[i - RR];
}

// ---------------- fused T2 weight: [ptw*diag(s1)*cWw | ptw], bias_t ----------------
__global__ void wt2_kernel(const float* __restrict__ ptw, const float* __restrict__ ptb,
                           const float* __restrict__ cWw) {
    int o = blockIdx.x;      // 0..63
    int m = threadIdx.x;     // 0..127
    float s = 0.f;
    for (int c = 0; c < CH; c++)
        s += ptw[o * CH + c] * g_s1[c] * cWw[c * CL + m];
    g_wt2b[o * KT2 + m] = __float2bfloat16(s);
    g_wt2b[o * KT2 + CL + m]      = __float2bfloat16(ptw[o * CH + m]);
    g_wt2b[o * KT2 + CL + 128 + m] = __float2bfloat16(ptw[o * CH + 128 + m]);
    if (m == 0) {
        float bt = ptb[o];
        for (int c = 0; c < CH; c++) bt += ptw[o * CH + c] * g_b1[c];
        g_biast[o] = bt;
    }
}

// ---------------- fused ZP weight: [s2*pWw | s1*cWw] ----------------
__global__ void zpw_kernel(const float* __restrict__ pWw, const float* __restrict__ cWw) {
    int o = blockIdx.x;      // 0..255
    int k = threadIdx.x;     // 0..191
    float v = (k < RR) ? g_s2v[o] * pWw[o * RR + k]
                       : g_s1[o] * cWw[o * CL + (k - RR)];
    g_zpwb[o * KZP + k] = __float2bfloat16(v);
}

// ---------------- fp32 -> bf16 converts ----------------
__global__ void f2b_kernel(const float* __restrict__ in, __nv_bfloat16* __restrict__ out) {
    int i = blockIdx.x * 256 + threadIdx.x;
    float2 v = *reinterpret_cast<const float2*>(in + 2 * i);
    __nv_bfloat162 h;
    h.x = __float2bfloat16(v.x); h.y = __float2bfloat16(v.y);
    *reinterpret_cast<__nv_bfloat162*>(out + 2 * i) = h;
}

__global__ void f2b_slab_kernel(const float* __restrict__ x) {   // x -> slab rows XOFF..
    int i = blockIdx.x * 256 + threadIdx.x;      // pair index, < BB*CH*HW/2
    long e = 2L * i;
    int b = (int)(e / (CH * HW));
    long inner = e - (long)b * (CH * HW);
    float2 v = *reinterpret_cast<const float2*>(x + e);
    __nv_bfloat162 h;
    h.x = __float2bfloat16(v.x); h.y = __float2bfloat16(v.y);
    *reinterpret_cast<__nv_bfloat162*>(g_slab + (long)b * SLABR * HW + (long)XOFF * HW + inner) = h;
}

// ---------------- BF16 tensor-core GEMM (cp.async 3-stage + ldmatrix) ----------------
#define MMA_BF16(d, a0,a1,a2,a3, b0,b1) \
    asm volatile("mma.sync.aligned.m16n8k16.row.col.f32.bf16.bf16.f32 " \
        "{%0,%1,%2,%3},{%4,%5,%6,%7},{%8,%9},{%0,%1,%2,%3};" \
        : "+f"(d[0]),"+f"(d[1]),"+f"(d[2]),"+f"(d[3]) \
        : "r"(a0),"r"(a1),"r"(a2),"r"(a3),"r"(b0),"r"(b1))

#define LDSM4(r0,r1,r2,r3, ad) \
    asm volatile("ldmatrix.sync.aligned.m8n8.x4.shared.b16 {%0,%1,%2,%3},[%4];" \
        : "=r"(r0),"=r"(r1),"=r"(r2),"=r"(r3) : "r"(ad))
#define LDSM4T(r0,r1,r2,r3, ad) \
    asm volatile("ldmatrix.sync.aligned.m8n8.x4.trans.shared.b16 {%0,%1,%2,%3},[%4];" \
        : "=r"(r0),"=r"(r1),"=r"(r2),"=r"(r3) : "r"(ad))

#define CP16(s, g)  asm volatile("cp.async.cg.shared.global [%0],[%1],16;\n" :: "r"(s), "l"(g))
#define CP16Z(s, g) asm volatile("cp.async.cg.shared.global [%0],[%1],16,0;\n" :: "r"(s), "l"(g))
#define CPCOMMIT()  asm volatile("cp.async.commit_group;\n")
#define CPWAIT1()   asm volatile("cp.async.wait_group 1;\n")

// C[M,N] = f( alpha * A[M,K] @ op(B)[K,N] ), bf16 operands, fp32 accum.
// MODE 0: out = alpha*AB + (bias ? bias[m] : 0)
// MODE 1: out = AB*scale[m] + bias[m] + R[m,n]
// MODE 2: split-K partial (fp32 C only; deterministic reduce later)
// MODE 3: out = AB + bias[m] + R[m,n]
// C (fp32) and/or CB (bf16) stores, either may be null.
template<int MODE, bool TB>
__global__ __launch_bounds__(256, 2) void gemm_bf(
    const __nv_bfloat16* __restrict__ A, const __nv_bfloat16* __restrict__ Bm,
    float* __restrict__ C, __nv_bfloat16* __restrict__ CB,
    const float* __restrict__ R,
    const float* __restrict__ bias, const float* __restrict__ scale,
    int M, int N, int K, int lda, int ldb, int ldc,
    long sA, long sB, long sC, float alpha, int splitK)
{
    int z = blockIdx.z;
    int batch = z / splitK;
    int kslice = z - batch * splitK;
    int Kchunk = K / splitK;
    int k0base = kslice * Kchunk;

    A  += (long)batch * sA;
    Bm += (long)batch * sB;
    if (MODE == 2) C += (long)z * sC;
    else {
        if (C)  C  += (long)batch * sC;
        if (CB) CB += (long)batch * sC;
        if (MODE == 1 || MODE == 3) R += (long)batch * sC;
    }

    const int m0 = blockIdx.y * 128;
    const int n0 = blockIdx.x * 128;
    const int tid = threadIdx.x;
    const int warp = tid >> 5, lane = tid & 31;
    const int wm = warp >> 2, wn = warp & 3;       // 2 x 4 warp grid
    const int g = lane >> 2, c = lane & 3;
    const int mi = lane >> 3, lr = lane & 7;
    const int m0w = wm * 64, n0w = wn * 32;

    __shared__ uint32_t SA[3][2048];
    __shared__ uint32_t SB[3][2048];

    float acc[4][4][4];
    #pragma unroll
    for (int i = 0; i < 4; i++)
        #pragma unroll
        for (int j = 0; j < 4; j++)
            #pragma unroll
            for (int e = 0; e < 4; e++) acc[i][j][e] = 0.f;

    const int nk = Kchunk / 32;

    auto issue = [&](int t) {
        int buf = t % 3;
        int k0 = k0base + t * 32;
        uint32_t sbA = (uint32_t)__cvta_generic_to_shared(&SA[buf][0]);
        uint32_t sbB = (uint32_t)__cvta_generic_to_shared(&SB[buf][0]);
        #pragma unroll
        for (int it = 0; it < 2; it++) {
            int f = tid + it * 256;
            {   // A: [M,K] rows of 32 bf16 (64B)
                int row = f >> 2, cn = f & 3;
                const __nv_bfloat16* gp = A + (long)(m0 + row) * lda + k0 + cn * 8;
                uint32_t sa = sbA + (uint32_t)(row * 4 + (cn ^ ((row >> 1) & 3))) * 16u;
                if (m0 + row < M) { CP16(sa, gp); } else { CP16Z(sa, A); }
            }
            if (!TB) {   // B: [K,N] rows of 128 bf16 (256B)
                int k = f >> 4, cn = f & 15;
                const __nv_bfloat16* gp = Bm + (long)(k0 + k) * ldb + n0 + cn * 8;
                CP16(sbB + (uint32_t)(k * 16 + (cn ^ (k & 7))) * 16u, gp);
            } else {     // B: [N,K] rows of 32 bf16
                int row = f >> 2, cn = f & 3;
                const __nv_bfloat16* gp = Bm + (long)(n0 + row) * ldb + k0 + cn * 8;
                CP16(sbB + (uint32_t)(row * 4 + (cn ^ ((row >> 1) & 3))) * 16u, gp);
            }
        }
    };

    if (0 < nk) issue(0);
    CPCOMMIT();
    if (1 < nk) issue(1);
    CPCOMMIT();

    for (int t = 0; t < nk; t++) {
        CPWAIT1();
        __syncthreads();
        if (t + 2 < nk) issue(t + 2);
        CPCOMMIT();

        int buf = t % 3;
        uint32_t baseA = (uint32_t)__cvta_generic_to_shared(&SA[buf][0]);
        uint32_t baseB = (uint32_t)__cvta_generic_to_shared(&SB[buf][0]);

        #pragma unroll
        for (int s = 0; s < 2; s++) {
            uint32_t bfr[4][2];
            if (!TB) {
                int krow = 16 * s + (mi & 1) * 8 + lr;
                #pragma unroll
                for (int p = 0; p < 2; p++) {
                    int chunk = wn * 4 + 2 * p + (mi >> 1);
                    uint32_t ad = baseB + (uint32_t)(krow * 16 + (chunk ^ (krow & 7))) * 16u;
                    LDSM4T(bfr[2*p][0], bfr[2*p][1], bfr[2*p+1][0], bfr[2*p+1][1], ad);
                }
            } else {
                #pragma unroll
                for (int p = 0; p < 2; p++) {
                    int nrow = n0w + 16 * p + 8 * (mi >> 1) + lr;
                    int chunk = 2 * s + (mi & 1);
                    uint32_t ad = baseB + (uint32_t)(nrow * 4 + (chunk ^ ((nrow >> 1) & 3))) * 16u;
                    LDSM4(bfr[2*p][0], bfr[2*p][1], bfr[2*p+1][0], bfr[2*p+1][1], ad);
                }
            }
            #pragma unroll
            for (int i = 0; i < 4; i++) {
                int row = m0w + 16 * i + (mi & 1) * 8 + lr;
                int chunk = 2 * s + (mi >> 1);
                uint32_t ad = baseA + (uint32_t)(row * 4 + (chunk ^ ((row >> 1) & 3))) * 16u;
                uint32_t a0, a1, a2, a3;
                LDSM4(a0, a1, a2, a3, ad);
                #pragma unroll
                for (int j = 0; j < 4; j++)
                    MMA_BF16(acc[i][j], a0, a1, a2, a3, bfr[j][0], bfr[j][1]);
            }
        }
    }

    // ---- epilogue ----
    #pragma unroll
    for (int i = 0; i < 4; i++) {
        int gm0 = m0 + m0w + i * 16 + g;
        #pragma unroll
        for (int half = 0; half < 2; half++) {
            int gm = gm0 + half * 8;
            if (gm >= M) continue;
            float bv = 0.f, sv = 1.f;
            if (MODE == 0) bv = bias ? bias[gm] : 0.f;
            if (MODE == 1) { bv = bias[gm]; sv = scale[gm]; }
            if (MODE == 3) bv = bias[gm];
            #pragma unroll
            for (int j = 0; j < 4; j++) {
                int gn = n0 + n0w + j * 8 + 2 * c;
                long idx = (long)gm * ldc + gn;
                float v0 = acc[i][j][half * 2 + 0];
                float v1 = acc[i][j][half * 2 + 1];
                float2 o;
                if (MODE == 0)      { o.x = alpha * v0 + bv;       o.y = alpha * v1 + bv; }
                else if (MODE == 1) { o.x = v0 * sv + bv + R[idx]; o.y = v1 * sv + bv + R[idx + 1]; }
                else if (MODE == 3) { o.x = v0 + bv + R[idx];      o.y = v1 + bv + R[idx + 1]; }
                else                { o.x = alpha * v0;            o.y = alpha * v1; }
                if (MODE == 2 || (MODE != 2 && C)) *reinterpret_cast<float2*>(&C[idx]) = o;
                if (MODE != 2 && CB) {
                    __nv_bfloat162 h;
                    h.x = __float2bfloat16(o.x); h.y = __float2bfloat16(o.y);
                    *reinterpret_cast<__nv_bfloat162*>(&CB[idx]) = h;
                }
            }
        }
    }
}

// ---------------- deterministic split-K reduce (bf16 out) ----------------
__global__ void reduce_splitk(const float* __restrict__ src, __nv_bfloat16* __restrict__ dstb,
                              int per, int nslice) {
    int i = blockIdx.x * 256 + threadIdx.x;
    int b = i / per;
    int r = i - b * per;
    float s = 0.f;
    for (int k = 0; k < nslice; k++)
        s += src[((long)b * nslice + k) * per + r];
    dstb[i] = __float2bfloat16(s);
}

// ---------------- CBAM: channel pooling (mean+max over HW, bf16 in) ----------------
__global__ void chanpool_kernel() {
    int c = blockIdx.x, b = blockIdx.y;
    int t = threadIdx.x;
    const __nv_bfloat162* p = reinterpret_cast<const __nv_bfloat162*>(
        g_ZPb + ((long)b * CH + c) * HW);
    float s = 0.f, mx = -1e30f;
    for (int i = t; i < HW / 2; i += 256) {
        __nv_bfloat162 h = p[i];
        float v0 = __bfloat162float(h.x), v1 = __bfloat162float(h.y);
        s += v0 + v1;
        mx = fmaxf(mx, fmaxf(v0, v1));
    }
    __shared__ float ss[256];
    __shared__ float sm[256];
    ss[t] = s; sm[t] = mx;
    __syncthreads();
    for (int o = 128; o > 0; o >>= 1) {
        if (t < o) { ss[t] += ss[t + o]; sm[t] = fmaxf(sm[t], sm[t + o]); }
        __syncthreads();
    }
    if (t == 0) {
        g_pm[b * CH + c] = ss[0] * (1.f / HW);
        g_px[b * CH + c] = sm[0];
    }
}

// ---------------- CBAM: channel-attention MLP ----------------
__global__ void camlp_kernel(const float* __restrict__ fc1, const float* __restrict__ fc2) {
    int b = blockIdx.x;
    int t = threadIdx.x;
    __shared__ float hm[16], hx[16];
    if (t < 16) {
        float s = 0.f;
        for (int c = 0; c < CH; c++) s += fc1[t * CH + c] * g_pm[b * CH + c];
        hm[t] = fmaxf(s, 0.f);
    } else if (t < 32) {
        int h = t - 16;
        float s = 0.f;
        for (int c = 0; c < CH; c++) s += fc1[h * CH + c] * g_px[b * CH + c];
        hx[h] = fmaxf(s, 0.f);
    }
    __syncthreads();
    float sm = 0.f, sx = 0.f;
    #pragma unroll
    for (int h = 0; h < 16; h++) {
        float w = fc2[t * 16 + h];
        sm += w * hm[h];
        sx += w * hx[h];
    }
    g_ca[b * CH + t] = 1.f / (1.f + expf(-(sm + sx)));
}

// ---------------- CBAM: spatial pooling over channels of z_pnl*ca ----------------
__global__ void spool_kernel() {
    __shared__ float cas[CH];
    int idx = blockIdx.x * 256 + threadIdx.x;
    int b = idx / HW;
    int p = idx - b * HW;
    for (int c = threadIdx.x; c < CH; c += 256) cas[c] = g_ca[b * CH + c];
    __syncthreads();
    float s = 0.f, mx = -1e30f;
    for (int c = 0; c < CH; c++) {
        float v = __bfloat162float(g_ZPb[((long)b * CH + c) * HW + p]) * cas[c];
        s += v;
        mx = fmaxf(mx, v);
    }
    g_sam[idx] = s * (1.f / CH);
    g_sax[idx] = mx;
}

// ---------------- CBAM: 7x7 spatial conv + sigmoid ----------------
__global__ void sconv_kernel(const float* __restrict__ w) {
    int idx = blockIdx.x * 256 + threadIdx.x;
    int b = idx / HW;
    int p = idx - b * HW;
    int h = p >> 6, wq = p & 63;
    float s = 0.f;
    #pragma unroll
    for (int kh = 0; kh < 7; kh++) {
        int ih = h + kh - 3;
        if (ih < 0 || ih >= 64) continue;
        #pragma unroll
        for (int kw = 0; kw < 7; kw++) {
            int iw = wq + kw - 3;
            if (iw < 0 || iw >= 64) continue;
            int q = (ih << 6) | iw;
            s += w[kh * 7 + kw] * g_sam[b * HW + q] + w[49 + kh * 7 + kw] * g_sax[b * HW + q];
        }
    }
    g_sas[idx] = 1.f / (1.f + expf(-s));
}

// ---------------- final weighted fusion ----------------
__global__ void final_kernel(const float* __restrict__ x, const float* __restrict__ fwp,
                             float* __restrict__ out) {
    long e = 2L * (blockIdx.x * 256 + threadIdx.x);
    long p = e % HW;
    long bc = e / HW;
    long b = bc / CH;
    float fw = *fwp;
    __nv_bfloat162 zp2 = *reinterpret_cast<const __nv_bfloat162*>(g_ZPb + e);
    float2 x2 = *reinterpret_cast<const float2*>(x + e);
    float ca = g_ca[bc];
    float2 o;
    o.x = fw * __bfloat162float(zp2.x) * ca * g_sas[b * HW + p]     + (1.f - fw) * x2.x;
    o.y = fw * __bfloat162float(zp2.y) * ca * g_sas[b * HW + p + 1] + (1.f - fw) * x2.y;
    *reinterpret_cast<float2*>(out + e) = o;
}

// ---------------- launch ----------------
extern "C" void kernel_launch(void* const* d_in, const int* in_sizes, int n_in,
                              void* d_out, int out_size) {
    const float* x   = (const float*)d_in[0];
    const float* x0  = (const float*)d_in[1];
    const float* cgw = (const float*)d_in[2];
    const float* cgb = (const float*)d_in[3];
    const float* ctw = (const float*)d_in[4];
    const float* ctb = (const float*)d_in[5];
    const float* cpw = (const float*)d_in[6];
    const float* cpb = (const float*)d_in[7];
    const float* cWw = (const float*)d_in[8];
    const float* cWb = (const float*)d_in[9];
    const float* cbg = (const float*)d_in[10];
    const float* cbb = (const float*)d_in[11];
    const float* cbm = (const float*)d_in[12];
    const float* cbv = (const float*)d_in[13];
    const float* pgw = (const float*)d_in[14];
    const float* pgb = (const float*)d_in[15];
    const float* ptw = (const float*)d_in[16];
    const float* ptb = (const float*)d_in[17];
    const float* ppw = (const float*)d_in[18];
    const float* ppb = (const float*)d_in[19];
    const float* pWw = (const float*)d_in[20];
    const float* pWb = (const float*)d_in[21];
    const float* pbg = (const float*)d_in[22];
    const float* pbb = (const float*)d_in[23];
    const float* pbm = (const float*)d_in[24];
    const float* pbv = (const float*)d_in[25];
    const float* fc1 = (const float*)d_in[26];
    const float* fc2 = (const float*)d_in[27];
    const float* saw = (const float*)d_in[28];
    const float* fwp = (const float*)d_in[29];
    float* out = (float*)d_out;

    __nv_bfloat16 *SLAB, *X0B, *THB, *PHGXB, *GPB, *T2B, *ZPB, *ATTB, *S2B;
    __nv_bfloat16 *CTWB, *GPWB, *PGXWB, *WT2B, *ZPWB;
    float *ATTP, *S2P, *GPBI, *PGXBI, *BIAST, *BIAS2;
    cudaGetSymbolAddress((void**)&SLAB, g_slab);
    cudaGetSymbolAddress((void**)&X0B,  g_x0b);
    cudaGetSymbolAddress((void**)&THB,  g_THb);
    cudaGetSymbolAddress((void**)&PHGXB,g_PHGXb);
    cudaGetSymbolAddress((void**)&GPB,  g_GPb);
    cudaGetSymbolAddress((void**)&T2B,  g_T2b);
    cudaGetSymbolAddress((void**)&ZPB,  g_ZPb);
    cudaGetSymbolAddress((void**)&ATTB, g_ATTb);
    cudaGetSymbolAddress((void**)&S2B,  g_S2b);
    cudaGetSymbolAddress((void**)&CTWB, g_ctwb);
    cudaGetSymbolAddress((void**)&GPWB, g_gpwb);
    cudaGetSymbolAddress((void**)&PGXWB,g_pgxwb);
    cudaGetSymbolAddress((void**)&WT2B, g_wt2b);
    cudaGetSymbolAddress((void**)&ZPWB, g_zpwb);
    cudaGetSymbolAddress((void**)&ATTP, g_ATTP);
    cudaGetSymbolAddress((void**)&S2P,  g_S2P);
    cudaGetSymbolAddress((void**)&GPBI, g_gpb);
    cudaGetSymbolAddress((void**)&PGXBI,g_pgxb);
    cudaGetSymbolAddress((void**)&BIAST,g_biast);
    cudaGetSymbolAddress((void**)&BIAS2,g_bias2);

    prep_kernel<<<1, 256>>>(cWb, cbg, cbb, cbm, cbv, pWb, pbg, pbb, pbm, pbv);
    wprep_kernel<<<CL*CH/256, 256>>>(ctw, pgw, ppw, cpw, cgw, pgb, ppb, cpb, cgb);
    wt2_kernel<<<RR, CL>>>(ptw, ptb, cWw);
    zpw_kernel<<<CH, KZP>>>(pWw, cWw);
    f2b_slab_kernel<<<BB*CH*HW/512, 256>>>(x);
    f2b_kernel<<<BB*CL*HW/512, 256>>>(x0, X0B);

    const long sSLAB = (long)SLABR * HW;

    // ---- CNL 1x1 convs: TH (from x in slab), PH|GX stacked (from x0) ----
    gemm_bf<0,false><<<dim3(HW/128, 1, BB), 256>>>(
        CTWB, SLAB + (long)XOFF*HW, nullptr, THB, nullptr, ctb, nullptr,
        CL, HW, CH, CH, HW, HW, 0L, sSLAB, (long)CL*HW, 1.f, 1);
    gemm_bf<0,false><<<dim3(HW/128, 2, BB), 256>>>(
        PGXWB, X0B, nullptr, PHGXB, nullptr, PGXBI, nullptr, 2*CL, HW, CL, CL, HW, HW,
        0L, (long)CL*HW, (long)2*CL*HW, 1.f, 1);
    // ---- CNL affinity: ATT = TH @ PH^T / Cl  (split-K, deterministic) ----
    gemm_bf<2,true><<<dim3(1, 1, BB*SPLITK), 256>>>(
        THB, PHGXB, ATTP, nullptr, nullptr, nullptr, nullptr, CL, CL, HW, HW, HW, CL,
        (long)CL*HW, (long)2*CL*HW, (long)CL*CL, 1.f/CL, SPLITK);
    reduce_splitk<<<BB*CL*CL/256, 256>>>(ATTP, ATTB, CL*CL, SPLITK);
    // ---- Y = ATT @ GX  -> slab rows YOFF.. ----
    gemm_bf<0,false><<<dim3(HW/128, 1, BB), 256>>>(
        ATTB, PHGXB + (long)CL*HW, nullptr, SLAB + (long)YOFF*HW, nullptr, nullptr, nullptr,
        CL, HW, CL, CL, HW, HW,
        (long)CL*CL, (long)2*CL*HW, sSLAB, 1.f, 1);

    // ---- PNL convs: stacked G2|P2 (from x0); T2 fused over [Y; x] (K=384) ----
    gemm_bf<0,false><<<dim3(HW/128, 1, BB), 256>>>(
        GPWB, X0B, nullptr, GPB, nullptr, GPBI, nullptr, CL, HW, CL, CL, HW, HW,
        0L, (long)CL*HW, (long)2*RR*HW, 1.f, 1);
    gemm_bf<0,false><<<dim3(HW/128, 1, BB), 256>>>(
        WT2B, SLAB + (long)YOFF*HW, nullptr, T2B, nullptr, BIAST, nullptr,
        RR, HW, KT2, KT2, HW, HW, 0L, sSLAB, (long)RR*HW, 1.f, 1);
    // ---- PNL reassociated: S2 = (G2v @ P2v^T)/M then Y2v = S2 @ T2v -> slab rows 0-63 ----
    gemm_bf<2,true><<<dim3(1, 1, BB*SPLITK2), 256>>>(
        GPB, GPB + (long)RR*HW, S2P, nullptr, nullptr, nullptr, nullptr,
        CL, CL, MM, MM, MM, CL,
        (long)2*RR*HW, (long)2*RR*HW, (long)CL*CL, 1.f/MM, SPLITK2);
    reduce_splitk<<<BB*CL*CL/256, 256>>>(S2P, S2B, CL*CL, SPLITK2);
    gemm_bf<0,false><<<dim3(MM/128, 1, BB), 256>>>(
        S2B, T2B, nullptr, SLAB + (long)Y2OFF*HW, nullptr, nullptr, nullptr,
        CL, MM, CL, CL, MM, MM,
        (long)CL*CL, (long)RR*HW, sSLAB, 1.f, 1);
    // ---- Z_PNL fused: ZP = [s2*pWw | s1*cWw] @ [Y2;Y] + (b1+b2) + x  (bf16 out) ----
    gemm_bf<3,false><<<dim3(HW/128, CH/128, BB), 256>>>(
        ZPWB, SLAB, nullptr, ZPB, x, BIAS2, nullptr, CH, HW, KZP, KZP, HW, HW,
        0L, sSLAB, (long)CH*HW, 1.f, 1);

    // ---- CBAM + fusion ----
    chanpool_kernel<<<dim3(CH, BB), 256>>>();
    camlp_kernel<<<BB, 256>>>(fc1, fc2);
    spool_kernel<<<BB*HW/256, 256>>>();
    sconv_kernel<<<BB*HW/256, 256>>>(saw);
    final_kernel<<<BB*CH*HW/512, 256>>>(x, fwp, out);
}

// round 8
// speedup vs baseline: 4.9110x; 1.0604x over previous
#include <cuda_runtime.h>
#include <cuda_bf16.h>
#include <cstdint>
#include <math.h>

#define BB 8
#define CH 256
#define CL 128
#define RR 64
#define HW 4096
#define MM 2048
#define SPLITK 32     // ATT affinity (K=4096)
#define SPLITK2 16    // S2 (K=2048)
#define SLABR 448     // slab rows per batch: [Y2(64) | Y(128) | x(256)]
#define Y2OFF 0
#define YOFF  64
#define XOFF  192
#define KT2   384     // T2 fused K  ([Y;x])
#define KZP   192     // ZP fused K  ([Y2;Y])
#define PGR   384     // stacked conv rows: PH(128)|GX(128)|G2(64)|P2(64)

// ---------------- scratch (static device globals; no runtime alloc) ----------------
__device__ __align__(16) __nv_bfloat16 g_slab[BB*SLABR*HW];   // Y2 | Y | x
__device__ __align__(16) __nv_bfloat16 g_x0b [BB*CL*HW];
__device__ __align__(16) __nv_bfloat16 g_THb [BB*CL*HW];
__device__ __align__(16) __nv_bfloat16 g_pgx [BB*PGR*HW];     // PH|GX|G2|P2
__device__ __align__(16) __nv_bfloat16 g_T2b [BB*RR*HW];
__device__ __align__(16) __nv_bfloat16 g_ZPb [BB*CH*HW];
__device__ __align__(16) __nv_bfloat16 g_ATTb[BB*CL*CL];
__device__ __align__(16) __nv_bfloat16 g_S2b [BB*CL*CL];
__device__ __align__(16) __nv_bfloat16 g_ctwb[CL*CH];
__device__ __align__(16) __nv_bfloat16 g_pgxw[PGR*CL];        // cpw|cgw|pgw|ppw
__device__ __align__(16) __nv_bfloat16 g_wt2b[RR*KT2];        // [ptw*s1*cWw | ptw]
__device__ __align__(16) __nv_bfloat16 g_zpwb[CH*KZP];        // [s2*pWw | s1*cWw]
__device__ float g_ATTP[BB*SPLITK*CL*CL];
__device__ float g_S2P[BB*SPLITK2*CL*CL];
__device__ float g_pgxbias[PGR];
__device__ float g_biast[RR];
__device__ float g_bias2[CH];
__device__ float g_pm[BB*CH];
__device__ float g_px[BB*CH];
__device__ float g_ca[BB*CH];
__device__ float g_sam[BB*HW];
__device__ float g_sax[BB*HW];
__device__ float g_sas[BB*HW];

// ---------------- merged setup: all weight stacking / BN folding in one launch ----------------
#define SEG0 32768          // ctwb
#define SEG1 (SEG0+49152)   // pgxw
#define SEG2 (SEG1+384)     // pgxbias
#define SEG3 (SEG2+49152)   // zpwb
#define SEG4 (SEG3+16384)   // wt2b copy half
#define SEG5 (SEG4+8192)    // wt2b inner-product half
#define SEG6 (SEG5+64)      // biast
#define SEG7 (SEG6+256)     // bias2
__global__ void setup_kernel(
    const float* __restrict__ ctw, const float* __restrict__ cpw,
    const float* __restrict__ cgw, const float* __restrict__ pgw,
    const float* __restrict__ ppw, const float* __restrict__ cpb,
    const float* __restrict__ cgb, const float* __restrict__ pgb,
    const float* __restrict__ ppb, const float* __restrict__ pWw,
    const float* __restrict__ cWw, const float* __restrict__ ptw,
    const float* __restrict__ ptb, const float* __restrict__ cbg,
    const float* __restrict__ cbb, const float* __restrict__ cbm,
    const float* __restrict__ cbv, const float* __restrict__ cWb,
    const float* __restrict__ pbg, const float* __restrict__ pbb,
    const float* __restrict__ pbm, const float* __restrict__ pbv,
    const float* __restrict__ pWb)
{
    int i = blockIdx.x * 256 + threadIdx.x;
    auto s1f = [&](int c) { return cbg[c] * rsqrtf(cbv[c] + 1e-5f); };
    auto b1f = [&](int c) { float s = s1f(c); return cWb[c] * s + cbb[c] - cbm[c] * s; };
    auto s2f = [&](int c) { return pbg[c] * rsqrtf(pbv[c] + 1e-5f); };
    auto b2f = [&](int c) { float s = s2f(c); return pWb[c] * s + pbb[c] - pbm[c] * s; };
    if (i < SEG0) {
        g_ctwb[i] = __float2bfloat16(ctw[i]);
    } else if (i < SEG1) {
        int j = i - SEG0, r = j >> 7, k = j & 127;
        float v = (r < 128) ? cpw[r * 128 + k]
                : (r < 256) ? cgw[(r - 128) * 128 + k]
                : (r < 320) ? pgw[(r - 256) * 128 + k]
                            : ppw[(r - 320) * 128 + k];
        g_pgxw[j] = __float2bfloat16(v);
    } else if (i < SEG2) {
        int r = i - SEG1;
        g_pgxbias[r] = (r < 128) ? cpb[r] : (r < 256) ? cgb[r - 128]
                     : (r < 320) ? pgb[r - 256] : ppb[r - 320];
    } else if (i < SEG3) {
        int j = i - SEG2, o = j / KZP, k = j - o * KZP;
        float v = (k < RR) ? s2f(o) * pWw[o * RR + k]
                           : s1f(o) * cWw[o * CL + (k - RR)];
        g_zpwb[j] = __float2bfloat16(v);
    } else if (i < SEG4) {
        int j = i - SEG3, o = j >> 8, kk = j & 255;
        g_wt2b[o * KT2 + CL + kk] = __float2bfloat16(ptw[o * CH + kk]);
    } else if (i < SEG5) {
        int j = i - SEG4, o = j >> 7, m = j & 127;
        float s = 0.f;
        for (int c = 0; c < CH; c++)
            s += ptw[o * CH + c] * s1f(c) * cWw[c * CL + m];
        g_wt2b[o * KT2 + m] = __float2bfloat16(s);
    } else if (i < SEG6) {
        int o = i - SEG5;
        float bt = ptb[o];
        for (int c = 0; c < CH; c++) bt += ptw[o * CH + c] * b1f(c);
        g_biast[o] = bt;
    } else if (i < SEG7) {
        int c = i - SEG6;
        g_bias2[c] = b1f(c) + b2f(c);
    }
}

// ---------------- merged fp32 -> bf16 converts (x -> slab, x0 -> x0b) ----------------
#define CVA (BB*CH*HW/2)
#define CVT (CVA + BB*CL*HW/2)
__global__ void convert_kernel(const float* __restrict__ x, const float* __restrict__ x0) {
    int i = blockIdx.x * 256 + threadIdx.x;
    if (i < CVA) {
        long e = 2L * i;
        int b = (int)(e / (CH * HW));
        long inner = e - (long)b * (CH * HW);
        float2 v = *reinterpret_cast<const float2*>(x + e);
        __nv_bfloat162 h;
        h.x = __float2bfloat16(v.x); h.y = __float2bfloat16(v.y);
        *reinterpret_cast<__nv_bfloat162*>(g_slab + (long)b * SLABR * HW + (long)XOFF * HW + inner) = h;
    } else if (i < CVT) {
        long e = 2L * (i - CVA);
        float2 v = *reinterpret_cast<const float2*>(x0 + e);
        __nv_bfloat162 h;
        h.x = __float2bfloat16(v.x); h.y = __float2bfloat16(v.y);
        *reinterpret_cast<__nv_bfloat162*>(g_x0b + e) = h;
    }
}

// ---------------- runtime-task BF16 tensor-core GEMM ----------------
#define MMA_BF16(d, a0,a1,a2,a3, b0,b1) \
    asm volatile("mma.sync.aligned.m16n8k16.row.col.f32.bf16.bf16.f32 " \
        "{%0,%1,%2,%3},{%4,%5,%6,%7},{%8,%9},{%0,%1,%2,%3};" \
        : "+f"(d[0]),"+f"(d[1]),"+f"(d[2]),"+f"(d[3]) \
        : "r"(a0),"r"(a1),"r"(a2),"r"(a3),"r"(b0),"r"(b1))

#define LDSM4(r0,r1,r2,r3, ad) \
    asm volatile("ldmatrix.sync.aligned.m8n8.x4.shared.b16 {%0,%1,%2,%3},[%4];" \
        : "=r"(r0),"=r"(r1),"=r"(r2),"=r"(r3) : "r"(ad))
#define LDSM4T(r0,r1,r2,r3, ad) \
    asm volatile("ldmatrix.sync.aligned.m8n8.x4.trans.shared.b16 {%0,%1,%2,%3},[%4];" \
        : "=r"(r0),"=r"(r1),"=r"(r2),"=r"(r3) : "r"(ad))

#define CP16(s, g)  asm volatile("cp.async.cg.shared.global [%0],[%1],16;\n" :: "r"(s), "l"(g))
#define CP16Z(s, g) asm volatile("cp.async.cg.shared.global [%0],[%1],16,0;\n" :: "r"(s), "l"(g))
#define CPCOMMIT()  asm volatile("cp.async.commit_group;\n")
#define CPWAIT1()   asm volatile("cp.async.wait_group 1;\n")

struct GTask {
    const __nv_bfloat16 *A, *B;
    float* C;                 // fp32 out (mode 2 partials)
    __nv_bfloat16* CB;        // bf16 out (modes 0,3)
    const float *R, *bias;
    int M, K, lda, ldb, ldc;
    long sA, sB, sC;
    float alpha;
    int splitK;               // >=1 (mode 2 k-slicing via z)
    int mode;                 // 0: alpha*AB+bias -> CB; 2: alpha*AB -> C[z]; 3: AB+bias+R -> CB
};

// Two tasks per launch, selected by blockIdx.y >= ySplit or blockIdx.z >= zSplit.
template<bool TB>
__global__ __launch_bounds__(256, 2) void gemm_rt(GTask t0, GTask t1, int ySplit, int zSplit)
{
    const bool second = ((int)blockIdx.y >= ySplit) || ((int)blockIdx.z >= zSplit);
    const GTask& t = second ? t1 : t0;
    int by = blockIdx.y - (((int)blockIdx.y >= ySplit) ? ySplit : 0);
    int bz = blockIdx.z - (((int)blockIdx.z >= zSplit) ? zSplit : 0);

    const int batch = bz / t.splitK;
    const int kslice = bz - batch * t.splitK;
    const int Kchunk = t.K / t.splitK;
    const int k0base = kslice * Kchunk;

    const __nv_bfloat16* A = t.A + (long)batch * t.sA;
    const __nv_bfloat16* Bm = t.B + (long)batch * t.sB;
    float* C = t.C;
    __nv_bfloat16* CB = t.CB;
    const float* R = t.R;
    if (t.mode == 2) C += (long)bz * t.sC;
    else {
        if (CB) CB += (long)batch * t.sC;
        if (R)  R  += (long)batch * t.sC;
    }
    const int lda = t.lda, ldb = t.ldb, ldc = t.ldc, M = t.M;

    const int m0 = by * 128;
    const int n0 = blockIdx.x * 128;
    const int tid = threadIdx.x;
    const int warp = tid >> 5, lane = tid & 31;
    const int wm = warp >> 2, wn = warp & 3;
    const int g = lane >> 2, c = lane & 3;
    const int mi = lane >> 3, lr = lane & 7;
    const int m0w = wm * 64, n0w = wn * 32;

    __shared__ uint32_t SA[3][2048];
    __shared__ uint32_t SB[3][2048];

    float acc[4][4][4];
    #pragma unroll
    for (int i = 0; i < 4; i++)
        #pragma unroll
        for (int j = 0; j < 4; j++)
            #pragma unroll
            for (int e = 0; e < 4; e++) acc[i][j][e] = 0.f;

    const int nk = Kchunk / 32;

    auto issue = [&](int tt) {
        int buf = tt % 3;
        int k0 = k0base + tt * 32;
        uint32_t sbA = (uint32_t)__cvta_generic_to_shared(&SA[buf][0]);
        uint32_t sbB = (uint32_t)__cvta_generic_to_shared(&SB[buf][0]);
        #pragma unroll
        for (int it = 0; it < 2; it++) {
            int f = tid + it * 256;
            {   // A: [M,K] rows of 32 bf16
                int row = f >> 2, cn = f & 3;
                const __nv_bfloat16* gp = A + (long)(m0 + row) * lda + k0 + cn * 8;
                uint32_t sa = sbA + (uint32_t)(row * 4 + (cn ^ ((row >> 1) & 3))) * 16u;
                if (m0 + row < M) { CP16(sa, gp); } else { CP16Z(sa, A); }
            }
            if (!TB) {   // B: [K,N] rows of 128 bf16
                int k = f >> 4, cn = f & 15;
                const __nv_bfloat16* gp = Bm + (long)(k0 + k) * ldb + n0 + cn * 8;
                CP16(sbB + (uint32_t)(k * 16 + (cn ^ (k & 7))) * 16u, gp);
            } else {     // B: [N,K] rows of 32 bf16
                int row = f >> 2, cn = f & 3;
                const __nv_bfloat16* gp = Bm + (long)(n0 + row) * ldb + k0 + cn * 8;
                CP16(sbB + (uint32_t)(row * 4 + (cn ^ ((row >> 1) & 3))) * 16u, gp);
            }
        }
    };

    if (0 < nk) issue(0);
    CPCOMMIT();
    if (1 < nk) issue(1);
    CPCOMMIT();

    for (int tt = 0; tt < nk; tt++) {
        CPWAIT1();
        __syncthreads();
        if (tt + 2 < nk) issue(tt + 2);
        CPCOMMIT();

        int buf = tt % 3;
        uint32_t baseA = (uint32_t)__cvta_generic_to_shared(&SA[buf][0]);
        uint32_t baseB = (uint32_t)__cvta_generic_to_shared(&SB[buf][0]);

        #pragma unroll
        for (int s = 0; s < 2; s++) {
            uint32_t bfr[4][2];
            if (!TB) {
                int krow = 16 * s + (mi & 1) * 8 + lr;
                #pragma unroll
                for (int p = 0; p < 2; p++) {
                    int chunk = wn * 4 + 2 * p + (mi >> 1);
                    uint32_t ad = baseB + (uint32_t)(krow * 16 + (chunk ^ (krow & 7))) * 16u;
                    LDSM4T(bfr[2*p][0], bfr[2*p][1], bfr[2*p+1][0], bfr[2*p+1][1], ad);
                }
            } else {
                #pragma unroll
                for (int p = 0; p < 2; p++) {
                    int nrow = n0w + 16 * p + 8 * (mi >> 1) + lr;
                    int chunk = 2 * s + (mi & 1);
                    uint32_t ad = baseB + (uint32_t)(nrow * 4 + (chunk ^ ((nrow >> 1) & 3))) * 16u;
                    LDSM4(bfr[2*p][0], bfr[2*p][1], bfr[2*p+1][0], bfr[2*p+1][1], ad);
                }
            }
            #pragma unroll
            for (int i = 0; i < 4; i++) {
                int row = m0w + 16 * i + (mi & 1) * 8 + lr;
                int chunk = 2 * s + (mi >> 1);
                uint32_t ad = baseA + (uint32_t)(row * 4 + (chunk ^ ((row >> 1) & 3))) * 16u;
                uint32_t a0, a1, a2, a3;
                LDSM4(a0, a1, a2, a3, ad);
                #pragma unroll
                for (int j = 0; j < 4; j++)
                    MMA_BF16(acc[i][j], a0, a1, a2, a3, bfr[j][0], bfr[j][1]);
            }
        }
    }

    // ---- epilogue (runtime mode) ----
    #pragma unroll
    for (int i = 0; i < 4; i++) {
        int gm0 = m0 + m0w + i * 16 + g;
        #pragma unroll
        for (int half = 0; half < 2; half++) {
            int gm = gm0 + half * 8;
            if (gm >= M) continue;
            float bv = (t.mode != 2 && t.bias) ? t.bias[gm] : 0.f;
            #pragma unroll
            for (int j = 0; j < 4; j++) {
                int gn = n0 + n0w + j * 8 + 2 * c;
                long idx = (long)gm * ldc + gn;
                float v0 = acc[i][j][half * 2 + 0];
                float v1 = acc[i][j][half * 2 + 1];
                if (t.mode == 2) {
                    float2 o = make_float2(t.alpha * v0, t.alpha * v1);
                    *reinterpret_cast<float2*>(&C[idx]) = o;
                } else {
                    float o0, o1;
                    if (t.mode == 3) { o0 = v0 + bv + R[idx]; o1 = v1 + bv + R[idx + 1]; }
                    else             { o0 = t.alpha * v0 + bv; o1 = t.alpha * v1 + bv; }
                    __nv_bfloat162 h;
                    h.x = __float2bfloat16(o0); h.y = __float2bfloat16(o1);
                    *reinterpret_cast<__nv_bfloat162*>(&CB[idx]) = h;
                }
            }
        }
    }
}

static inline GTask mkTask(const __nv_bfloat16* A, const __nv_bfloat16* B,
                           float* C, __nv_bfloat16* CB, const float* R, const float* bias,
                           int M, int K, int lda, int ldb, int ldc,
                           long sA, long sB, long sC, float alpha, int splitK, int mode) {
    GTask t; t.A = A; t.B = B; t.C = C; t.CB = CB; t.R = R; t.bias = bias;
    t.M = M; t.K = K; t.lda = lda; t.ldb = ldb; t.ldc = ldc;
    t.sA = sA; t.sB = sB; t.sC = sC; t.alpha = alpha; t.splitK = splitK; t.mode = mode;
    return t;
}

// ---------------- merged deterministic split-K reduce (ATT + S2) ----------------
__global__ void reduce_both() {
    int i = blockIdx.x * 256 + threadIdx.x;
    const int PER = CL * CL;
    if (i < BB * PER) {
        int b = i / PER, r = i - b * PER;
        float s = 0.f;
        #pragma unroll
        for (int k = 0; k < SPLITK; k++)
            s += g_ATTP[((long)b * SPLITK + k) * PER + r];
        g_ATTb[i] = __float2bfloat16(s);
    } else {
        int j = i - BB * PER;
        int b = j / PER, r = j - b * PER;
        float s = 0.f;
        #pragma unroll
        for (int k = 0; k < SPLITK2; k++)
            s += g_S2P[((long)b * SPLITK2 + k) * PER + r];
        g_S2b[j] = __float2bfloat16(s);
    }
}

// ---------------- CBAM: channel pooling (mean+max over HW, bf16 in) ----------------
__global__ void chanpool_kernel() {
    int c = blockIdx.x, b = blockIdx.y;
    int t = threadIdx.x;
    const __nv_bfloat162* p = reinterpret_cast<const __nv_bfloat162*>(
        g_ZPb + ((long)b * CH + c) * HW);
    float s = 0.f, mx = -1e30f;
    for (int i = t; i < HW / 2; i += 256) {
        __nv_bfloat162 h = p[i];
        float v0 = __bfloat162float(h.x), v1 = __bfloat162float(h.y);
        s += v0 + v1;
        mx = fmaxf(mx, fmaxf(v0, v1));
    }
    __shared__ float ss[256];
    __shared__ float sm[256];
    ss[t] = s; sm[t] = mx;
    __syncthreads();
    for (int o = 128; o > 0; o >>= 1) {
        if (t < o) { ss[t] += ss[t + o]; sm[t] = fmaxf(sm[t], sm[t + o]); }
        __syncthreads();
    }
    if (t == 0) {
        g_pm[b * CH + c] = ss[0] * (1.f / HW);
        g_px[b * CH + c] = sm[0];
    }
}

// ---------------- CBAM: channel-attention MLP ----------------
__global__ void camlp_kernel(const float* __restrict__ fc1, const float* __restrict__ fc2) {
    int b = blockIdx.x;
    int t = threadIdx.x;
    __shared__ float hm[16], hx[16];
    if (t < 16) {
        float s = 0.f;
        for (int c = 0; c < CH; c++) s += fc1[t * CH + c] * g_pm[b * CH + c];
        hm[t] = fmaxf(s, 0.f);
    } else if (t < 32) {
        int h = t - 16;
        float s = 0.f;
        for (int c = 0; c < CH; c++) s += fc1[h * CH + c] * g_px[b * CH + c];
        hx[h] = fmaxf(s, 0.f);
    }
    __syncthreads();
    float sm = 0.f, sx = 0.f;
    #pragma unroll
    for (int h = 0; h < 16; h++) {
        float w = fc2[t * 16 + h];
        sm += w * hm[h];
        sx += w * hx[h];
    }
    g_ca[b * CH + t] = 1.f / (1.f + expf(-(sm + sx)));
}

// ---------------- CBAM: spatial pooling over channels of z_pnl*ca ----------------
__global__ void spool_kernel() {
    __shared__ float cas[CH];
    int idx = blockIdx.x * 256 + threadIdx.x;
    int b = idx / HW;
    int p = idx - b * HW;
    for (int c = threadIdx.x; c < CH; c += 256) cas[c] = g_ca[b * CH + c];
    __syncthreads();
    float s = 0.f, mx = -1e30f;
    for (int c = 0; c < CH; c++) {
        float v = __bfloat162float(g_ZPb[((long)b * CH + c) * HW + p]) * cas[c];
        s += v;
        mx = fmaxf(mx, v);
    }
    g_sam[idx] = s * (1.f / CH);
    g_sax[idx] = mx;
}

// ---------------- CBAM: 7x7 spatial conv + sigmoid ----------------
__global__ void sconv_kernel(const float* __restrict__ w) {
    int idx = blockIdx.x * 256 + threadIdx.x;
    int b = idx / HW;
    int p = idx - b * HW;
    int h = p >> 6, wq = p & 63;
    float s = 0.f;
    #pragma unroll
    for (int kh = 0; kh < 7; kh++) {
        int ih = h + kh - 3;
        if (ih < 0 || ih >= 64) continue;
        #pragma unroll
        for (int kw = 0; kw < 7; kw++) {
            int iw = wq + kw - 3;
            if (iw < 0 || iw >= 64) continue;
            int q = (ih << 6) | iw;
            s += w[kh * 7 + kw] * g_sam[b * HW + q] + w[49 + kh * 7 + kw] * g_sax[b * HW + q];
        }
    }
    g_sas[idx] = 1.f / (1.f + expf(-s));
}

// ---------------- final weighted fusion ----------------
__global__ void final_kernel(const float* __restrict__ x, const float* __restrict__ fwp,
                             float* __restrict__ out) {
    long e = 2L * (blockIdx.x * 256 + threadIdx.x);
    long p = e % HW;
    long bc = e / HW;
    long b = bc / CH;
    float fw = *fwp;
    __nv_bfloat162 zp2 = *reinterpret_cast<const __nv_bfloat162*>(g_ZPb + e);
    float2 x2 = *reinterpret_cast<const float2*>(x + e);
    float ca = g_ca[bc];
    float2 o;
    o.x = fw * __bfloat162float(zp2.x) * ca * g_sas[b * HW + p]     + (1.f - fw) * x2.x;
    o.y = fw * __bfloat162float(zp2.y) * ca * g_sas[b * HW + p + 1] + (1.f - fw) * x2.y;
    *reinterpret_cast<float2*>(out + e) = o;
}

// ---------------- launch ----------------
extern "C" void kernel_launch(void* const* d_in, const int* in_sizes, int n_in,
                              void* d_out, int out_size) {
    const float* x   = (const float*)d_in[0];
    const float* x0  = (const float*)d_in[1];
    const float* cgw = (const float*)d_in[2];
    const float* cgb = (const float*)d_in[3];
    const float* ctw = (const float*)d_in[4];
    const float* ctb = (const float*)d_in[5];
    const float* cpw = (const float*)d_in[6];
    const float* cpb = (const float*)d_in[7];
    const float* cWw = (const float*)d_in[8];
    const float* cWb = (const float*)d_in[9];
    const float* cbg = (const float*)d_in[10];
    const float* cbb = (const float*)d_in[11];
    const float* cbm = (const float*)d_in[12];
    const float* cbv = (const float*)d_in[13];
    const float* pgw = (const float*)d_in[14];
    const float* pgb = (const float*)d_in[15];
    const float* ptw = (const float*)d_in[16];
    const float* ptb = (const float*)d_in[17];
    const float* ppw = (const float*)d_in[18];
    const float* ppb = (const float*)d_in[19];
    const float* pWw = (const float*)d_in[20];
    const float* pWb = (const float*)d_in[21];
    const float* pbg = (const float*)d_in[22];
    const float* pbb = (const float*)d_in[23];
    const float* pbm = (const float*)d_in[24];
    const float* pbv = (const float*)d_in[25];
    const float* fc1 = (const float*)d_in[26];
    const float* fc2 = (const float*)d_in[27];
    const float* saw = (const float*)d_in[28];
    const float* fwp = (const float*)d_in[29];
    float* out = (float*)d_out;

    __nv_bfloat16 *SLAB, *X0B, *THB, *PGX, *T2B, *ZPB, *ATTB, *S2B;
    __nv_bfloat16 *CTWB, *PGXW, *WT2B, *ZPWB;
    float *ATTP, *S2P, *PGXBI, *BIAST, *BIAS2;
    cudaGetSymbolAddress((void**)&SLAB, g_slab);
    cudaGetSymbolAddress((void**)&X0B,  g_x0b);
    cudaGetSymbolAddress((void**)&THB,  g_THb);
    cudaGetSymbolAddress((void**)&PGX,  g_pgx);
    cudaGetSymbolAddress((void**)&T2B,  g_T2b);
    cudaGetSymbolAddress((void**)&ZPB,  g_ZPb);
    cudaGetSymbolAddress((void**)&ATTB, g_ATTb);
    cudaGetSymbolAddress((void**)&S2B,  g_S2b);
    cudaGetSymbolAddress((void**)&CTWB, g_ctwb);
    cudaGetSymbolAddress((void**)&PGXW, g_pgxw);
    cudaGetSymbolAddress((void**)&WT2B, g_wt2b);
    cudaGetSymbolAddress((void**)&ZPWB, g_zpwb);
    cudaGetSymbolAddress((void**)&ATTP, g_ATTP);
    cudaGetSymbolAddress((void**)&S2P,  g_S2P);
    cudaGetSymbolAddress((void**)&PGXBI,g_pgxbias);
    cudaGetSymbolAddress((void**)&BIAST,g_biast);
    cudaGetSymbolAddress((void**)&BIAS2,g_bias2);

    const long sSLAB = (long)SLABR * HW;
    const long sPGX  = (long)PGR * HW;
    const int BIG = 1 << 30;

    // 1) setup (all weight prep in one launch)
    setup_kernel<<<(SEG7 + 255) / 256, 256>>>(
        ctw, cpw, cgw, pgw, ppw, cpb, cgb, pgb, ppb, pWw, cWw, ptw, ptb,
        cbg, cbb, cbm, cbv, cWb, pbg, pbb, pbm, pbv, pWb);
    // 2) converts (x -> slab, x0 -> x0b)
    convert_kernel<<<(CVT + 255) / 256, 256>>>(x, x0);

    // 3) stacked conv PH|GX|G2|P2 (y 0-2) + TH (y 3)
    {
        GTask t0 = mkTask(PGXW, X0B, nullptr, PGX, nullptr, PGXBI,
                          PGR, CL, CL, HW, HW, 0L, (long)CL*HW, sPGX, 1.f, 1, 0);
        GTask t1 = mkTask(CTWB, SLAB + (long)XOFF*HW, nullptr, THB, nullptr, ctb,
                          CL, CH, CH, HW, HW, 0L, sSLAB, (long)CL*HW, 1.f, 1, 0);
        gemm_rt<false><<<dim3(HW/128, 4, BB), 256>>>(t0, t1, 3, BIG);
    }
    // 4) dual split-K: ATT (z<256) + S2 (z>=256)
    {
        GTask t0 = mkTask(THB, PGX, ATTP, nullptr, nullptr, nullptr,
                          CL, HW, HW, HW, CL, (long)CL*HW, sPGX, (long)CL*CL,
                          1.f/CL, SPLITK, 2);
        GTask t1 = mkTask(PGX + (long)256*HW, PGX + (long)320*HW, S2P, nullptr, nullptr, nullptr,
                          CL, MM, MM, MM, CL, sPGX, sPGX, (long)CL*CL,
                          1.f/MM, SPLITK2, 2);
        gemm_rt<true><<<dim3(1, 1, BB*SPLITK + BB*SPLITK2), 256>>>(t0, t1, BIG, BB*SPLITK);
    }
    // 5) merged reduce -> ATTB, S2B
    reduce_both<<<2*BB*CL*CL/256, 256>>>();
    // 6) Y = ATT @ GX  -> slab rows YOFF..
    {
        GTask t0 = mkTask(ATTB, PGX + (long)CL*HW, nullptr, SLAB + (long)YOFF*HW, nullptr, nullptr,
                          CL, CL, CL, HW, HW, (long)CL*CL, sPGX, sSLAB, 1.f, 1, 0);
        gemm_rt<false><<<dim3(HW/128, 1, BB), 256>>>(t0, t0, BIG, BIG);
    }
    // 7) T2 fused over [Y; x] (K=384)
    {
        GTask t0 = mkTask(WT2B, SLAB + (long)YOFF*HW, nullptr, T2B, nullptr, BIAST,
                          RR, KT2, KT2, HW, HW, 0L, sSLAB, (long)RR*HW, 1.f, 1, 0);
        gemm_rt<false><<<dim3(HW/128, 1, BB), 256>>>(t0, t0, BIG, BIG);
    }
    // 8) Y2v = S2 @ T2v -> slab rows 0-63
    {
        GTask t0 = mkTask(S2B, T2B, nullptr, SLAB + (long)Y2OFF*HW, nullptr, nullptr,
                          CL, CL, CL, MM, MM, (long)CL*CL, (long)RR*HW, sSLAB, 1.f, 1, 0);
        gemm_rt<false><<<dim3(MM/128, 1, BB), 256>>>(t0, t0, BIG, BIG);
    }
    // 9) ZP = [s2*pWw | s1*cWw] @ [Y2;Y] + (b1+b2) + x  (bf16 out)
    {
        GTask t0 = mkTask(ZPWB, SLAB, nullptr, ZPB, x, BIAS2,
                          CH, KZP, KZP, HW, HW, 0L, sSLAB, (long)CH*HW, 1.f, 1, 3);
        gemm_rt<false><<<dim3(HW/128, CH/128, BB), 256>>>(t0, t0, BIG, BIG);
    }

    // ---- CBAM + fusion ----
    chanpool_kernel<<<dim3(CH, BB), 256>>>();
    camlp_kernel<<<BB, 256>>>(fc1, fc2);
    spool_kernel<<<BB*HW/256, 256>>>();
    sconv_kernel<<<BB*HW/256, 256>>>(saw);
    final_kernel<<<BB*CH*HW/512, 256>>>(x, fwp, out);
}

// round 9
// speedup vs baseline: 4.9953x; 1.0172x over previous
#include <cuda_runtime.h>
#include <cuda_bf16.h>
#include <cstdint>
#include <math.h>

#define BB 8
#define CH 256
#define CL 128
#define RR 64
#define HW 4096
#define MM 2048
#define SPLITK 32     // ATT affinity (K=4096)
#define SPLITK2 16    // S2 (K=2048)
#define SLABR 448     // slab rows per batch: [Y2(64) | Y(128) | x(256)]
#define Y2OFF 0
#define YOFF  64
#define XOFF  192
#define KT2   384     // T2 fused K  ([Y;x])
#define KZP   192     // ZP fused K  ([Y2;Y])
#define PGR   384     // stacked conv rows: PH(128)|GX(128)|G2(64)|P2(64)

// ---------------- scratch (static device globals; no runtime alloc) ----------------
__device__ __align__(16) __nv_bfloat16 g_slab[BB*SLABR*HW];   // Y2 | Y | x
__device__ __align__(16) __nv_bfloat16 g_x0b [BB*CL*HW];
__device__ __align__(16) __nv_bfloat16 g_THb [BB*CL*HW];
__device__ __align__(16) __nv_bfloat16 g_pgx [BB*PGR*HW];     // PH|GX|G2|P2
__device__ __align__(16) __nv_bfloat16 g_T2b [BB*RR*HW];
__device__ __align__(16) __nv_bfloat16 g_ZPb [BB*CH*HW];
__device__ __align__(16) __nv_bfloat16 g_ATTb[BB*CL*CL];
__device__ __align__(16) __nv_bfloat16 g_S2b [BB*CL*CL];
__device__ __align__(16) __nv_bfloat16 g_ctwb[CL*CH];
__device__ __align__(16) __nv_bfloat16 g_pgxw[PGR*CL];        // cpw|cgw|pgw|ppw
__device__ __align__(16) __nv_bfloat16 g_wt2b[RR*KT2];        // [ptw*s1*cWw | ptw]
__device__ __align__(16) __nv_bfloat16 g_zpwb[CH*KZP];        // [s2*pWw | s1*cWw]
__device__ float g_ATTP[BB*SPLITK*CL*CL];
__device__ float g_S2P[BB*SPLITK2*CL*CL];
__device__ float g_pgxbias[PGR];
__device__ float g_biast[RR];
__device__ float g_bias2[CH];
__device__ float g_pm[BB*CH];
__device__ float g_px[BB*CH];
__device__ float g_ca[BB*CH];
__device__ float g_sam[BB*HW];
__device__ float g_sax[BB*HW];
__device__ float g_sas[BB*HW];

// ---------------- merged converts + setup (one launch) ----------------
#define CVA (BB*CH*HW/2)
#define CVT (CVA + BB*CL*HW/2)
#define SEG0 (CVT+32768)    // ctwb
#define SEG1 (SEG0+49152)   // pgxw
#define SEG2 (SEG1+384)     // pgxbias
#define SEG3 (SEG2+49152)   // zpwb
#define SEG4 (SEG3+16384)   // wt2b copy half
#define SEG5 (SEG4+8192)    // wt2b inner-product half
#define SEG6 (SEG5+64)      // biast
#define SEG7 (SEG6+256)     // bias2
__global__ void prep_all_kernel(
    const float* __restrict__ x, const float* __restrict__ x0,
    const float* __restrict__ ctw, const float* __restrict__ cpw,
    const float* __restrict__ cgw, const float* __restrict__ pgw,
    const float* __restrict__ ppw, const float* __restrict__ cpb,
    const float* __restrict__ cgb, const float* __restrict__ pgb,
    const float* __restrict__ ppb, const float* __restrict__ pWw,
    const float* __restrict__ cWw, const float* __restrict__ ptw,
    const float* __restrict__ ptb, const float* __restrict__ cbg,
    const float* __restrict__ cbb, const float* __restrict__ cbm,
    const float* __restrict__ cbv, const float* __restrict__ cWb,
    const float* __restrict__ pbg, const float* __restrict__ pbb,
    const float* __restrict__ pbm, const float* __restrict__ pbv,
    const float* __restrict__ pWb)
{
    int i = blockIdx.x * 256 + threadIdx.x;
    auto s1f = [&](int c) { return cbg[c] * rsqrtf(cbv[c] + 1e-5f); };
    auto b1f = [&](int c) { float s = s1f(c); return cWb[c] * s + cbb[c] - cbm[c] * s; };
    auto s2f = [&](int c) { return pbg[c] * rsqrtf(pbv[c] + 1e-5f); };
    auto b2f = [&](int c) { float s = s2f(c); return pWb[c] * s + pbb[c] - pbm[c] * s; };
    if (i < CVA) {
        long e = 2L * i;
        int b = (int)(e / (CH * HW));
        long inner = e - (long)b * (CH * HW);
        float2 v = *reinterpret_cast<const float2*>(x + e);
        __nv_bfloat162 h;
        h.x = __float2bfloat16(v.x); h.y = __float2bfloat16(v.y);
        *reinterpret_cast<__nv_bfloat162*>(g_slab + (long)b * SLABR * HW + (long)XOFF * HW + inner) = h;
    } else if (i < CVT) {
        long e = 2L * (i - CVA);
        float2 v = *reinterpret_cast<const float2*>(x0 + e);
        __nv_bfloat162 h;
        h.x = __float2bfloat16(v.x); h.y = __float2bfloat16(v.y);
        *reinterpret_cast<__nv_bfloat162*>(g_x0b + e) = h;
    } else if (i < SEG0) {
        int j = i - CVT;
        g_ctwb[j] = __float2bfloat16(ctw[j]);
    } else if (i < SEG1) {
        int j = i - SEG0, r = j >> 7, k = j & 127;
        float v = (r < 128) ? cpw[r * 128 + k]
                : (r < 256) ? cgw[(r - 128) * 128 + k]
                : (r < 320) ? pgw[(r - 256) * 128 + k]
                            : ppw[(r - 320) * 128 + k];
        g_pgxw[j] = __float2bfloat16(v);
    } else if (i < SEG2) {
        int r = i - SEG1;
        g_pgxbias[r] = (r < 128) ? cpb[r] : (r < 256) ? cgb[r - 128]
                     : (r < 320) ? pgb[r - 256] : ppb[r - 320];
    } else if (i < SEG3) {
        int j = i - SEG2, o = j / KZP, k = j - o * KZP;
        float v = (k < RR) ? s2f(o) * pWw[o * RR + k]
                           : s1f(o) * cWw[o * CL + (k - RR)];
        g_zpwb[j] = __float2bfloat16(v);
    } else if (i < SEG4) {
        int j = i - SEG3, o = j >> 8, kk = j & 255;
        g_wt2b[o * KT2 + CL + kk] = __float2bfloat16(ptw[o * CH + kk]);
    } else if (i < SEG5) {
        int j = i - SEG4, o = j >> 7, m = j & 127;
        float s = 0.f;
        for (int c = 0; c < CH; c++)
            s += ptw[o * CH + c] * s1f(c) * cWw[c * CL + m];
        g_wt2b[o * KT2 + m] = __float2bfloat16(s);
    } else if (i < SEG6) {
        int o = i - SEG5;
        float bt = ptb[o];
        for (int c = 0; c < CH; c++) bt += ptw[o * CH + c] * b1f(c);
        g_biast[o] = bt;
    } else if (i < SEG7) {
        int c = i - SEG6;
        g_bias2[c] = b1f(c) + b2f(c);
    }
}

// ---------------- runtime-task BF16 tensor-core GEMM (hoisted addressing) ----------------
#define MMA_BF16(d, a0,a1,a2,a3, b0,b1) \
    asm volatile("mma.sync.aligned.m16n8k16.row.col.f32.bf16.bf16.f32 " \
        "{%0,%1,%2,%3},{%4,%5,%6,%7},{%8,%9},{%0,%1,%2,%3};" \
        : "+f"(d[0]),"+f"(d[1]),"+f"(d[2]),"+f"(d[3]) \
        : "r"(a0),"r"(a1),"r"(a2),"r"(a3),"r"(b0),"r"(b1))

#define LDSM4(r0,r1,r2,r3, ad) \
    asm volatile("ldmatrix.sync.aligned.m8n8.x4.shared.b16 {%0,%1,%2,%3},[%4];" \
        : "=r"(r0),"=r"(r1),"=r"(r2),"=r"(r3) : "r"(ad))
#define LDSM4T(r0,r1,r2,r3, ad) \
    asm volatile("ldmatrix.sync.aligned.m8n8.x4.trans.shared.b16 {%0,%1,%2,%3},[%4];" \
        : "=r"(r0),"=r"(r1),"=r"(r2),"=r"(r3) : "r"(ad))

#define CP16(s, g)  asm volatile("cp.async.cg.shared.global [%0],[%1],16;\n" :: "r"(s), "l"(g))
#define CP16Z(s, g) asm volatile("cp.async.cg.shared.global [%0],[%1],16,0;\n" :: "r"(s), "l"(g))
#define CPCOMMIT()  asm volatile("cp.async.commit_group;\n")
#define CPWAIT1()   asm volatile("cp.async.wait_group 1;\n")

struct GTask {
    const __nv_bfloat16 *A, *B;
    float* C;
    __nv_bfloat16* CB;
    const float *R, *bias;
    int M, K, lda, ldb, ldc;
    long sA, sB, sC;
    float alpha;
    int splitK;
    int mode;   // 0: alpha*AB+bias -> CB; 2: alpha*AB -> C[z]; 3: AB+bias+R -> CB
};

template<bool TB>
__global__ __launch_bounds__(256, 2) void gemm_rt(GTask t0, GTask t1, int ySplit, int zSplit)
{
    const bool second = ((int)blockIdx.y >= ySplit) || ((int)blockIdx.z >= zSplit);
    const GTask& t = second ? t1 : t0;
    int by = blockIdx.y - (((int)blockIdx.y >= ySplit) ? ySplit : 0);
    int bz = blockIdx.z - (((int)blockIdx.z >= zSplit) ? zSplit : 0);

    const int batch = bz / t.splitK;
    const int kslice = bz - batch * t.splitK;
    const int Kchunk = t.K / t.splitK;
    const int k0base = kslice * Kchunk;

    const __nv_bfloat16* A = t.A + (long)batch * t.sA;
    const __nv_bfloat16* Bm = t.B + (long)batch * t.sB;
    float* C = t.C;
    __nv_bfloat16* CB = t.CB;
    const float* R = t.R;
    if (t.mode == 2) C += (long)bz * t.sC;
    else {
        if (CB) CB += (long)batch * t.sC;
        if (R)  R  += (long)batch * t.sC;
    }
    const int lda = t.lda, ldb = t.ldb, ldc = t.ldc, M = t.M;

    const int m0 = by * 128;
    const int n0 = blockIdx.x * 128;
    const int tid = threadIdx.x;
    const int warp = tid >> 5, lane = tid & 31;
    const int wm = warp >> 2, wn = warp & 3;
    const int g = lane >> 2, c = lane & 3;
    const int mi = lane >> 3, lr = lane & 7;
    const int m0w = wm * 64, n0w = wn * 32;

    __shared__ uint32_t SA[3][2048];
    __shared__ uint32_t SB[3][2048];
    const uint32_t stA = (uint32_t)__cvta_generic_to_shared(&SA[0][0]);
    const uint32_t stB = (uint32_t)__cvta_generic_to_shared(&SB[0][0]);

    float acc[4][4][4];
    #pragma unroll
    for (int i = 0; i < 4; i++)
        #pragma unroll
        for (int j = 0; j < 4; j++)
            #pragma unroll
            for (int e = 0; e < 4; e++) acc[i][j][e] = 0.f;

    const int nk = Kchunk / 32;

    // ---- hoisted cp.async addressing: per-it smem offsets + rotating global ptrs ----
    uint32_t saoff[2], sboff[2];
    const __nv_bfloat16 *gA[2], *gB[2];
    bool okA[2];
    const int bstep = TB ? 32 : 32 * ldb;
    #pragma unroll
    for (int it = 0; it < 2; it++) {
        int f = tid + it * 256;
        {   int row = f >> 2, cn = f & 3;
            saoff[it] = (uint32_t)(row * 4 + (cn ^ ((row >> 1) & 3))) * 16u;
            okA[it] = (m0 + row) < M;
            gA[it] = A + (okA[it] ? (long)(m0 + row) * lda : 0L) + k0base + cn * 8;
        }
        if (!TB) {
            int k = f >> 4, cn = f & 15;
            sboff[it] = (uint32_t)(k * 16 + (cn ^ (k & 7))) * 16u;
            gB[it] = Bm + (long)(k0base + k) * ldb + n0 + cn * 8;
        } else {
            int row = f >> 2, cn = f & 3;
            sboff[it] = (uint32_t)(row * 4 + (cn ^ ((row >> 1) & 3))) * 16u;
            gB[it] = Bm + (long)(n0 + row) * ldb + k0base + cn * 8;
        }
    }
    // ---- hoisted fragment offsets ----
    uint32_t aoff[2][4], boff[2][2];
    #pragma unroll
    for (int s = 0; s < 2; s++) {
        #pragma unroll
        for (int i = 0; i < 4; i++) {
            int row = m0w + 16 * i + (mi & 1) * 8 + lr;
            int chunk = 2 * s + (mi >> 1);
            aoff[s][i] = (uint32_t)(row * 4 + (chunk ^ ((row >> 1) & 3))) * 16u;
        }
        #pragma unroll
        for (int p = 0; p < 2; p++) {
            if (!TB) {
                int krow = 16 * s + (mi & 1) * 8 + lr;
                int chunk = wn * 4 + 2 * p + (mi >> 1);
                boff[s][p] = (uint32_t)(krow * 16 + (chunk ^ (krow & 7))) * 16u;
            } else {
                int nrow = n0w + 16 * p + 8 * (mi >> 1) + lr;
                int chunk = 2 * s + (mi & 1);
                boff[s][p] = (uint32_t)(nrow * 4 + (chunk ^ ((nrow >> 1) & 3))) * 16u;
            }
        }
    }

    auto issue = [&](uint32_t bA, uint32_t bB) {
        #pragma unroll
        for (int it = 0; it < 2; it++) {
            if (okA[it]) { CP16(bA + saoff[it], gA[it]); } else { CP16Z(bA + saoff[it], gA[it]); }
            CP16(bB + sboff[it], gB[it]);
            gA[it] += 32;
            gB[it] += bstep;
        }
    };

    if (0 < nk) issue(stA, stB);
    CPCOMMIT();
    if (1 < nk) issue(stA + 8192, stB + 8192);
    CPCOMMIT();

    uint32_t iA = stA + 16384, iB = stB + 16384;   // issue stage (t+2)
    uint32_t cA = stA, cB = stB;                   // consume stage (t)

    for (int tt = 0; tt < nk; tt++) {
        CPWAIT1();
        __syncthreads();
        if (tt + 2 < nk) issue(iA, iB);
        CPCOMMIT();
        iA += 8192; if (iA == stA + 24576) iA = stA;
        iB += 8192; if (iB == stB + 24576) iB = stB;

        #pragma unroll
        for (int s = 0; s < 2; s++) {
            uint32_t bfr[4][2];
            #pragma unroll
            for (int p = 0; p < 2; p++) {
                if (!TB) {
                    LDSM4T(bfr[2*p][0], bfr[2*p][1], bfr[2*p+1][0], bfr[2*p+1][1], cB + boff[s][p]);
                } else {
                    LDSM4(bfr[2*p][0], bfr[2*p][1], bfr[2*p+1][0], bfr[2*p+1][1], cB + boff[s][p]);
                }
            }
            #pragma unroll
            for (int i = 0; i < 4; i++) {
                uint32_t a0, a1, a2, a3;
                LDSM4(a0, a1, a2, a3, cA + aoff[s][i]);
                #pragma unroll
                for (int j = 0; j < 4; j++)
                    MMA_BF16(acc[i][j], a0, a1, a2, a3, bfr[j][0], bfr[j][1]);
            }
        }
        cA += 8192; if (cA == stA + 24576) cA = stA;
        cB += 8192; if (cB == stB + 24576) cB = stB;
    }

    // ---- epilogue ----
    #pragma unroll
    for (int i = 0; i < 4; i++) {
        int gm0 = m0 + m0w + i * 16 + g;
        #pragma unroll
        for (int half = 0; half < 2; half++) {
            int gm = gm0 + half * 8;
            if (gm >= M) continue;
            float bv = (t.mode != 2 && t.bias) ? t.bias[gm] : 0.f;
            #pragma unroll
            for (int j = 0; j < 4; j++) {
                int gn = n0 + n0w + j * 8 + 2 * c;
                long idx = (long)gm * ldc + gn;
                float v0 = acc[i][j][half * 2 + 0];
                float v1 = acc[i][j][half * 2 + 1];
                if (t.mode == 2) {
                    float2 o = make_float2(t.alpha * v0, t.alpha * v1);
                    *reinterpret_cast<float2*>(&C[idx]) = o;
                } else {
                    float o0, o1;
                    if (t.mode == 3) { o0 = v0 + bv + R[idx]; o1 = v1 + bv + R[idx + 1]; }
                    else             { o0 = t.alpha * v0 + bv; o1 = t.alpha * v1 + bv; }
                    __nv_bfloat162 h;
                    h.x = __float2bfloat16(o0); h.y = __float2bfloat16(o1);
                    *reinterpret_cast<__nv_bfloat162*>(&CB[idx]) = h;
                }
            }
        }
    }
}

static inline GTask mkTask(const __nv_bfloat16* A, const __nv_bfloat16* B,
                           float* C, __nv_bfloat16* CB, const float* R, const float* bias,
                           int M, int K, int lda, int ldb, int ldc,
                           long sA, long sB, long sC, float alpha, int splitK, int mode) {
    GTask t; t.A = A; t.B = B; t.C = C; t.CB = CB; t.R = R; t.bias = bias;
    t.M = M; t.K = K; t.lda = lda; t.ldb = ldb; t.ldc = ldc;
    t.sA = sA; t.sB = sB; t.sC = sC; t.alpha = alpha; t.splitK = splitK; t.mode = mode;
    return t;
}

// ---------------- merged deterministic split-K reduce (ATT + S2) ----------------
__global__ void reduce_both() {
    int i = blockIdx.x * 256 + threadIdx.x;
    const int PER = CL * CL;
    if (i < BB * PER) {
        int b = i / PER, r = i - b * PER;
        float s = 0.f;
        #pragma unroll
        for (int k = 0; k < SPLITK; k++)
            s += g_ATTP[((long)b * SPLITK + k) * PER + r];
        g_ATTb[i] = __float2bfloat16(s);
    } else {
        int j = i - BB * PER;
        int b = j / PER, r = j - b * PER;
        float s = 0.f;
        #pragma unroll
        for (int k = 0; k < SPLITK2; k++)
            s += g_S2P[((long)b * SPLITK2 + k) * PER + r];
        g_S2b[j] = __float2bfloat16(s);
    }
}

// ---------------- CBAM: channel pooling (mean+max over HW, bf16 in) ----------------
__global__ void chanpool_kernel() {
    int c = blockIdx.x, b = blockIdx.y;
    int t = threadIdx.x;
    const __nv_bfloat162* p = reinterpret_cast<const __nv_bfloat162*>(
        g_ZPb + ((long)b * CH + c) * HW);
    float s = 0.f, mx = -1e30f;
    for (int i = t; i < HW / 2; i += 256) {
        __nv_bfloat162 h = p[i];
        float v0 = __bfloat162float(h.x), v1 = __bfloat162float(h.y);
        s += v0 + v1;
        mx = fmaxf(mx, fmaxf(v0, v1));
    }
    __shared__ float ss[256];
    __shared__ float sm[256];
    ss[t] = s; sm[t] = mx;
    __syncthreads();
    for (int o = 128; o > 0; o >>= 1) {
        if (t < o) { ss[t] += ss[t + o]; sm[t] = fmaxf(sm[t], sm[t + o]); }
        __syncthreads();
    }
    if (t == 0) {
        g_pm[b * CH + c] = ss[0] * (1.f / HW);
        g_px[b * CH + c] = sm[0];
    }
}

// ---------------- CBAM: channel-attention MLP ----------------
__global__ void camlp_kernel(const float* __restrict__ fc1, const float* __restrict__ fc2) {
    int b = blockIdx.x;
    int t = threadIdx.x;
    __shared__ float hm[16], hx[16];
    if (t < 16) {
        float s = 0.f;
        for (int c = 0; c < CH; c++) s += fc1[t * CH + c] * g_pm[b * CH + c];
        hm[t] = fmaxf(s, 0.f);
    } else if (t < 32) {
        int h = t - 16;
        float s = 0.f;
        for (int c = 0; c < CH; c++) s += fc1[h * CH + c] * g_px[b * CH + c];
        hx[h] = fmaxf(s, 0.f);
    }
    __syncthreads();
    float sm = 0.f, sx = 0.f;
    #pragma unroll
    for (int h = 0; h < 16; h++) {
        float w = fc2[t * 16 + h];
        sm += w * hm[h];
        sx += w * hx[h];
    }
    g_ca[b * CH + t] = 1.f / (1.f + expf(-(sm + sx)));
}

// ---------------- CBAM: spatial pooling over channels of z_pnl*ca ----------------
__global__ void spool_kernel() {
    __shared__ float cas[CH];
    int idx = blockIdx.x * 256 + threadIdx.x;
    int b = idx / HW;
    int p = idx - b * HW;
    for (int c = threadIdx.x; c < CH; c += 256) cas[c] = g_ca[b * CH + c];
    __syncthreads();
    float s = 0.f, mx = -1e30f;
    for (int c = 0; c < CH; c++) {
        float v = __bfloat162float(g_ZPb[((long)b * CH + c) * HW + p]) * cas[c];
        s += v;
        mx = fmaxf(mx, v);
    }
    g_sam[idx] = s * (1.f / CH);
    g_sax[idx] = mx;
}

// ---------------- CBAM: 7x7 spatial conv + sigmoid ----------------
__global__ void sconv_kernel(const float* __restrict__ w) {
    int idx = blockIdx.x * 256 + threadIdx.x;
    int b = idx / HW;
    int p = idx - b * HW;
    int h = p >> 6, wq = p & 63;
    float s = 0.f;
    #pragma unroll
    for (int kh = 0; kh < 7; kh++) {
        int ih = h + kh - 3;
        if (ih < 0 || ih >= 64) continue;
        #pragma unroll
        for (int kw = 0; kw < 7; kw++) {
            int iw = wq + kw - 3;
            if (iw < 0 || iw >= 64) continue;
            int q = (ih << 6) | iw;
            s += w[kh * 7 + kw] * g_sam[b * HW + q] + w[49 + kh * 7 + kw] * g_sax[b * HW + q];
        }
    }
    g_sas[idx] = 1.f / (1.f + expf(-s));
}

// ---------------- final weighted fusion ----------------
__global__ void final_kernel(const float* __restrict__ x, const float* __restrict__ fwp,
                             float* __restrict__ out) {
    long e = 2L * (blockIdx.x * 256 + threadIdx.x);
    long p = e % HW;
    long bc = e / HW;
    long b = bc / CH;
    float fw = *fwp;
    __nv_bfloat162 zp2 = *reinterpret_cast<const __nv_bfloat162*>(g_ZPb + e);
    float2 x2 = *reinterpret_cast<const float2*>(x + e);
    float ca = g_ca[bc];
    float2 o;
    o.x = fw * __bfloat162float(zp2.x) * ca * g_sas[b * HW + p]     + (1.f - fw) * x2.x;
    o.y = fw * __bfloat162float(zp2.y) * ca * g_sas[b * HW + p + 1] + (1.f - fw) * x2.y;
    *reinterpret_cast<float2*>(out + e) = o;
}

// ---------------- launch ----------------
extern "C" void kernel_launch(void* const* d_in, const int* in_sizes, int n_in,
                              void* d_out, int out_size) {
    const float* x   = (const float*)d_in[0];
    const float* x0  = (const float*)d_in[1];
    const float* cgw = (const float*)d_in[2];
    const float* cgb = (const float*)d_in[3];
    const float* ctw = (const float*)d_in[4];
    const float* ctb = (const float*)d_in[5];
    const float* cpw = (const float*)d_in[6];
    const float* cpb = (const float*)d_in[7];
    const float* cWw = (const float*)d_in[8];
    const float* cWb = (const float*)d_in[9];
    const float* cbg = (const float*)d_in[10];
    const float* cbb = (const float*)d_in[11];
    const float* cbm = (const float*)d_in[12];
    const float* cbv = (const float*)d_in[13];
    const float* pgw = (const float*)d_in[14];
    const float* pgb = (const float*)d_in[15];
    const float* ptw = (const float*)d_in[16];
    const float* ptb = (const float*)d_in[17];
    const float* ppw = (const float*)d_in[18];
    const float* ppb = (const float*)d_in[19];
    const float* pWw = (const float*)d_in[20];
    const float* pWb = (const float*)d_in[21];
    const float* pbg = (const float*)d_in[22];
    const float* pbb = (const float*)d_in[23];
    const float* pbm = (const float*)d_in[24];
    const float* pbv = (const float*)d_in[25];
    const float* fc1 = (const float*)d_in[26];
    const float* fc2 = (const float*)d_in[27];
    const float* saw = (const float*)d_in[28];
    const float* fwp = (const float*)d_in[29];
    float* out = (float*)d_out;

    __nv_bfloat16 *SLAB, *X0B, *THB, *PGX, *T2B, *ZPB, *ATTB, *S2B;
    __nv_bfloat16 *CTWB, *PGXW, *WT2B, *ZPWB;
    float *ATTP, *S2P, *PGXBI, *BIAST, *BIAS2;
    cudaGetSymbolAddress((void**)&SLAB, g_slab);
    cudaGetSymbolAddress((void**)&X0B,  g_x0b);
    cudaGetSymbolAddress((void**)&THB,  g_THb);
    cudaGetSymbolAddress((void**)&PGX,  g_pgx);
    cudaGetSymbolAddress((void**)&T2B,  g_T2b);
    cudaGetSymbolAddress((void**)&ZPB,  g_ZPb);
    cudaGetSymbolAddress((void**)&ATTB, g_ATTb);
    cudaGetSymbolAddress((void**)&S2B,  g_S2b);
    cudaGetSymbolAddress((void**)&CTWB, g_ctwb);
    cudaGetSymbolAddress((void**)&PGXW, g_pgxw);
    cudaGetSymbolAddress((void**)&WT2B, g_wt2b);
    cudaGetSymbolAddress((void**)&ZPWB, g_zpwb);
    cudaGetSymbolAddress((void**)&ATTP, g_ATTP);
    cudaGetSymbolAddress((void**)&S2P,  g_S2P);
    cudaGetSymbolAddress((void**)&PGXBI,g_pgxbias);
    cudaGetSymbolAddress((void**)&BIAST,g_biast);
    cudaGetSymbolAddress((void**)&BIAS2,g_bias2);

    const long sSLAB = (long)SLABR * HW;
    const long sPGX  = (long)PGR * HW;
    const int BIG = 1 << 30;

    // 1) merged converts + weight prep
    prep_all_kernel<<<(SEG7 + 255) / 256, 256>>>(
        x, x0, ctw, cpw, cgw, pgw, ppw, cpb, cgb, pgb, ppb, pWw, cWw, ptw, ptb,
        cbg, cbb, cbm, cbv, cWb, pbg, pbb, pbm, pbv, pWb);

    // 2) stacked conv PH|GX|G2|P2 (y 0-2) + TH (y 3)
    {
        GTask t0 = mkTask(PGXW, X0B, nullptr, PGX, nullptr, PGXBI,
                          PGR, CL, CL, HW, HW, 0L, (long)CL*HW, sPGX, 1.f, 1, 0);
        GTask t1 = mkTask(CTWB, SLAB + (long)XOFF*HW, nullptr, THB, nullptr, ctb,
                          CL, CH, CH, HW, HW, 0L, sSLAB, (long)CL*HW, 1.f, 1, 0);
        gemm_rt<false><<<dim3(HW/128, 4, BB), 256>>>(t0, t1, 3, BIG);
    }
    // 3) dual split-K: ATT (z<256) + S2 (z>=256)
    {
        GTask t0 = mkTask(THB, PGX, ATTP, nullptr, nullptr, nullptr,
                          CL, HW, HW, HW, CL, (long)CL*HW, sPGX, (long)CL*CL,
                          1.f/CL, SPLITK, 2);
        GTask t1 = mkTask(PGX + (long)256*HW, PGX + (long)320*HW, S2P, nullptr, nullptr, nullptr,
                          CL, MM, MM, MM, CL, sPGX, sPGX, (long)CL*CL,
                          1.f/MM, SPLITK2, 2);
        gemm_rt<true><<<dim3(1, 1, BB*SPLITK + BB*SPLITK2), 256>>>(t0, t1, BIG, BB*SPLITK);
    }
    // 4) merged reduce -> ATTB, S2B
    reduce_both<<<2*BB*CL*CL/256, 256>>>();
    // 5) Y = ATT @ GX  -> slab rows YOFF..
    {
        GTask t0 = mkTask(ATTB, PGX + (long)CL*HW, nullptr, SLAB + (long)YOFF*HW, nullptr, nullptr,
                          CL, CL, CL, HW, HW, (long)CL*CL, sPGX, sSLAB, 1.f, 1, 0);
        gemm_rt<false><<<dim3(HW/128, 1, BB), 256>>>(t0, t0, BIG, BIG);
    }
    // 6) T2 fused over [Y; x] (K=384)
    {
        GTask t0 = mkTask(WT2B, SLAB + (long)YOFF*HW, nullptr, T2B, nullptr, BIAST,
                          RR, KT2, KT2, HW, HW, 0L, sSLAB, (long)RR*HW, 1.f, 1, 0);
        gemm_rt<false><<<dim3(HW/128, 1, BB), 256>>>(t0, t0, BIG, BIG);
    }
    // 7) Y2v = S2 @ T2v -> slab rows 0-63
    {
        GTask t0 = mkTask(S2B, T2B, nullptr, SLAB + (long)Y2OFF*HW, nullptr, nullptr,
                          CL, CL, CL, MM, MM, (long)CL*CL, (long)RR*HW, sSLAB, 1.f, 1, 0);
        gemm_rt<false><<<dim3(MM/128, 1, BB), 256>>>(t0, t0, BIG, BIG);
    }
    // 8) ZP = [s2*pWw | s1*cWw] @ [Y2;Y] + (b1+b2) + x  (bf16 out)
    {
        GTask t0 = mkTask(ZPWB, SLAB, nullptr, ZPB, x, BIAS2,
                          CH, KZP, KZP, HW, HW, 0L, sSLAB, (long)CH*HW, 1.f, 1, 3);
        gemm_rt<false><<<dim3(HW/128, CH/128, BB), 256>>>(t0, t0, BIG, BIG);
    }

    // ---- CBAM + fusion ----
    chanpool_kernel<<<dim3(CH, BB), 256>>>();
    camlp_kernel<<<BB, 256>>>(fc1, fc2);
    spool_kernel<<<BB*HW/256, 256>>>();
    sconv_kernel<<<BB*HW/256, 256>>>(saw);
    final_kernel<<<BB*CH*HW/512, 256>>>(x, fwp, out);
}

// round 10
// speedup vs baseline: 5.2102x; 1.0430x over previous
#include <cuda_runtime.h>
#include <cuda_bf16.h>
#include <cstdint>
#include <math.h>

#define BB 8
#define CH 256
#define CL 128
#define RR 64
#define HW 4096
#define MM 2048
#define SPLITK 16     // ATT affinity (K=4096 -> Kchunk 256)
#define SPLITK2 8     // S2 (K=2048 -> Kchunk 256)
#define SLABR 448     // slab rows per batch: [Y2(64) | Y(128) | x(256)]
#define Y2OFF 0
#define YOFF  64
#define XOFF  192
#define KT2   384     // T2 fused K  ([Y;x])
#define KZP   192     // ZP fused K  ([Y2;Y])
#define PGR   384     // stacked conv rows: PH(128)|GX(128)|G2(64)|P2(64)

// ---------------- scratch (static device globals; no runtime alloc) ----------------
__device__ __align__(16) __nv_bfloat16 g_slab[BB*SLABR*HW];   // Y2 | Y | x
__device__ __align__(16) __nv_bfloat16 g_x0b [BB*CL*HW];
__device__ __align__(16) __nv_bfloat16 g_THb [BB*CL*HW];
__device__ __align__(16) __nv_bfloat16 g_pgx [BB*PGR*HW];     // PH|GX|G2|P2
__device__ __align__(16) __nv_bfloat16 g_T2b [BB*RR*HW];
__device__ __align__(16) __nv_bfloat16 g_ZPb [BB*CH*HW];
__device__ __align__(16) __nv_bfloat16 g_ATTb[BB*CL*CL];
__device__ __align__(16) __nv_bfloat16 g_S2b [BB*CL*CL];
__device__ __align__(16) __nv_bfloat16 g_ATTP[BB*SPLITK*CL*CL];   // bf16 split-K partials
__device__ __align__(16) __nv_bfloat16 g_S2P [BB*SPLITK2*CL*CL];
__device__ __align__(16) __nv_bfloat16 g_ctwb[CL*CH];
__device__ __align__(16) __nv_bfloat16 g_pgxw[PGR*CL];        // cpw|cgw|pgw|ppw
__device__ __align__(16) __nv_bfloat16 g_wt2b[RR*KT2];        // [ptw*s1*cWw | ptw]
__device__ __align__(16) __nv_bfloat16 g_zpwb[CH*KZP];        // [s2*pWw | s1*cWw]
__device__ float g_pgxbias[PGR];
__device__ float g_biast[RR];
__device__ float g_bias2[CH];
__device__ float g_pm[BB*CH];
__device__ float g_px[BB*CH];
__device__ float g_ca[BB*CH];
__device__ float g_sam[BB*HW];
__device__ float g_sax[BB*HW];
__device__ float g_sas[BB*HW];

// ---------------- merged converts (x4 vectorized) + setup (one launch) ----------------
#define CVA (BB*CH*HW/4)
#define CVT (CVA + BB*CL*HW/4)
#define SEG0 (CVT+32768)    // ctwb
#define SEG1 (SEG0+49152)   // pgxw
#define SEG2 (SEG1+384)     // pgxbias
#define SEG3 (SEG2+49152)   // zpwb
#define SEG4 (SEG3+16384)   // wt2b copy half
#define SEG5 (SEG4+8192)    // wt2b inner-product half
#define SEG6 (SEG5+64)      // biast
#define SEG7 (SEG6+256)     // bias2
__global__ void prep_all_kernel(
    const float* __restrict__ x, const float* __restrict__ x0,
    const float* __restrict__ ctw, const float* __restrict__ cpw,
    const float* __restrict__ cgw, const float* __restrict__ pgw,
    const float* __restrict__ ppw, const float* __restrict__ cpb,
    const float* __restrict__ cgb, const float* __restrict__ pgb,
    const float* __restrict__ ppb, const float* __restrict__ pWw,
    const float* __restrict__ cWw, const float* __restrict__ ptw,
    const float* __restrict__ ptb, const float* __restrict__ cbg,
    const float* __restrict__ cbb, const float* __restrict__ cbm,
    const float* __restrict__ cbv, const float* __restrict__ cWb,
    const float* __restrict__ pbg, const float* __restrict__ pbb,
    const float* __restrict__ pbm, const float* __restrict__ pbv,
    const float* __restrict__ pWb)
{
    int i = blockIdx.x * 256 + threadIdx.x;
    auto s1f = [&](int c) { return cbg[c] * rsqrtf(cbv[c] + 1e-5f); };
    auto b1f = [&](int c) { float s = s1f(c); return cWb[c] * s + cbb[c] - cbm[c] * s; };
    auto s2f = [&](int c) { return pbg[c] * rsqrtf(pbv[c] + 1e-5f); };
    auto b2f = [&](int c) { float s = s2f(c); return pWb[c] * s + pbb[c] - pbm[c] * s; };
    if (i < CVA) {
        long e = 4L * i;
        int b = (int)(e / (CH * HW));
        long inner = e - (long)b * (CH * HW);
        float4 v = *reinterpret_cast<const float4*>(x + e);
        __nv_bfloat162 h0, h1;
        h0.x = __float2bfloat16(v.x); h0.y = __float2bfloat16(v.y);
        h1.x = __float2bfloat16(v.z); h1.y = __float2bfloat16(v.w);
        uint2 u;
        u.x = *reinterpret_cast<uint32_t*>(&h0);
        u.y = *reinterpret_cast<uint32_t*>(&h1);
        *reinterpret_cast<uint2*>(g_slab + (long)b * SLABR * HW + (long)XOFF * HW + inner) = u;
    } else if (i < CVT) {
        long e = 4L * (i - CVA);
        float4 v = *reinterpret_cast<const float4*>(x0 + e);
        __nv_bfloat162 h0, h1;
        h0.x = __float2bfloat16(v.x); h0.y = __float2bfloat16(v.y);
        h1.x = __float2bfloat16(v.z); h1.y = __float2bfloat16(v.w);
        uint2 u;
        u.x = *reinterpret_cast<uint32_t*>(&h0);
        u.y = *reinterpret_cast<uint32_t*>(&h1);
        *reinterpret_cast<uint2*>(g_x0b + e) = u;
    } else if (i < SEG0) {
        int j = i - CVT;
        g_ctwb[j] = __float2bfloat16(ctw[j]);
    } else if (i < SEG1) {
        int j = i - SEG0, r = j >> 7, k = j & 127;
        float v = (r < 128) ? cpw[r * 128 + k]
                : (r < 256) ? cgw[(r - 128) * 128 + k]
                : (r < 320) ? pgw[(r - 256) * 128 + k]
                            : ppw[(r - 320) * 128 + k];
        g_pgxw[j] = __float2bfloat16(v);
    } else if (i < SEG2) {
        int r = i - SEG1;
        g_pgxbias[r] = (r < 128) ? cpb[r] : (r < 256) ? cgb[r - 128]
                     : (r < 320) ? pgb[r - 256] : ppb[r - 320];
    } else if (i < SEG3) {
        int j = i - SEG2, o = j / KZP, k = j - o * KZP;
        float v = (k < RR) ? s2f(o) * pWw[o * RR + k]
                           : s1f(o) * cWw[o * CL + (k - RR)];
        g_zpwb[j] = __float2bfloat16(v);
    } else if (i < SEG4) {
        int j = i - SEG3, o = j >> 8, kk = j & 255;
        g_wt2b[o * KT2 + CL + kk] = __float2bfloat16(ptw[o * CH + kk]);
    } else if (i < SEG5) {
        int j = i - SEG4, o = j >> 7, m = j & 127;
        float s = 0.f;
        for (int c = 0; c < CH; c++)
            s += ptw[o * CH + c] * s1f(c) * cWw[c * CL + m];
        g_wt2b[o * KT2 + m] = __float2bfloat16(s);
    } else if (i < SEG6) {
        int o = i - SEG5;
        float bt = ptb[o];
        for (int c = 0; c < CH; c++) bt += ptw[o * CH + c] * b1f(c);
        g_biast[o] = bt;
    } else if (i < SEG7) {
        int c = i - SEG6;
        g_bias2[c] = b1f(c) + b2f(c);
    }
}

// ---------------- runtime-task BF16 tensor-core GEMM (hoisted addressing) ----------------
#define MMA_BF16(d, a0,a1,a2,a3, b0,b1) \
    asm volatile("mma.sync.aligned.m16n8k16.row.col.f32.bf16.bf16.f32 " \
        "{%0,%1,%2,%3},{%4,%5,%6,%7},{%8,%9},{%0,%1,%2,%3};" \
        : "+f"(d[0]),"+f"(d[1]),"+f"(d[2]),"+f"(d[3]) \
        : "r"(a0),"r"(a1),"r"(a2),"r"(a3),"r"(b0),"r"(b1))

#define LDSM4(r0,r1,r2,r3, ad) \
    asm volatile("ldmatrix.sync.aligned.m8n8.x4.shared.b16 {%0,%1,%2,%3},[%4];" \
        : "=r"(r0),"=r"(r1),"=r"(r2),"=r"(r3) : "r"(ad))
#define LDSM4T(r0,r1,r2,r3, ad) \
    asm volatile("ldmatrix.sync.aligned.m8n8.x4.trans.shared.b16 {%0,%1,%2,%3},[%4];" \
        : "=r"(r0),"=r"(r1),"=r"(r2),"=r"(r3) : "r"(ad))

#define CP16(s, g)  asm volatile("cp.async.cg.shared.global [%0],[%1],16;\n" :: "r"(s), "l"(g))
#define CP16Z(s, g) asm volatile("cp.async.cg.shared.global [%0],[%1],16,0;\n" :: "r"(s), "l"(g))
#define CPCOMMIT()  asm volatile("cp.async.commit_group;\n")
#define CPWAIT1()   asm volatile("cp.async.wait_group 1;\n")

struct GTask {
    const __nv_bfloat16 *A, *B;
    __nv_bfloat16* CB;        // bf16 out (all modes)
    const float *R, *bias;
    int M, K, lda, ldb, ldc;
    long sA, sB, sC;
    float alpha;
    int splitK;
    int mode;   // 0: alpha*AB+bias; 2: alpha*AB (split-K partial at z-slice); 3: AB+bias+R
};

template<bool TB>
__global__ __launch_bounds__(256, 2) void gemm_rt(GTask t0, GTask t1, int ySplit, int zSplit)
{
    const bool second = ((int)blockIdx.y >= ySplit) || ((int)blockIdx.z >= zSplit);
    const GTask& t = second ? t1 : t0;
    int by = blockIdx.y - (((int)blockIdx.y >= ySplit) ? ySplit : 0);
    int bz = blockIdx.z - (((int)blockIdx.z >= zSplit) ? zSplit : 0);

    const int batch = bz / t.splitK;
    const int kslice = bz - batch * t.splitK;
    const int Kchunk = t.K / t.splitK;
    const int k0base = kslice * Kchunk;

    const __nv_bfloat16* A = t.A + (long)batch * t.sA;
    const __nv_bfloat16* Bm = t.B + (long)batch * t.sB;
    __nv_bfloat16* CB = t.CB;
    const float* R = t.R;
    if (t.mode == 2) CB += (long)bz * t.sC;
    else {
        CB += (long)batch * t.sC;
        if (R) R += (long)batch * t.sC;
    }
    const int lda = t.lda, ldb = t.ldb, ldc = t.ldc, M = t.M;

    const int m0 = by * 128;
    const int n0 = blockIdx.x * 128;
    const int tid = threadIdx.x;
    const int warp = tid >> 5, lane = tid & 31;
    const int wm = warp >> 2, wn = warp & 3;
    const int g = lane >> 2, c = lane & 3;
    const int mi = lane >> 3, lr = lane & 7;
    const int m0w = wm * 64, n0w = wn * 32;

    __shared__ uint32_t SA[3][2048];
    __shared__ uint32_t SB[3][2048];
    const uint32_t stA = (uint32_t)__cvta_generic_to_shared(&SA[0][0]);
    const uint32_t stB = (uint32_t)__cvta_generic_to_shared(&SB[0][0]);

    float acc[4][4][4];
    #pragma unroll
    for (int i = 0; i < 4; i++)
        #pragma unroll
        for (int j = 0; j < 4; j++)
            #pragma unroll
            for (int e = 0; e < 4; e++) acc[i][j][e] = 0.f;

    const int nk = Kchunk / 32;

    // ---- hoisted cp.async addressing ----
    uint32_t saoff[2], sboff[2];
    const __nv_bfloat16 *gA[2], *gB[2];
    bool okA[2];
    const int bstep = TB ? 32 : 32 * ldb;
    #pragma unroll
    for (int it = 0; it < 2; it++) {
        int f = tid + it * 256;
        {   int row = f >> 2, cn = f & 3;
            saoff[it] = (uint32_t)(row * 4 + (cn ^ ((row >> 1) & 3))) * 16u;
            okA[it] = (m0 + row) < M;
            gA[it] = A + (okA[it] ? (long)(m0 + row) * lda : 0L) + k0base + cn * 8;
        }
        if (!TB) {
            int k = f >> 4, cn = f & 15;
            sboff[it] = (uint32_t)(k * 16 + (cn ^ (k & 7))) * 16u;
            gB[it] = Bm + (long)(k0base + k) * ldb + n0 + cn * 8;
        } else {
            int row = f >> 2, cn = f & 3;
            sboff[it] = (uint32_t)(row * 4 + (cn ^ ((row >> 1) & 3))) * 16u;
            gB[it] = Bm + (long)(n0 + row) * ldb + k0base + cn * 8;
        }
    }
    // ---- hoisted fragment offsets ----
    uint32_t aoff[2][4], boff[2][2];
    #pragma unroll
    for (int s = 0; s < 2; s++) {
        #pragma unroll
        for (int i = 0; i < 4; i++) {
            int row = m0w + 16 * i + (mi & 1) * 8 + lr;
            int chunk = 2 * s + (mi >> 1);
            aoff[s][i] = (uint32_t)(row * 4 + (chunk ^ ((row >> 1) & 3))) * 16u;
        }
        #pragma unroll
        for (int p = 0; p < 2; p++) {
            if (!TB) {
                int krow = 16 * s + (mi & 1) * 8 + lr;
                int chunk = wn * 4 + 2 * p + (mi >> 1);
                boff[s][p] = (uint32_t)(krow * 16 + (chunk ^ (krow & 7))) * 16u;
            } else {
                int nrow = n0w + 16 * p + 8 * (mi >> 1) + lr;
                int chunk = 2 * s + (mi & 1);
                boff[s][p] = (uint32_t)(nrow * 4 + (chunk ^ ((nrow >> 1) & 3))) * 16u;
            }
        }
    }

    auto issue = [&](uint32_t bA, uint32_t bB) {
        #pragma unroll
        for (int it = 0; it < 2; it++) {
            if (okA[it]) { CP16(bA + saoff[it], gA[it]); } else { CP16Z(bA + saoff[it], gA[it]); }
            CP16(bB + sboff[it], gB[it]);
            gA[it] += 32;
            gB[it] += bstep;
        }
    };

    if (0 < nk) issue(stA, stB);
    CPCOMMIT();
    if (1 < nk) issue(stA + 8192, stB + 8192);
    CPCOMMIT();

    uint32_t iA = stA + 16384, iB = stB + 16384;
    uint32_t cA = stA, cB = stB;

    for (int tt = 0; tt < nk; tt++) {
        CPWAIT1();
        __syncthreads();
        if (tt + 2 < nk) issue(iA, iB);
        CPCOMMIT();
        iA += 8192; if (iA == stA + 24576) iA = stA;
        iB += 8192; if (iB == stB + 24576) iB = stB;

        #pragma unroll
        for (int s = 0; s < 2; s++) {
            uint32_t bfr[4][2];
            #pragma unroll
            for (int p = 0; p < 2; p++) {
                if (!TB) {
                    LDSM4T(bfr[2*p][0], bfr[2*p][1], bfr[2*p+1][0], bfr[2*p+1][1], cB + boff[s][p]);
                } else {
                    LDSM4(bfr[2*p][0], bfr[2*p][1], bfr[2*p+1][0], bfr[2*p+1][1], cB + boff[s][p]);
                }
            }
            #pragma unroll
            for (int i = 0; i < 4; i++) {
                uint32_t a0, a1, a2, a3;
                LDSM4(a0, a1, a2, a3, cA + aoff[s][i]);
                #pragma unroll
                for (int j = 0; j < 4; j++)
                    MMA_BF16(acc[i][j], a0, a1, a2, a3, bfr[j][0], bfr[j][1]);
            }
        }
        cA += 8192; if (cA == stA + 24576) cA = stA;
        cB += 8192; if (cB == stB + 24576) cB = stB;
    }

    // ---- epilogue ----
    #pragma unroll
    for (int i = 0; i < 4; i++) {
        int gm0 = m0 + m0w + i * 16 + g;
        #pragma unroll
        for (int half = 0; half < 2; half++) {
            int gm = gm0 + half * 8;
            if (gm >= M) continue;
            float bv = (t.mode != 2 && t.bias) ? t.bias[gm] : 0.f;
            #pragma unroll
            for (int j = 0; j < 4; j++) {
                int gn = n0 + n0w + j * 8 + 2 * c;
                long idx = (long)gm * ldc + gn;
                float v0 = acc[i][j][half * 2 + 0];
                float v1 = acc[i][j][half * 2 + 1];
                float o0, o1;
                if (t.mode == 2)      { o0 = t.alpha * v0;            o1 = t.alpha * v1; }
                else if (t.mode == 3) { o0 = v0 + bv + R[idx];        o1 = v1 + bv + R[idx + 1]; }
                else                  { o0 = t.alpha * v0 + bv;       o1 = t.alpha * v1 + bv; }
                __nv_bfloat162 h;
                h.x = __float2bfloat16(o0); h.y = __float2bfloat16(o1);
                *reinterpret_cast<__nv_bfloat162*>(&CB[idx]) = h;
            }
        }
    }
}

static inline GTask mkTask(const __nv_bfloat16* A, const __nv_bfloat16* B,
                           __nv_bfloat16* CB, const float* R, const float* bias,
                           int M, int K, int lda, int ldb, int ldc,
                           long sA, long sB, long sC, float alpha, int splitK, int mode) {
    GTask t; t.A = A; t.B = B; t.CB = CB; t.R = R; t.bias = bias;
    t.M = M; t.K = K; t.lda = lda; t.ldb = ldb; t.ldc = ldc;
    t.sA = sA; t.sB = sB; t.sC = sC; t.alpha = alpha; t.splitK = splitK; t.mode = mode;
    return t;
}

// ---------------- merged deterministic split-K reduce (bf16 partials, x2 vector) ----------------
__global__ void reduce_both() {
    int i = blockIdx.x * 256 + threadIdx.x;   // pair index
    const int PERP = CL * CL / 2;             // 8192 pairs per matrix
    if (i < BB * PERP) {
        int b = i / PERP, r = i - b * PERP;
        const __nv_bfloat162* src = reinterpret_cast<const __nv_bfloat162*>(g_ATTP);
        float s0 = 0.f, s1 = 0.f;
        #pragma unroll
        for (int k = 0; k < SPLITK; k++) {
            __nv_bfloat162 h = src[((long)b * SPLITK + k) * PERP + r];
            s0 += __bfloat162float(h.x);
            s1 += __bfloat162float(h.y);
        }
        __nv_bfloat162 o;
        o.x = __float2bfloat16(s0); o.y = __float2bfloat16(s1);
        reinterpret_cast<__nv_bfloat162*>(g_ATTb)[i] = o;
    } else {
        int j = i - BB * PERP;
        int b = j / PERP, r = j - b * PERP;
        const __nv_bfloat162* src = reinterpret_cast<const __nv_bfloat162*>(g_S2P);
        float s0 = 0.f, s1 = 0.f;
        #pragma unroll
        for (int k = 0; k < SPLITK2; k++) {
            __nv_bfloat162 h = src[((long)b * SPLITK2 + k) * PERP + r];
            s0 += __bfloat162float(h.x);
            s1 += __bfloat162float(h.y);
        }
        __nv_bfloat162 o;
        o.x = __float2bfloat16(s0); o.y = __float2bfloat16(s1);
        reinterpret_cast<__nv_bfloat162*>(g_S2b)[j] = o;
    }
}

// ---------------- CBAM: channel pooling (mean+max over HW, bf16 in) ----------------
__global__ void chanpool_kernel() {
    int c = blockIdx.x, b = blockIdx.y;
    int t = threadIdx.x;
    const __nv_bfloat162* p = reinterpret_cast<const __nv_bfloat162*>(
        g_ZPb + ((long)b * CH + c) * HW);
    float s = 0.f, mx = -1e30f;
    for (int i = t; i < HW / 2; i += 256) {
        __nv_bfloat162 h = p[i];
        float v0 = __bfloat162float(h.x), v1 = __bfloat162float(h.y);
        s += v0 + v1;
        mx = fmaxf(mx, fmaxf(v0, v1));
    }
    __shared__ float ss[256];
    __shared__ float sm[256];
    ss[t] = s; sm[t] = mx;
    __syncthreads();
    for (int o = 128; o > 0; o >>= 1) {
        if (t < o) { ss[t] += ss[t + o]; sm[t] = fmaxf(sm[t], sm[t + o]); }
        __syncthreads();
    }
    if (t == 0) {
        g_pm[b * CH + c] = ss[0] * (1.f / HW);
        g_px[b * CH + c] = sm[0];
    }
}

// ---------------- CBAM: channel-attention MLP ----------------
__global__ void camlp_kernel(const float* __restrict__ fc1, const float* __restrict__ fc2) {
    int b = blockIdx.x;
    int t = threadIdx.x;
    __shared__ float hm[16], hx[16];
    if (t < 16) {
        float s = 0.f;
        for (int c = 0; c < CH; c++) s += fc1[t * CH + c] * g_pm[b * CH + c];
        hm[t] = fmaxf(s, 0.f);
    } else if (t < 32) {
        int h = t - 16;
        float s = 0.f;
        for (int c = 0; c < CH; c++) s += fc1[h * CH + c] * g_px[b * CH + c];
        hx[h] = fmaxf(s, 0.f);
    }
    __syncthreads();
    float sm = 0.f, sx = 0.f;
    #pragma unroll
    for (int h = 0; h < 16; h++) {
        float w = fc2[t * 16 + h];
        sm += w * hm[h];
        sx += w * hx[h];
    }
    g_ca[b * CH + t] = 1.f / (1.f + expf(-(sm + sx)));
}

// ---------------- CBAM: spatial pooling over channels of z_pnl*ca ----------------
__global__ void spool_kernel() {
    __shared__ float cas[CH];
    int idx = blockIdx.x * 256 + threadIdx.x;
    int b = idx / HW;
    int p = idx - b * HW;
    for (int c = threadIdx.x; c < CH; c += 256) cas[c] = g_ca[b * CH + c];
    __syncthreads();
    float s = 0.f, mx = -1e30f;
    for (int c = 0; c < CH; c++) {
        float v = __bfloat162float(g_ZPb[((long)b * CH + c) * HW + p]) * cas[c];
        s += v;
        mx = fmaxf(mx, v);
    }
    g_sam[idx] = s * (1.f / CH);
    g_sax[idx] = mx;
}

// ---------------- CBAM: 7x7 spatial conv + sigmoid ----------------
__global__ void sconv_kernel(const float* __restrict__ w) {
    int idx = blockIdx.x * 256 + threadIdx.x;
    int b = idx / HW;
    int p = idx - b * HW;
    int h = p >> 6, wq = p & 63;
    float s = 0.f;
    #pragma unroll
    for (int kh = 0; kh < 7; kh++) {
        int ih = h + kh - 3;
        if (ih < 0 || ih >= 64) continue;
        #pragma unroll
        for (int kw = 0; kw < 7; kw++) {
            int iw = wq + kw - 3;
            if (iw < 0 || iw >= 64) continue;
            int q = (ih << 6) | iw;
            s += w[kh * 7 + kw] * g_sam[b * HW + q] + w[49 + kh * 7 + kw] * g_sax[b * HW + q];
        }
    }
    g_sas[idx] = 1.f / (1.f + expf(-s));
}

// ---------------- final weighted fusion (x4 vectorized) ----------------
__global__ void final_kernel(const float* __restrict__ x, const float* __restrict__ fwp,
                             float* __restrict__ out) {
    long e = 4L * (blockIdx.x * 256 + threadIdx.x);
    long p = e % HW;
    long bc = e / HW;
    long b = bc / CH;
    float fw = *fwp;
    uint2 zr = *reinterpret_cast<const uint2*>(g_ZPb + e);
    __nv_bfloat162 z0 = *reinterpret_cast<__nv_bfloat162*>(&zr.x);
    __nv_bfloat162 z1 = *reinterpret_cast<__nv_bfloat162*>(&zr.y);
    float4 xv = *reinterpret_cast<const float4*>(x + e);
    float ca = g_ca[bc];
    const float* sas = g_sas + b * HW + p;
    float4 o;
    o.x = fw * __bfloat162float(z0.x) * ca * sas[0] + (1.f - fw) * xv.x;
    o.y = fw * __bfloat162float(z0.y) * ca * sas[1] + (1.f - fw) * xv.y;
    o.z = fw * __bfloat162float(z1.x) * ca * sas[2] + (1.f - fw) * xv.z;
    o.w = fw * __bfloat162float(z1.y) * ca * sas[3] + (1.f - fw) * xv.w;
    *reinterpret_cast<float4*>(out + e) = o;
}

// ---------------- launch ----------------
extern "C" void kernel_launch(void* const* d_in, const int* in_sizes, int n_in,
                              void* d_out, int out_size) {
    const float* x   = (const float*)d_in[0];
    const float* x0  = (const float*)d_in[1];
    const float* cgw = (const float*)d_in[2];
    const float* cgb = (const float*)d_in[3];
    const float* ctw = (const float*)d_in[4];
    const float* ctb = (const float*)d_in[5];
    const float* cpw = (const float*)d_in[6];
    const float* cpb = (const float*)d_in[7];
    const float* cWw = (const float*)d_in[8];
    const float* cWb = (const float*)d_in[9];
    const float* cbg = (const float*)d_in[10];
    const float* cbb = (const float*)d_in[11];
    const float* cbm = (const float*)d_in[12];
    const float* cbv = (const float*)d_in[13];
    const float* pgw = (const float*)d_in[14];
    const float* pgb = (const float*)d_in[15];
    const float* ptw = (const float*)d_in[16];
    const float* ptb = (const float*)d_in[17];
    const float* ppw = (const float*)d_in[18];
    const float* ppb = (const float*)d_in[19];
    const float* pWw = (const float*)d_in[20];
    const float* pWb = (const float*)d_in[21];
    const float* pbg = (const float*)d_in[22];
    const float* pbb = (const float*)d_in[23];
    const float* pbm = (const float*)d_in[24];
    const float* pbv = (const float*)d_in[25];
    const float* fc1 = (const float*)d_in[26];
    const float* fc2 = (const float*)d_in[27];
    const float* saw = (const float*)d_in[28];
    const float* fwp = (const float*)d_in[29];
    float* out = (float*)d_out;

    __nv_bfloat16 *SLAB, *X0B, *THB, *PGX, *T2B, *ZPB, *ATTB, *S2B, *ATTP, *S2P;
    __nv_bfloat16 *CTWB, *PGXW, *WT2B, *ZPWB;
    float *PGXBI, *BIAST, *BIAS2;
    cudaGetSymbolAddress((void**)&SLAB, g_slab);
    cudaGetSymbolAddress((void**)&X0B,  g_x0b);
    cudaGetSymbolAddress((void**)&THB,  g_THb);
    cudaGetSymbolAddress((void**)&PGX,  g_pgx);
    cudaGetSymbolAddress((void**)&T2B,  g_T2b);
    cudaGetSymbolAddress((void**)&ZPB,  g_ZPb);
    cudaGetSymbolAddress((void**)&ATTB, g_ATTb);
    cudaGetSymbolAddress((void**)&S2B,  g_S2b);
    cudaGetSymbolAddress((void**)&ATTP, g_ATTP);
    cudaGetSymbolAddress((void**)&S2P,  g_S2P);
    cudaGetSymbolAddress((void**)&CTWB, g_ctwb);
    cudaGetSymbolAddress((void**)&PGXW, g_pgxw);
    cudaGetSymbolAddress((void**)&WT2B, g_wt2b);
    cudaGetSymbolAddress((void**)&ZPWB, g_zpwb);
    cudaGetSymbolAddress((void**)&PGXBI,g_pgxbias);
    cudaGetSymbolAddress((void**)&BIAST,g_biast);
    cudaGetSymbolAddress((void**)&BIAS2,g_bias2);

    const long sSLAB = (long)SLABR * HW;
    const long sPGX  = (long)PGR * HW;
    const int BIG = 1 << 30;

    // 1) merged converts + weight prep
    prep_all_kernel<<<(SEG7 + 255) / 256, 256>>>(
        x, x0, ctw, cpw, cgw, pgw, ppw, cpb, cgb, pgb, ppb, pWw, cWw, ptw, ptb,
        cbg, cbb, cbm, cbv, cWb, pbg, pbb, pbm, pbv, pWb);

    // 2) stacked conv PH|GX|G2|P2 (y 0-2) + TH (y 3)
    {
        GTask t0 = mkTask(PGXW, X0B, PGX, nullptr, PGXBI,
                          PGR, CL, CL, HW, HW, 0L, (long)CL*HW, sPGX, 1.f, 1, 0);
        GTask t1 = mkTask(CTWB, SLAB + (long)XOFF*HW, THB, nullptr, ctb,
                          CL, CH, CH, HW, HW, 0L, sSLAB, (long)CL*HW, 1.f, 1, 0);
        gemm_rt<false><<<dim3(HW/128, 4, BB), 256>>>(t0, t1, 3, BIG);
    }
    // 3) dual split-K: ATT (z<128) + S2 (z>=128), bf16 partials
    {
        GTask t0 = mkTask(THB, PGX, ATTP, nullptr, nullptr,
                          CL, HW, HW, HW, CL, (long)CL*HW, sPGX, (long)CL*CL,
                          1.f/CL, SPLITK, 2);
        GTask t1 = mkTask(PGX + (long)256*HW, PGX + (long)320*HW, S2P, nullptr, nullptr,
                          CL, MM, MM, MM, CL, sPGX, sPGX, (long)CL*CL,
                          1.f/MM, SPLITK2, 2);
        gemm_rt<true><<<dim3(1, 1, BB*SPLITK + BB*SPLITK2), 256>>>(t0, t1, BIG, BB*SPLITK);
    }
    // 4) merged reduce -> ATTB, S2B
    reduce_both<<<2*BB*(CL*CL/2)/256, 256>>>();
    // 5) Y = ATT @ GX  -> slab rows YOFF..
    {
        GTask t0 = mkTask(ATTB, PGX + (long)CL*HW, SLAB + (long)YOFF*HW, nullptr, nullptr,
                          CL, CL, CL, HW, HW, (long)CL*CL, sPGX, sSLAB, 1.f, 1, 0);
        gemm_rt<false><<<dim3(HW/128, 1, BB), 256>>>(t0, t0, BIG, BIG);
    }
    // 6) T2 fused over [Y; x] (K=384)
    {
        GTask t0 = mkTask(WT2B, SLAB + (long)YOFF*HW, T2B, nullptr, BIAST,
                          RR, KT2, KT2, HW, HW, 0L, sSLAB, (long)RR*HW, 1.f, 1, 0);
        gemm_rt<false><<<dim3(HW/128, 1, BB), 256>>>(t0, t0, BIG, BIG);
    }
    // 7) Y2v = S2 @ T2v -> slab rows 0-63
    {
        GTask t0 = mkTask(S2B, T2B, SLAB + (long)Y2OFF*HW, nullptr, nullptr,
                          CL, CL, CL, MM, MM, (long)CL*CL, (long)RR*HW, sSLAB, 1.f, 1, 0);
        gemm_rt<false><<<dim3(MM/128, 1, BB), 256>>>(t0, t0, BIG, BIG);
    }
    // 8) ZP = [s2*pWw | s1*cWw] @ [Y2;Y] + (b1+b2) + x  (bf16 out)
    {
        GTask t0 = mkTask(ZPWB, SLAB, ZPB, x, BIAS2,
                          CH, KZP, KZP, HW, HW, 0L, sSLAB, (long)CH*HW, 1.f, 1, 3);
        gemm_rt<false><<<dim3(HW/128, CH/128, BB), 256>>>(t0, t0, BIG, BIG);
    }

    // ---- CBAM + fusion ----
    chanpool_kernel<<<dim3(CH, BB), 256>>>();
    camlp_kernel<<<BB, 256>>>(fc1, fc2);
    spool_kernel<<<BB*HW/256, 256>>>();
    sconv_kernel<<<BB*HW/256, 256>>>(saw);
    final_kernel<<<BB*CH*HW/1024, 256>>>(x, fwp, out);
}